// round 9
// baseline (speedup 1.0000x reference)
#include <cuda_runtime.h>
#include <cuda_bf16.h>
#include <cstdint>
#include <math.h>

#define S_  2048
#define DM  2048
#define H_  16
#define DK  128
#define F_  64
#define AUG 192
#define INV_SCALE (1.0f/11.313708498984761f)
#define COUPLING 0.1f

typedef __nv_bfloat16 bf16;

// ---------------- device scratch (256B-aligned) ----------------
__device__ __align__(256) bf16  d_xhi[S_*DM],  d_xlo[S_*DM];
__device__ __align__(256) bf16  d_wqkhi[2*DM*DM], d_wqklo[2*DM*DM];   // wq then wk
__device__ __align__(256) bf16  d_wvhi[DM*DM], d_wvlo[DM*DM];
__device__ __align__(256) bf16  d_wohi[DM*DM], d_wolo[DM*DM];
__device__ __align__(256) float d_QK[2*S_*DM];                        // Q then K (fp32)
__device__ __align__(256) bf16  d_Vthi[DM*S_], d_Vtlo[DM*S_];         // V transposed [d][s]
__device__ __align__(256) float d_fp[S_*F_];
__device__ __align__(256) float d_fpart[16*S_*F_];
__device__ __align__(256) float d_g[S_*F_];
__device__ __align__(256) float d_metric[F_*F_];
__device__ __align__(256) float d_mi[F_];
__device__ __align__(256) float d_fpsum[F_];
__device__ __align__(256) float d_curv[S_];
__device__ __align__(256) float d_curvb[S_];
__device__ __align__(256) bf16  d_Qahi[H_*S_*AUG], d_Qalo[H_*S_*AUG];
__device__ __align__(256) bf16  d_Kahi[H_*S_*AUG], d_Kalo[H_*S_*AUG];
__device__ __align__(256) float d_scores[H_*S_*S_];
__device__ __align__(256) bf16  d_Phi[H_*S_*S_], d_Plo[H_*S_*S_];
__device__ __align__(256) bf16  d_attnhi[S_*DM], d_attnlo[S_*DM];

// ================= portable-ISA helpers =================
__device__ __forceinline__ uint32_t smem_to_u32(const void* p) {
    uint32_t a;
    asm("{ .reg .u64 t; cvta.to.shared.u64 t, %1; cvt.u32.u64 %0, t; }" : "=r"(a) : "l"(p));
    return a;
}
__device__ __forceinline__ void cp16(uint32_t saddr, const void* g) {
    asm volatile("cp.async.cg.shared.global [%0], [%1], 16;" :: "r"(saddr), "l"(g));
}
__device__ __forceinline__ void ldsm4(uint32_t* r, uint32_t a) {
    asm volatile("ldmatrix.sync.aligned.m8n8.x4.shared.b16 {%0,%1,%2,%3}, [%4];"
                 : "=r"(r[0]), "=r"(r[1]), "=r"(r[2]), "=r"(r[3]) : "r"(a));
}
__device__ __forceinline__ void mma_bf16(float* c, const uint32_t* a, uint32_t b0, uint32_t b1) {
    asm volatile("mma.sync.aligned.m16n8k16.row.col.f32.bf16.bf16.f32 "
                 "{%0,%1,%2,%3}, {%4,%5,%6,%7}, {%8,%9}, {%0,%1,%2,%3};"
                 : "+f"(c[0]), "+f"(c[1]), "+f"(c[2]), "+f"(c[3])
                 : "r"(a[0]), "r"(a[1]), "r"(a[2]), "r"(a[3]), "r"(b0), "r"(b1));
}
__device__ __forceinline__ uint32_t pack_bf16x2(float lo, float hi) {
    uint32_t r;
    unsigned short l = __bfloat16_as_ushort(__float2bfloat16(lo));
    unsigned short h = __bfloat16_as_ushort(__float2bfloat16(hi));
    r = (uint32_t)l | ((uint32_t)h << 16);
    return r;
}

__device__ __forceinline__ uint32_t sw_off(int row, int chunk) {
    return (uint32_t)(row * 64 + ((chunk ^ ((row >> 1) & 3)) << 4));
}

// =================== narrow kernel: 128x128 CTA tile (for AV, N=128) ===================
#define STAGE_BYTES 32768
#define MMA_SMEM (2*STAGE_BYTES)

__device__ __forceinline__ void load_tiles(uint32_t sbase, int tid,
    const bf16* g0, const bf16* g1, const bf16* g2, const bf16* g3,
    int lda, int ldb, int k0)
{
    const bf16* gp[4] = {g0, g1, g2, g3};
#pragma unroll
    for (int i = 0; i < 8; i++) {
        int q = tid + i * 256;
        int tile = q >> 9, r = (q >> 2) & 127, c = q & 3;
        int ld = (tile < 2) ? lda : ldb;
        const bf16* src = gp[tile] + (size_t)r * ld + k0 + c * 8;
        uint32_t so = sbase + tile * 8192 + sw_off(r, c);
        cp16(so, src);
    }
    asm volatile("cp.async.commit_group;" ::: "memory");
}

template<int OUT_MODE>
__global__ void __launch_bounds__(256)
mma_gemm_nt(const bf16* __restrict__ Ahi, const bf16* __restrict__ Alo, int lda, size_t sAz,
            const bf16* __restrict__ Bhi, const bf16* __restrict__ Blo, int ldb, size_t sBz,
            float* __restrict__ C, bf16* __restrict__ Chi, bf16* __restrict__ Clo,
            int ldc, size_t sCz, int K, const float* __restrict__ bias)
{
    extern __shared__ char smem[];
    const uint32_t sb = smem_to_u32(smem);
    const int tid = threadIdx.x, lane = tid & 31, wid = tid >> 5;
    const int wm = wid & 1, wn = wid >> 1;           // 2 x 4 warp grid, warp tile 64x32
    const size_t z = blockIdx.z;
    const int bm = blockIdx.y * 128, bn = blockIdx.x * 128;

    const bf16* gA0 = Ahi + z * sAz + (size_t)bm * lda;
    const bf16* gA1 = Alo + z * sAz + (size_t)bm * lda;
    const bf16* gB0 = Bhi + z * sBz + (size_t)bn * ldb;
    const bf16* gB1 = Blo + z * sBz + (size_t)bn * ldb;

    float acc[4][4][4];
#pragma unroll
    for (int i = 0; i < 4; i++)
#pragma unroll
        for (int j = 0; j < 4; j++)
#pragma unroll
            for (int k = 0; k < 4; k++) acc[i][j][k] = 0.f;

    const int a_row_l = (lane & 7) + ((lane >> 3) & 1) * 8;
    const int a_chk_l = lane >> 4;
    const int b_row_l = (lane & 7) + ((lane >> 4) & 1) * 8;
    const int b_chk_l = (lane >> 3) & 1;

    const int nch = K >> 5;
    load_tiles(sb, tid, gA0, gA1, gB0, gB1, lda, ldb, 0);

    for (int c = 0; c < nch; c++) {
        if (c + 1 < nch) {
            load_tiles(sb + ((c + 1) & 1) * STAGE_BYTES, tid, gA0, gA1, gB0, gB1,
                       lda, ldb, (c + 1) * 32);
            asm volatile("cp.async.wait_group 1;" ::: "memory");
        } else {
            asm volatile("cp.async.wait_group 0;" ::: "memory");
        }
        __syncthreads();
        const uint32_t s0 = sb + (c & 1) * STAGE_BYTES;
#pragma unroll
        for (int ks = 0; ks < 2; ks++) {
            uint32_t a_hi[4][4], a_lo[4][4], b_hi[8], b_lo[8];
#pragma unroll
            for (int mt = 0; mt < 4; mt++) {
                int row = wm * 64 + mt * 16 + a_row_l;
                uint32_t off = sw_off(row, ks * 2 + a_chk_l);
                ldsm4(a_hi[mt], s0 + off);
                ldsm4(a_lo[mt], s0 + 8192 + off);
            }
#pragma unroll
            for (int ntp = 0; ntp < 2; ntp++) {
                int row = wn * 32 + ntp * 16 + b_row_l;
                uint32_t off = sw_off(row, ks * 2 + b_chk_l);
                ldsm4(&b_hi[ntp * 4], s0 + 16384 + off);
                ldsm4(&b_lo[ntp * 4], s0 + 24576 + off);
            }
#pragma unroll
            for (int mt = 0; mt < 4; mt++)
#pragma unroll
                for (int nt = 0; nt < 4; nt++) {
                    int bi = (nt >> 1) * 4 + (nt & 1) * 2;
                    mma_bf16(acc[mt][nt], a_hi[mt], b_hi[bi], b_hi[bi + 1]);
                    mma_bf16(acc[mt][nt], a_hi[mt], b_lo[bi], b_lo[bi + 1]);
                    mma_bf16(acc[mt][nt], a_lo[mt], b_hi[bi], b_hi[bi + 1]);
                }
        }
        __syncthreads();
    }

    const int r_l = lane >> 2, c_l = (lane & 3) * 2;
#pragma unroll
    for (int mt = 0; mt < 4; mt++) {
#pragma unroll
        for (int nt = 0; nt < 4; nt++) {
            int row0 = bm + wm * 64 + mt * 16 + r_l;
            int col  = bn + wn * 32 + nt * 8 + c_l;
            float v0 = acc[mt][nt][0], v1 = acc[mt][nt][1];
            float v2 = acc[mt][nt][2], v3 = acc[mt][nt][3];
            if (OUT_MODE == 0) {
                if (bias) { v0 += bias[col]; v1 += bias[col + 1]; v2 += bias[col]; v3 += bias[col + 1]; }
                float* p0 = C + z * sCz + (size_t)row0 * ldc + col;
                float* p1 = C + z * sCz + (size_t)(row0 + 8) * ldc + col;
                p0[0] = v0; p0[1] = v1;
                p1[0] = v2; p1[1] = v3;
            } else {
                bf16 h0 = __float2bfloat16(v0), h1 = __float2bfloat16(v1);
                bf16 h2 = __float2bfloat16(v2), h3 = __float2bfloat16(v3);
                bf16 l0 = __float2bfloat16(v0 - __bfloat162float(h0));
                bf16 l1 = __float2bfloat16(v1 - __bfloat162float(h1));
                bf16 l2 = __float2bfloat16(v2 - __bfloat162float(h2));
                bf16 l3 = __float2bfloat16(v3 - __bfloat162float(h3));
                bf16* hp0 = Chi + z * sCz + (size_t)row0 * ldc + col;
                bf16* hp1 = Chi + z * sCz + (size_t)(row0 + 8) * ldc + col;
                bf16* lp0 = Clo + z * sCz + (size_t)row0 * ldc + col;
                bf16* lp1 = Clo + z * sCz + (size_t)(row0 + 8) * ldc + col;
                hp0[0] = h0; hp0[1] = h1; hp1[0] = h2; hp1[1] = h3;
                lp0[0] = l0; lp0[1] = l1; lp1[0] = l2; lp1[1] = l3;
            }
        }
    }
}

// =================== wide kernel: 128x256 CTA tile, warp tile 64x64 ===================
// stage: Ahi(8K) | Alo(8K) | Bhi(16K) | Blo(16K) = 48KB ; 2 stages = 96KB
#define WSTAGE_BYTES 49152
#define WMMA_SMEM (2*WSTAGE_BYTES)

__device__ __forceinline__ void load_tiles_wide(uint32_t sbase, int tid,
    const bf16* gA0, const bf16* gA1, const bf16* gB0, const bf16* gB1,
    int lda, int ldb, int k0)
{
#pragma unroll
    for (int i = 0; i < 12; i++) {
        int q = tid + i * 256;
        const bf16* src;
        uint32_t so;
        if (q < 1024) {                               // A tiles: 128 rows x 4 chunks x2
            int tile = q >> 9, r = (q >> 2) & 127, c = q & 3;
            src = (tile == 0 ? gA0 : gA1) + (size_t)r * lda + k0 + c * 8;
            so = sbase + tile * 8192 + sw_off(r, c);
        } else {                                      // B tiles: 256 rows x 4 chunks x2
            int qq = q - 1024;
            int tile = qq >> 10, r = (qq >> 2) & 255, c = qq & 3;
            src = (tile == 0 ? gB0 : gB1) + (size_t)r * ldb + k0 + c * 8;
            so = sbase + 16384 + tile * 16384 + sw_off(r, c);
        }
        cp16(so, src);
    }
    asm volatile("cp.async.commit_group;" ::: "memory");
}

template<int OUT_MODE>
__global__ void __launch_bounds__(256)
mma_gemm_nt_wide(const bf16* __restrict__ Ahi, const bf16* __restrict__ Alo, int lda, size_t sAz,
                 const bf16* __restrict__ Bhi, const bf16* __restrict__ Blo, int ldb, size_t sBz,
                 float* __restrict__ C, bf16* __restrict__ Chi, bf16* __restrict__ Clo,
                 int ldc, size_t sCz, int K, const float* __restrict__ bias)
{
    extern __shared__ char smem[];
    const uint32_t sb = smem_to_u32(smem);
    const int tid = threadIdx.x, lane = tid & 31, wid = tid >> 5;
    const int wm = wid & 1, wn = wid >> 1;           // 2 x 4 warp grid, warp tile 64x64
    const size_t z = blockIdx.z;
    const int bm = blockIdx.y * 128, bn = blockIdx.x * 256;

    const bf16* gA0 = Ahi + z * sAz + (size_t)bm * lda;
    const bf16* gA1 = Alo + z * sAz + (size_t)bm * lda;
    const bf16* gB0 = Bhi + z * sBz + (size_t)bn * ldb;
    const bf16* gB1 = Blo + z * sBz + (size_t)bn * ldb;

    float acc[4][8][4];
#pragma unroll
    for (int i = 0; i < 4; i++)
#pragma unroll
        for (int j = 0; j < 8; j++)
#pragma unroll
            for (int k = 0; k < 4; k++) acc[i][j][k] = 0.f;

    const int a_row_l = (lane & 7) + ((lane >> 3) & 1) * 8;
    const int a_chk_l = lane >> 4;
    const int b_row_l = (lane & 7) + ((lane >> 4) & 1) * 8;
    const int b_chk_l = (lane >> 3) & 1;

    const int nch = K >> 5;
    load_tiles_wide(sb, tid, gA0, gA1, gB0, gB1, lda, ldb, 0);

    for (int c = 0; c < nch; c++) {
        if (c + 1 < nch) {
            load_tiles_wide(sb + ((c + 1) & 1) * WSTAGE_BYTES, tid, gA0, gA1, gB0, gB1,
                            lda, ldb, (c + 1) * 32);
            asm volatile("cp.async.wait_group 1;" ::: "memory");
        } else {
            asm volatile("cp.async.wait_group 0;" ::: "memory");
        }
        __syncthreads();
        const uint32_t s0 = sb + (c & 1) * WSTAGE_BYTES;
#pragma unroll
        for (int ks = 0; ks < 2; ks++) {
            uint32_t a_hi[4][4], a_lo[4][4], b_hi[16], b_lo[16];
#pragma unroll
            for (int mt = 0; mt < 4; mt++) {
                int row = wm * 64 + mt * 16 + a_row_l;
                uint32_t off = sw_off(row, ks * 2 + a_chk_l);
                ldsm4(a_hi[mt], s0 + off);
                ldsm4(a_lo[mt], s0 + 8192 + off);
            }
#pragma unroll
            for (int ntp = 0; ntp < 4; ntp++) {
                int row = wn * 64 + ntp * 16 + b_row_l;
                uint32_t off = sw_off(row, ks * 2 + b_chk_l);
                ldsm4(&b_hi[ntp * 4], s0 + 16384 + off);
                ldsm4(&b_lo[ntp * 4], s0 + 32768 + off);
            }
#pragma unroll
            for (int mt = 0; mt < 4; mt++)
#pragma unroll
                for (int nt = 0; nt < 8; nt++) {
                    int bi = (nt >> 1) * 4 + (nt & 1) * 2;
                    mma_bf16(acc[mt][nt], a_hi[mt], b_hi[bi], b_hi[bi + 1]);
                    mma_bf16(acc[mt][nt], a_hi[mt], b_lo[bi], b_lo[bi + 1]);
                    mma_bf16(acc[mt][nt], a_lo[mt], b_hi[bi], b_hi[bi + 1]);
                }
        }
        __syncthreads();
    }

    const int r_l = lane >> 2, c_l = (lane & 3) * 2;
#pragma unroll
    for (int mt = 0; mt < 4; mt++) {
#pragma unroll
        for (int nt = 0; nt < 8; nt++) {
            int row0 = bm + wm * 64 + mt * 16 + r_l;
            int col  = bn + wn * 64 + nt * 8 + c_l;
            float v0 = acc[mt][nt][0], v1 = acc[mt][nt][1];
            float v2 = acc[mt][nt][2], v3 = acc[mt][nt][3];
            if (OUT_MODE == 0) {
                if (bias) { v0 += bias[col]; v1 += bias[col + 1]; v2 += bias[col]; v3 += bias[col + 1]; }
                float* p0 = C + z * sCz + (size_t)row0 * ldc + col;
                float* p1 = C + z * sCz + (size_t)(row0 + 8) * ldc + col;
                p0[0] = v0; p0[1] = v1;
                p1[0] = v2; p1[1] = v3;
            } else {
                bf16 h0 = __float2bfloat16(v0), h1 = __float2bfloat16(v1);
                bf16 h2 = __float2bfloat16(v2), h3 = __float2bfloat16(v3);
                bf16 l0 = __float2bfloat16(v0 - __bfloat162float(h0));
                bf16 l1 = __float2bfloat16(v1 - __bfloat162float(h1));
                bf16 l2 = __float2bfloat16(v2 - __bfloat162float(h2));
                bf16 l3 = __float2bfloat16(v3 - __bfloat162float(h3));
                bf16* hp0 = Chi + z * sCz + (size_t)row0 * ldc + col;
                bf16* hp1 = Chi + z * sCz + (size_t)(row0 + 8) * ldc + col;
                bf16* lp0 = Clo + z * sCz + (size_t)row0 * ldc + col;
                bf16* lp1 = Clo + z * sCz + (size_t)(row0 + 8) * ldc + col;
                hp0[0] = h0; hp0[1] = h1; hp1[0] = h2; hp1[1] = h3;
                lp0[0] = l0; lp0[1] = l1; lp1[0] = l2; lp1[1] = l3;
            }
        }
    }
}

// ================= small kernels =================
__global__ void split5_kernel(
    const float* __restrict__ s0, const float* __restrict__ s1, const float* __restrict__ s2,
    const float* __restrict__ s3, const float* __restrict__ s4,
    bf16* __restrict__ h0, bf16* __restrict__ h1, bf16* __restrict__ h2,
    bf16* __restrict__ h3, bf16* __restrict__ h4,
    bf16* __restrict__ l0, bf16* __restrict__ l1, bf16* __restrict__ l2,
    bf16* __restrict__ l3, bf16* __restrict__ l4)
{
    int i4 = blockIdx.x * blockDim.x + threadIdx.x;
    int zz = blockIdx.y;
    const float* src = (zz == 0) ? s0 : (zz == 1) ? s1 : (zz == 2) ? s2 : (zz == 3) ? s3 : s4;
    bf16* hi = (zz == 0) ? h0 : (zz == 1) ? h1 : (zz == 2) ? h2 : (zz == 3) ? h3 : h4;
    bf16* lo = (zz == 0) ? l0 : (zz == 1) ? l1 : (zz == 2) ? l2 : (zz == 3) ? l3 : l4;
    float4 v = *((const float4*)src + i4);
    bf16 a = __float2bfloat16(v.x), b = __float2bfloat16(v.y);
    bf16 c = __float2bfloat16(v.z), d = __float2bfloat16(v.w);
    uint2 hv, lv;
    hv.x = (uint32_t)__bfloat16_as_ushort(a) | ((uint32_t)__bfloat16_as_ushort(b) << 16);
    hv.y = (uint32_t)__bfloat16_as_ushort(c) | ((uint32_t)__bfloat16_as_ushort(d) << 16);
    lv.x = pack_bf16x2(v.x - __bfloat162float(a), v.y - __bfloat162float(b));
    lv.y = pack_bf16x2(v.z - __bfloat162float(c), v.w - __bfloat162float(d));
    *((uint2*)hi + i4) = hv;
    *((uint2*)lo + i4) = lv;
}

__global__ void fiber_gemm(const float* __restrict__ x, const float* __restrict__ fw,
                           float* __restrict__ fpart)
{
    __shared__ float Xs[64][68];
    __shared__ float Fs[64][68];
    const int ksplit = blockIdx.x;
    const int rb = blockIdx.y * 64;
    const int t = threadIdx.x;
    const int rt = t & 15, ct = t >> 4;
    float acc[4][4] = {};
    for (int sub = 0; sub < 2; sub++) {
        const int k0 = ksplit * 128 + sub * 64;
        __syncthreads();
        for (int i = t; i < 1024; i += 256) {
            int row = i >> 4, kq = (i & 15) * 4;
            float4 v = *(const float4*)&x[(size_t)(rb + row) * DM + k0 + kq];
            Xs[kq][row] = v.x; Xs[kq+1][row] = v.y; Xs[kq+2][row] = v.z; Xs[kq+3][row] = v.w;
            float4 w = *(const float4*)&fw[(size_t)row * DM + k0 + kq];
            Fs[kq][row] = w.x; Fs[kq+1][row] = w.y; Fs[kq+2][row] = w.z; Fs[kq+3][row] = w.w;
        }
        __syncthreads();
#pragma unroll 16
        for (int k = 0; k < 64; k++) {
            float a[4], b[4];
#pragma unroll
            for (int i = 0; i < 4; i++) a[i] = Xs[k][rt*4 + i];
#pragma unroll
            for (int j = 0; j < 4; j++) b[j] = Fs[k][ct*4 + j];
#pragma unroll
            for (int i = 0; i < 4; i++)
#pragma unroll
                for (int j = 0; j < 4; j++) acc[i][j] = fmaf(a[i], b[j], acc[i][j]);
        }
    }
    float* dst = fpart + (size_t)ksplit * S_ * F_;
#pragma unroll
    for (int i = 0; i < 4; i++)
#pragma unroll
        for (int j = 0; j < 4; j++)
            dst[(size_t)(rb + rt*4 + i) * F_ + ct*4 + j] = acc[i][j];
}

__global__ void fiber_reduce(const float* __restrict__ fpart, const float* __restrict__ fb,
                             float* __restrict__ fp)
{
    int i = blockIdx.x * blockDim.x + threadIdx.x;
    if (i >= S_ * F_) return;
    float a = fb[i & 63];
#pragma unroll
    for (int s = 0; s < 16; s++) a += fpart[(size_t)s * S_ * F_ + i];
    fp[i] = a;
}

__global__ void fp_stats_kernel(const float* __restrict__ fp,
                                float* __restrict__ fpsum, float* __restrict__ mi)
{
    __shared__ float sm[256];
    int t = threadIdx.x;
    int f = t & 63, c = t >> 6;
    float s = 0.f;
    for (int i = c; i < S_; i += 4) s += fp[i*F_ + f];
    sm[t] = s; __syncthreads();
    if (c == 0) {
        float tot = sm[f] + sm[64+f] + sm[128+f] + sm[192+f];
        fpsum[f] = tot;
        mi[f] = tot / (float)S_;
    }
}

__global__ void mlp_metric_kernel(const float* __restrict__ mi,
                                  const float* __restrict__ fm1w, const float* __restrict__ fm1b,
                                  const float* __restrict__ fm2w, const float* __restrict__ fm2b,
                                  float* __restrict__ metric)
{
    __shared__ float smi[F_];
    __shared__ float hid[F_/2];
    __shared__ float raw[F_];
    int t = threadIdx.x;
    smi[t] = mi[t];
    __syncthreads();
    if (t < F_/2) {
        float a = fm1b[t];
        for (int f = 0; f < F_; f++) a = fmaf(smi[f], fm1w[t*F_ + f], a);
        hid[t] = fmaxf(a, 0.f);
    }
    __syncthreads();
    {
        float a = fm2b[t];
        for (int j = 0; j < F_/2; j++) a = fmaf(hid[j], fm2w[t*(F_/2) + j], a);
        raw[t] = a;
    }
    __syncthreads();
    for (int b = 0; b < F_; b++)
        metric[t*F_ + b] = raw[t]*raw[b] + ((t == b) ? 0.1f : 0.f);
}

__global__ void compute_g_kernel(const float* __restrict__ fp,
                                 const float* __restrict__ metric,
                                 float* __restrict__ g)
{
    __shared__ float sm[F_*F_];
    for (int i = threadIdx.x; i < F_*F_; i += blockDim.x) sm[i] = metric[i];
    __syncthreads();
    int t = threadIdx.x;
    int f = t & 63, r = t >> 6;
    int i = blockIdx.x*4 + r;
    const float* fr = fp + (size_t)i*F_;
    float a = 0.f;
#pragma unroll
    for (int k = 0; k < F_; k++) a = fmaf(fr[k], sm[k*F_ + f], a);
    g[(size_t)i*F_ + f] = a;
}

__global__ void curv_kernel(const float* __restrict__ fp, const float* __restrict__ cm,
                            float* __restrict__ curv, float* __restrict__ curvb)
{
    int j = blockIdx.x*blockDim.x + threadIdx.x;
    if (j >= S_) return;
    float a = 0.f;
#pragma unroll
    for (int f = 0; f < F_; f++) a = fmaf(fp[(size_t)j*F_ + f], cm[f*(F_+1)], a);
    curv[j] = a;
    curvb[j] = COUPLING * a;
}

__global__ void pack_aug_kernel(const float* __restrict__ Q, const float* __restrict__ Km,
                                const float* __restrict__ g, const float* __restrict__ fp,
                                bf16* __restrict__ Qhi, bf16* __restrict__ Qlo,
                                bf16* __restrict__ Khi, bf16* __restrict__ Klo)
{
    int idx = blockIdx.x*blockDim.x + threadIdx.x;
    if (idx >= H_*S_*AUG) return;
    int d = idx % AUG;
    int i = (idx / AUG) % S_;
    int h = idx / (AUG*S_);
    float qv, kv;
    if (d < DK) {
        qv = Q[(size_t)i*DM + h*DK + d] * INV_SCALE;
        kv = Km[(size_t)i*DM + h*DK + d];
    } else {
        qv = COUPLING * g[(size_t)i*F_ + (d-DK)];
        kv = fp[(size_t)i*F_ + (d-DK)];
    }
    bf16 qh = __float2bfloat16(qv);
    Qhi[idx] = qh;
    Qlo[idx] = __float2bfloat16(qv - __bfloat162float(qh));
    bf16 kh = __float2bfloat16(kv);
    Khi[idx] = kh;
    Klo[idx] = __float2bfloat16(kv - __bfloat162float(kh));
}

__global__ void softmax_kernel(const float* __restrict__ P,
                               bf16* __restrict__ Phi, bf16* __restrict__ Plo)
{
    size_t row = blockIdx.x;
    const float* p = P + row * (size_t)S_;
    int t = threadIdx.x;
    float vals[8];
    float4 v0 = *(const float4*)(p + t*8);
    float4 v1 = *(const float4*)(p + t*8 + 4);
    vals[0]=v0.x; vals[1]=v0.y; vals[2]=v0.z; vals[3]=v0.w;
    vals[4]=v1.x; vals[5]=v1.y; vals[6]=v1.z; vals[7]=v1.w;
    float m = vals[0];
#pragma unroll
    for (int i = 1; i < 8; i++) m = fmaxf(m, vals[i]);
    __shared__ float red[8];
    for (int o = 16; o; o >>= 1) m = fmaxf(m, __shfl_xor_sync(~0u, m, o));
    if ((t & 31) == 0) red[t>>5] = m;
    __syncthreads();
    m = red[0];
#pragma unroll
    for (int i = 1; i < 8; i++) m = fmaxf(m, red[i]);
    float s = 0.f;
#pragma unroll
    for (int i = 0; i < 8; i++) { vals[i] = __expf(vals[i] - m); s += vals[i]; }
    for (int o = 16; o; o >>= 1) s += __shfl_xor_sync(~0u, s, o);
    __shared__ float red2[8];
    if ((t & 31) == 0) red2[t>>5] = s;
    __syncthreads();
    s = red2[0];
#pragma unroll
    for (int i = 1; i < 8; i++) s += red2[i];
    float inv = 1.0f / s;
    uint4 hv, lv;
    float w0 = vals[0]*inv, w1 = vals[1]*inv, w2 = vals[2]*inv, w3 = vals[3]*inv;
    float w4 = vals[4]*inv, w5 = vals[5]*inv, w6 = vals[6]*inv, w7 = vals[7]*inv;
    bf16 h0=__float2bfloat16(w0), h1=__float2bfloat16(w1), h2=__float2bfloat16(w2), h3=__float2bfloat16(w3);
    bf16 h4=__float2bfloat16(w4), h5=__float2bfloat16(w5), h6=__float2bfloat16(w6), h7=__float2bfloat16(w7);
    hv.x = (uint32_t)__bfloat16_as_ushort(h0) | ((uint32_t)__bfloat16_as_ushort(h1) << 16);
    hv.y = (uint32_t)__bfloat16_as_ushort(h2) | ((uint32_t)__bfloat16_as_ushort(h3) << 16);
    hv.z = (uint32_t)__bfloat16_as_ushort(h4) | ((uint32_t)__bfloat16_as_ushort(h5) << 16);
    hv.w = (uint32_t)__bfloat16_as_ushort(h6) | ((uint32_t)__bfloat16_as_ushort(h7) << 16);
    lv.x = pack_bf16x2(w0 - __bfloat162float(h0), w1 - __bfloat162float(h1));
    lv.y = pack_bf16x2(w2 - __bfloat162float(h2), w3 - __bfloat162float(h3));
    lv.z = pack_bf16x2(w4 - __bfloat162float(h4), w5 - __bfloat162float(h5));
    lv.w = pack_bf16x2(w6 - __bfloat162float(h6), w7 - __bfloat162float(h7));
    *(uint4*)(Phi + row * (size_t)S_ + t*8) = hv;
    *(uint4*)(Plo + row * (size_t)S_ + t*8) = lv;
}

__global__ void scalar_kernel(const float* __restrict__ g, const float* __restrict__ fpsum,
                              const float* __restrict__ curv, float* __restrict__ out0,
                              float* __restrict__ out1)
{
    __shared__ float sm[256];
    __shared__ float sc[256];
    int t = threadIdx.x;
    int f = t & 63, c = t >> 6;
    float s = 0.f;
    for (int i = c; i < S_; i += 4) s += g[i*F_ + f];
    sm[t] = s; __syncthreads();
    float tot = 0.f;
    if (c == 0) tot = sm[f] + sm[64+f] + sm[128+f] + sm[192+f];
    __syncthreads();
    sm[t] = (c == 0) ? tot * fpsum[f] : 0.f;
    float cs = 0.f;
    for (int j = t; j < S_; j += 256) cs += curv[j];
    sc[t] = cs;
    __syncthreads();
    if (t == 0) {
        float a = 0.f, b = 0.f;
        for (int i = 0; i < 64; i++) a += sm[i];
        for (int i = 0; i < 256; i++) b += sc[i];
        float val = a / ((float)S_ * (float)S_) + b / (float)S_;
        *out0 = val;
        if (out1) *out1 = val;
    }
}

// ================= launch =================
extern "C" void kernel_launch(void* const* d_in, const int* in_sizes, int n_in,
                              void* d_out, int out_size)
{
    const float* x    = (const float*)d_in[0];
    const float* wq   = (const float*)d_in[2];
    const float* wk   = (const float*)d_in[3];
    const float* wv   = (const float*)d_in[4];
    const float* wo_w = (const float*)d_in[5];
    const float* wo_b = (const float*)d_in[6];
    const float* fw   = (const float*)d_in[7];
    const float* fb   = (const float*)d_in[8];
    const float* fm1w = (const float*)d_in[9];
    const float* fm1b = (const float*)d_in[10];
    const float* fm2w = (const float*)d_in[11];
    const float* fm2b = (const float*)d_in[12];
    const float* cm   = (const float*)d_in[13];
    float* out = (float*)d_out;

    bf16 *xhi,*xlo,*wqkhi,*wqklo,*wvhi,*wvlo,*wohi,*wolo;
    bf16 *Vthi,*Vtlo,*Qahi,*Qalo,*Kahi,*Kalo,*Phi,*Plo,*athi,*atlo;
    float *QK,*fp,*fpart,*g,*metric,*mi,*fpsum,*curv,*curvb,*scores;
    cudaGetSymbolAddress((void**)&xhi, d_xhi);     cudaGetSymbolAddress((void**)&xlo, d_xlo);
    cudaGetSymbolAddress((void**)&wqkhi, d_wqkhi); cudaGetSymbolAddress((void**)&wqklo, d_wqklo);
    cudaGetSymbolAddress((void**)&wvhi, d_wvhi);   cudaGetSymbolAddress((void**)&wvlo, d_wvlo);
    cudaGetSymbolAddress((void**)&wohi, d_wohi);   cudaGetSymbolAddress((void**)&wolo, d_wolo);
    cudaGetSymbolAddress((void**)&Vthi, d_Vthi);   cudaGetSymbolAddress((void**)&Vtlo, d_Vtlo);
    cudaGetSymbolAddress((void**)&Qahi, d_Qahi);   cudaGetSymbolAddress((void**)&Qalo, d_Qalo);
    cudaGetSymbolAddress((void**)&Kahi, d_Kahi);   cudaGetSymbolAddress((void**)&Kalo, d_Kalo);
    cudaGetSymbolAddress((void**)&Phi, d_Phi);     cudaGetSymbolAddress((void**)&Plo, d_Plo);
    cudaGetSymbolAddress((void**)&athi, d_attnhi); cudaGetSymbolAddress((void**)&atlo, d_attnlo);
    cudaGetSymbolAddress((void**)&QK, d_QK);
    cudaGetSymbolAddress((void**)&fp, d_fp);       cudaGetSymbolAddress((void**)&fpart, d_fpart);
    cudaGetSymbolAddress((void**)&g, d_g);
    cudaGetSymbolAddress((void**)&metric, d_metric); cudaGetSymbolAddress((void**)&mi, d_mi);
    cudaGetSymbolAddress((void**)&fpsum, d_fpsum);   cudaGetSymbolAddress((void**)&curv, d_curv);
    cudaGetSymbolAddress((void**)&curvb, d_curvb);   cudaGetSymbolAddress((void**)&scores, d_scores);

    cudaFuncSetAttribute(mma_gemm_nt<1>, cudaFuncAttributeMaxDynamicSharedMemorySize, MMA_SMEM);
    cudaFuncSetAttribute(mma_gemm_nt_wide<0>, cudaFuncAttributeMaxDynamicSharedMemorySize, WMMA_SMEM);
    cudaFuncSetAttribute(mma_gemm_nt_wide<1>, cudaFuncAttributeMaxDynamicSharedMemorySize, WMMA_SMEM);

    const int NDM = S_*DM;
    // 0) all 5 bf16 hi/lo splits, vectorized x4, one launch
    split5_kernel<<<dim3(NDM/1024, 5), 256>>>(
        x, wq, wk, wv, wo_w,
        xhi, wqkhi, wqkhi + (size_t)DM*DM, wvhi, wohi,
        xlo, wqklo, wqklo + (size_t)DM*DM, wvlo, wolo);

    // 1) Q and K projections batched: z=2 (wide tile)
    mma_gemm_nt_wide<0><<<dim3(8,16,2), 256, WMMA_SMEM>>>(
        xhi, xlo, DM, 0, wqkhi, wqklo, DM, (size_t)DM*DM,
        QK, nullptr, nullptr, DM, (size_t)S_*DM, DM, nullptr);
    // 2) Vt[d][s] = wv @ x^T (wide tile, bf16 hi/lo out)
    mma_gemm_nt_wide<1><<<dim3(8,16,1), 256, WMMA_SMEM>>>(wvhi, wvlo, DM, 0, xhi, xlo, DM, 0,
                                                          nullptr, Vthi, Vtlo, S_, 0, DM, nullptr);
    // 3) fiber projection (deterministic split-K)
    fiber_gemm<<<dim3(16, 32), 256>>>(x, fw, fpart);
    fiber_reduce<<<S_*F_/256, 256>>>(fpart, fb, fp);
    // 4) stats -> MLP -> metric -> g -> curv
    fp_stats_kernel<<<1, 256>>>(fp, fpsum, mi);
    mlp_metric_kernel<<<1, 64>>>(mi, fm1w, fm1b, fm2w, fm2b, metric);
    compute_g_kernel<<<S_/4, 256>>>(fp, metric, g);
    curv_kernel<<<S_/256, 256>>>(fp, cm, curv, curvb);
    // 5) pack augmented Q/K hi/lo
    pack_aug_kernel<<<(H_*S_*AUG)/256, 256>>>(QK, QK + (size_t)S_*DM, g, fp,
                                              Qahi, Qalo, Kahi, Kalo);
    // 6) scores = Qaug @ Kaug^T + 0.1*curv[col] (wide tile, K=192, batched heads)
    mma_gemm_nt_wide<0><<<dim3(8,16,H_), 256, WMMA_SMEM>>>(
        Qahi, Qalo, AUG, (size_t)S_*AUG, Kahi, Kalo, AUG, (size_t)S_*AUG,
        scores, nullptr, nullptr, S_, (size_t)S_*S_, AUG, curvb);
    // 7) softmax -> P hi/lo (vectorized stores)
    softmax_kernel<<<H_*S_, 256>>>(scores, Phi, Plo);
    // 8) attn[q, h*128+d] = P[h] @ Vt[h]^T (narrow tile, N=128, bf16 hi/lo out)
    mma_gemm_nt<1><<<dim3(1,16,H_), 256, MMA_SMEM>>>(
        Phi, Plo, S_, (size_t)S_*S_, Vthi, Vtlo, S_, (size_t)DK*S_,
        nullptr, athi, atlo, DM, (size_t)DK, S_, nullptr);
    // 9) out = attn @ wo^T + wo_b (wide tile, fp32 -> d_out)
    mma_gemm_nt_wide<0><<<dim3(8,16,1), 256, WMMA_SMEM>>>(athi, atlo, DM, 0, wohi, wolo, DM, 0,
                                                          out, nullptr, nullptr, DM, 0, DM, wo_b);
    // 10) ci.mean() scalar
    if (out_size > S_*DM) {
        float* o0 = out + (size_t)S_*DM;
        float* o1 = out + (size_t)(out_size - 1);
        scalar_kernel<<<1, 256>>>(g, fpsum, curv, o0, (o1 != o0) ? o1 : nullptr);
    }
}

// round 10
// speedup vs baseline: 1.0146x; 1.0146x over previous
#include <cuda_runtime.h>
#include <cuda_bf16.h>
#include <cstdint>
#include <math.h>

#define S_  2048
#define DM  2048
#define H_  16
#define DK  128
#define F_  64
#define AUG 192
#define INV_SCALE (1.0f/11.313708498984761f)
#define COUPLING 0.1f

typedef __nv_bfloat16 bf16;

// ---------------- device scratch (256B-aligned) ----------------
__device__ __align__(256) bf16  d_xhi[S_*DM],  d_xlo[S_*DM];
__device__ __align__(256) bf16  d_wqkhi[2*DM*DM], d_wqklo[2*DM*DM];   // wq then wk
__device__ __align__(256) bf16  d_wvhi[DM*DM], d_wvlo[DM*DM];
__device__ __align__(256) bf16  d_wohi[DM*DM], d_wolo[DM*DM];
__device__ __align__(256) float d_QK[2*S_*DM];                        // Q then K (fp32)
__device__ __align__(256) bf16  d_Vthi[DM*S_], d_Vtlo[DM*S_];         // V transposed [d][s]
__device__ __align__(256) float d_fp[S_*F_];
__device__ __align__(256) float d_fpart[16*S_*F_];
__device__ __align__(256) float d_g[S_*F_];
__device__ __align__(256) float d_metric[F_*F_];
__device__ __align__(256) float d_mi[F_];
__device__ __align__(256) float d_fpsum[F_];
__device__ __align__(256) float d_curv[S_];
__device__ __align__(256) float d_curvb[S_];
__device__ __align__(256) bf16  d_Qahi[H_*S_*AUG], d_Qalo[H_*S_*AUG];
__device__ __align__(256) bf16  d_Kahi[H_*S_*AUG], d_Kalo[H_*S_*AUG];
__device__ __align__(256) float d_scores[H_*S_*S_];
__device__ __align__(256) bf16  d_Phi[H_*S_*S_], d_Plo[H_*S_*S_];
__device__ __align__(256) bf16  d_attnhi[S_*DM], d_attnlo[S_*DM];

// ================= portable-ISA helpers =================
__device__ __forceinline__ uint32_t smem_to_u32(const void* p) {
    uint32_t a;
    asm("{ .reg .u64 t; cvta.to.shared.u64 t, %1; cvt.u32.u64 %0, t; }" : "=r"(a) : "l"(p));
    return a;
}
__device__ __forceinline__ void cp16(uint32_t saddr, const void* g) {
    asm volatile("cp.async.cg.shared.global [%0], [%1], 16;" :: "r"(saddr), "l"(g));
}
__device__ __forceinline__ void ldsm4(uint32_t* r, uint32_t a) {
    asm volatile("ldmatrix.sync.aligned.m8n8.x4.shared.b16 {%0,%1,%2,%3}, [%4];"
                 : "=r"(r[0]), "=r"(r[1]), "=r"(r[2]), "=r"(r[3]) : "r"(a));
}
__device__ __forceinline__ void mma_bf16(float* c, const uint32_t* a, uint32_t b0, uint32_t b1) {
    asm volatile("mma.sync.aligned.m16n8k16.row.col.f32.bf16.bf16.f32 "
                 "{%0,%1,%2,%3}, {%4,%5,%6,%7}, {%8,%9}, {%0,%1,%2,%3};"
                 : "+f"(c[0]), "+f"(c[1]), "+f"(c[2]), "+f"(c[3])
                 : "r"(a[0]), "r"(a[1]), "r"(a[2]), "r"(a[3]), "r"(b0), "r"(b1));
}
__device__ __forceinline__ uint32_t pack_bf16x2(float lo, float hi) {
    uint32_t r;
    unsigned short l = __bfloat16_as_ushort(__float2bfloat16(lo));
    unsigned short h = __bfloat16_as_ushort(__float2bfloat16(hi));
    r = (uint32_t)l | ((uint32_t)h << 16);
    return r;
}

__device__ __forceinline__ uint32_t sw_off(int row, int chunk) {
    return (uint32_t)(row * 64 + ((chunk ^ ((row >> 1) & 3)) << 4));
}

// smem stage: Ahi | Alo | Bhi | Blo, each 128 rows x 32 bf16 (64B rows), XOR swizzled
#define STAGE_BYTES 32768
#define MMA_SMEM (2*STAGE_BYTES)

__device__ __forceinline__ void load_tiles(uint32_t sbase, int tid,
    const bf16* g0, const bf16* g1, const bf16* g2, const bf16* g3,
    int lda, int ldb, int k0)
{
    const bf16* gp[4] = {g0, g1, g2, g3};
#pragma unroll
    for (int i = 0; i < 8; i++) {
        int q = tid + i * 256;
        int tile = q >> 9, r = (q >> 2) & 127, c = q & 3;
        int ld = (tile < 2) ? lda : ldb;
        const bf16* src = gp[tile] + (size_t)r * ld + k0 + c * 8;
        uint32_t so = sbase + tile * 8192 + sw_off(r, c);
        cp16(so, src);
    }
    asm volatile("cp.async.commit_group;" ::: "memory");
}

// ================= NT GEMM via mma.sync, 3-term bf16 split, single-barrier mainloop =================
// C[bm.., bn..] = sum_k A[m,k]*B[n,k]; M,N multiples of 128; K multiple of 32; batch z.
// OUT_MODE 0: fp32 C (+bias[col]);  OUT_MODE 1: bf16 hi/lo outputs.
template<int OUT_MODE>
__global__ void __launch_bounds__(256)
mma_gemm_nt(const bf16* __restrict__ Ahi, const bf16* __restrict__ Alo, int lda, size_t sAz,
            const bf16* __restrict__ Bhi, const bf16* __restrict__ Blo, int ldb, size_t sBz,
            float* __restrict__ C, bf16* __restrict__ Chi, bf16* __restrict__ Clo,
            int ldc, size_t sCz, int K, const float* __restrict__ bias)
{
    extern __shared__ char smem[];
    const uint32_t sb = smem_to_u32(smem);
    const int tid = threadIdx.x, lane = tid & 31, wid = tid >> 5;
    const int wm = wid & 1, wn = wid >> 1;           // 2 x 4 warp grid, warp tile 64x32
    const size_t z = blockIdx.z;
    const int bm = blockIdx.y * 128, bn = blockIdx.x * 128;

    const bf16* gA0 = Ahi + z * sAz + (size_t)bm * lda;
    const bf16* gA1 = Alo + z * sAz + (size_t)bm * lda;
    const bf16* gB0 = Bhi + z * sBz + (size_t)bn * ldb;
    const bf16* gB1 = Blo + z * sBz + (size_t)bn * ldb;

    float acc[4][4][4];
#pragma unroll
    for (int i = 0; i < 4; i++)
#pragma unroll
        for (int j = 0; j < 4; j++)
#pragma unroll
            for (int k = 0; k < 4; k++) acc[i][j][k] = 0.f;

    const int a_row_l = (lane & 7) + ((lane >> 3) & 1) * 8;
    const int a_chk_l = lane >> 4;
    const int b_row_l = (lane & 7) + ((lane >> 4) & 1) * 8;
    const int b_chk_l = (lane >> 3) & 1;

    const int nch = K >> 5;
    load_tiles(sb, tid, gA0, gA1, gB0, gB1, lda, ldb, 0);

    for (int c = 0; c < nch; c++) {
        // wait for stage c (the only outstanding group), then ONE barrier:
        // gives cross-thread visibility of stage c AND proves all warps are
        // done computing stage c-1, so its buffer may be overwritten below.
        asm volatile("cp.async.wait_group 0;" ::: "memory");
        __syncthreads();
        if (c + 1 < nch)
            load_tiles(sb + ((c + 1) & 1) * STAGE_BYTES, tid, gA0, gA1, gB0, gB1,
                       lda, ldb, (c + 1) * 32);

        const uint32_t s0 = sb + (c & 1) * STAGE_BYTES;
#pragma unroll
        for (int ks = 0; ks < 2; ks++) {
            uint32_t a_hi[4][4], a_lo[4][4], b_hi[8], b_lo[8];
#pragma unroll
            for (int mt = 0; mt < 4; mt++) {
                int row = wm * 64 + mt * 16 + a_row_l;
                uint32_t off = sw_off(row, ks * 2 + a_chk_l);
                ldsm4(a_hi[mt], s0 + off);
                ldsm4(a_lo[mt], s0 + 8192 + off);
            }
#pragma unroll
            for (int ntp = 0; ntp < 2; ntp++) {
                int row = wn * 32 + ntp * 16 + b_row_l;
                uint32_t off = sw_off(row, ks * 2 + b_chk_l);
                ldsm4(&b_hi[ntp * 4], s0 + 16384 + off);
                ldsm4(&b_lo[ntp * 4], s0 + 24576 + off);
            }
#pragma unroll
            for (int mt = 0; mt < 4; mt++)
#pragma unroll
                for (int nt = 0; nt < 4; nt++) {
                    int bi = (nt >> 1) * 4 + (nt & 1) * 2;
                    mma_bf16(acc[mt][nt], a_hi[mt], b_hi[bi], b_hi[bi + 1]);
                    mma_bf16(acc[mt][nt], a_hi[mt], b_lo[bi], b_lo[bi + 1]);
                    mma_bf16(acc[mt][nt], a_lo[mt], b_hi[bi], b_hi[bi + 1]);
                }
        }
    }

    // epilogue
    const int r_l = lane >> 2, c_l = (lane & 3) * 2;
#pragma unroll
    for (int mt = 0; mt < 4; mt++) {
#pragma unroll
        for (int nt = 0; nt < 4; nt++) {
            int row0 = bm + wm * 64 + mt * 16 + r_l;
            int col  = bn + wn * 32 + nt * 8 + c_l;
            float v0 = acc[mt][nt][0], v1 = acc[mt][nt][1];
            float v2 = acc[mt][nt][2], v3 = acc[mt][nt][3];
            if (OUT_MODE == 0) {
                if (bias) { v0 += bias[col]; v1 += bias[col + 1]; v2 += bias[col]; v3 += bias[col + 1]; }
                float* p0 = C + z * sCz + (size_t)row0 * ldc + col;
                float* p1 = C + z * sCz + (size_t)(row0 + 8) * ldc + col;
                p0[0] = v0; p0[1] = v1;
                p1[0] = v2; p1[1] = v3;
            } else {
                bf16 h0 = __float2bfloat16(v0), h1 = __float2bfloat16(v1);
                bf16 h2 = __float2bfloat16(v2), h3 = __float2bfloat16(v3);
                bf16 l0 = __float2bfloat16(v0 - __bfloat162float(h0));
                bf16 l1 = __float2bfloat16(v1 - __bfloat162float(h1));
                bf16 l2 = __float2bfloat16(v2 - __bfloat162float(h2));
                bf16 l3 = __float2bfloat16(v3 - __bfloat162float(h3));
                bf16* hp0 = Chi + z * sCz + (size_t)row0 * ldc + col;
                bf16* hp1 = Chi + z * sCz + (size_t)(row0 + 8) * ldc + col;
                bf16* lp0 = Clo + z * sCz + (size_t)row0 * ldc + col;
                bf16* lp1 = Clo + z * sCz + (size_t)(row0 + 8) * ldc + col;
                hp0[0] = h0; hp0[1] = h1; hp1[0] = h2; hp1[1] = h3;
                lp0[0] = l0; lp0[1] = l1; lp1[0] = l2; lp1[1] = l3;
            }
        }
    }
}

// ================= small kernels =================
__global__ void split5_kernel(
    const float* __restrict__ s0, const float* __restrict__ s1, const float* __restrict__ s2,
    const float* __restrict__ s3, const float* __restrict__ s4,
    bf16* __restrict__ h0, bf16* __restrict__ h1, bf16* __restrict__ h2,
    bf16* __restrict__ h3, bf16* __restrict__ h4,
    bf16* __restrict__ l0, bf16* __restrict__ l1, bf16* __restrict__ l2,
    bf16* __restrict__ l3, bf16* __restrict__ l4)
{
    int i4 = blockIdx.x * blockDim.x + threadIdx.x;
    int zz = blockIdx.y;
    const float* src = (zz == 0) ? s0 : (zz == 1) ? s1 : (zz == 2) ? s2 : (zz == 3) ? s3 : s4;
    bf16* hi = (zz == 0) ? h0 : (zz == 1) ? h1 : (zz == 2) ? h2 : (zz == 3) ? h3 : h4;
    bf16* lo = (zz == 0) ? l0 : (zz == 1) ? l1 : (zz == 2) ? l2 : (zz == 3) ? l3 : l4;
    float4 v = *((const float4*)src + i4);
    bf16 a = __float2bfloat16(v.x), b = __float2bfloat16(v.y);
    bf16 c = __float2bfloat16(v.z), d = __float2bfloat16(v.w);
    uint2 hv, lv;
    hv.x = (uint32_t)__bfloat16_as_ushort(a) | ((uint32_t)__bfloat16_as_ushort(b) << 16);
    hv.y = (uint32_t)__bfloat16_as_ushort(c) | ((uint32_t)__bfloat16_as_ushort(d) << 16);
    lv.x = pack_bf16x2(v.x - __bfloat162float(a), v.y - __bfloat162float(b));
    lv.y = pack_bf16x2(v.z - __bfloat162float(c), v.w - __bfloat162float(d));
    *((uint2*)hi + i4) = hv;
    *((uint2*)lo + i4) = lv;
}

__global__ void fiber_gemm(const float* __restrict__ x, const float* __restrict__ fw,
                           float* __restrict__ fpart)
{
    __shared__ float Xs[64][68];
    __shared__ float Fs[64][68];
    const int ksplit = blockIdx.x;
    const int rb = blockIdx.y * 64;
    const int t = threadIdx.x;
    const int rt = t & 15, ct = t >> 4;
    float acc[4][4] = {};
    for (int sub = 0; sub < 2; sub++) {
        const int k0 = ksplit * 128 + sub * 64;
        __syncthreads();
        for (int i = t; i < 1024; i += 256) {
            int row = i >> 4, kq = (i & 15) * 4;
            float4 v = *(const float4*)&x[(size_t)(rb + row) * DM + k0 + kq];
            Xs[kq][row] = v.x; Xs[kq+1][row] = v.y; Xs[kq+2][row] = v.z; Xs[kq+3][row] = v.w;
            float4 w = *(const float4*)&fw[(size_t)row * DM + k0 + kq];
            Fs[kq][row] = w.x; Fs[kq+1][row] = w.y; Fs[kq+2][row] = w.z; Fs[kq+3][row] = w.w;
        }
        __syncthreads();
#pragma unroll 16
        for (int k = 0; k < 64; k++) {
            float a[4], b[4];
#pragma unroll
            for (int i = 0; i < 4; i++) a[i] = Xs[k][rt*4 + i];
#pragma unroll
            for (int j = 0; j < 4; j++) b[j] = Fs[k][ct*4 + j];
#pragma unroll
            for (int i = 0; i < 4; i++)
#pragma unroll
                for (int j = 0; j < 4; j++) acc[i][j] = fmaf(a[i], b[j], acc[i][j]);
        }
    }
    float* dst = fpart + (size_t)ksplit * S_ * F_;
#pragma unroll
    for (int i = 0; i < 4; i++)
#pragma unroll
        for (int j = 0; j < 4; j++)
            dst[(size_t)(rb + rt*4 + i) * F_ + ct*4 + j] = acc[i][j];
}

__global__ void fiber_reduce(const float* __restrict__ fpart, const float* __restrict__ fb,
                             float* __restrict__ fp)
{
    int i = blockIdx.x * blockDim.x + threadIdx.x;
    if (i >= S_ * F_) return;
    float a = fb[i & 63];
#pragma unroll
    for (int s = 0; s < 16; s++) a += fpart[(size_t)s * S_ * F_ + i];
    fp[i] = a;
}

__global__ void fp_stats_kernel(const float* __restrict__ fp,
                                float* __restrict__ fpsum, float* __restrict__ mi)
{
    __shared__ float sm[256];
    int t = threadIdx.x;
    int f = t & 63, c = t >> 6;
    float s = 0.f;
    for (int i = c; i < S_; i += 4) s += fp[i*F_ + f];
    sm[t] = s; __syncthreads();
    if (c == 0) {
        float tot = sm[f] + sm[64+f] + sm[128+f] + sm[192+f];
        fpsum[f] = tot;
        mi[f] = tot / (float)S_;
    }
}

__global__ void mlp_metric_kernel(const float* __restrict__ mi,
                                  const float* __restrict__ fm1w, const float* __restrict__ fm1b,
                                  const float* __restrict__ fm2w, const float* __restrict__ fm2b,
                                  float* __restrict__ metric)
{
    __shared__ float smi[F_];
    __shared__ float hid[F_/2];
    __shared__ float raw[F_];
    int t = threadIdx.x;
    smi[t] = mi[t];
    __syncthreads();
    if (t < F_/2) {
        float a = fm1b[t];
        for (int f = 0; f < F_; f++) a = fmaf(smi[f], fm1w[t*F_ + f], a);
        hid[t] = fmaxf(a, 0.f);
    }
    __syncthreads();
    {
        float a = fm2b[t];
        for (int j = 0; j < F_/2; j++) a = fmaf(hid[j], fm2w[t*(F_/2) + j], a);
        raw[t] = a;
    }
    __syncthreads();
    for (int b = 0; b < F_; b++)
        metric[t*F_ + b] = raw[t]*raw[b] + ((t == b) ? 0.1f : 0.f);
}

__global__ void compute_g_kernel(const float* __restrict__ fp,
                                 const float* __restrict__ metric,
                                 float* __restrict__ g)
{
    __shared__ float sm[F_*F_];
    for (int i = threadIdx.x; i < F_*F_; i += blockDim.x) sm[i] = metric[i];
    __syncthreads();
    int t = threadIdx.x;
    int f = t & 63, r = t >> 6;
    int i = blockIdx.x*4 + r;
    const float* fr = fp + (size_t)i*F_;
    float a = 0.f;
#pragma unroll
    for (int k = 0; k < F_; k++) a = fmaf(fr[k], sm[k*F_ + f], a);
    g[(size_t)i*F_ + f] = a;
}

__global__ void curv_kernel(const float* __restrict__ fp, const float* __restrict__ cm,
                            float* __restrict__ curv, float* __restrict__ curvb)
{
    int j = blockIdx.x*blockDim.x + threadIdx.x;
    if (j >= S_) return;
    float a = 0.f;
#pragma unroll
    for (int f = 0; f < F_; f++) a = fmaf(fp[(size_t)j*F_ + f], cm[f*(F_+1)], a);
    curv[j] = a;
    curvb[j] = COUPLING * a;
}

__global__ void pack_aug_kernel(const float* __restrict__ Q, const float* __restrict__ Km,
                                const float* __restrict__ g, const float* __restrict__ fp,
                                bf16* __restrict__ Qhi, bf16* __restrict__ Qlo,
                                bf16* __restrict__ Khi, bf16* __restrict__ Klo)
{
    int idx = blockIdx.x*blockDim.x + threadIdx.x;
    if (idx >= H_*S_*AUG) return;
    int d = idx % AUG;
    int i = (idx / AUG) % S_;
    int h = idx / (AUG*S_);
    float qv, kv;
    if (d < DK) {
        qv = Q[(size_t)i*DM + h*DK + d] * INV_SCALE;
        kv = Km[(size_t)i*DM + h*DK + d];
    } else {
        qv = COUPLING * g[(size_t)i*F_ + (d-DK)];
        kv = fp[(size_t)i*F_ + (d-DK)];
    }
    bf16 qh = __float2bfloat16(qv);
    Qhi[idx] = qh;
    Qlo[idx] = __float2bfloat16(qv - __bfloat162float(qh));
    bf16 kh = __float2bfloat16(kv);
    Khi[idx] = kh;
    Klo[idx] = __float2bfloat16(kv - __bfloat162float(kh));
}

__global__ void softmax_kernel(const float* __restrict__ P,
                               bf16* __restrict__ Phi, bf16* __restrict__ Plo)
{
    size_t row = blockIdx.x;
    const float* p = P + row * (size_t)S_;
    int t = threadIdx.x;
    float vals[8];
    float4 v0 = *(const float4*)(p + t*8);
    float4 v1 = *(const float4*)(p + t*8 + 4);
    vals[0]=v0.x; vals[1]=v0.y; vals[2]=v0.z; vals[3]=v0.w;
    vals[4]=v1.x; vals[5]=v1.y; vals[6]=v1.z; vals[7]=v1.w;
    float m = vals[0];
#pragma unroll
    for (int i = 1; i < 8; i++) m = fmaxf(m, vals[i]);
    __shared__ float red[8];
    for (int o = 16; o; o >>= 1) m = fmaxf(m, __shfl_xor_sync(~0u, m, o));
    if ((t & 31) == 0) red[t>>5] = m;
    __syncthreads();
    m = red[0];
#pragma unroll
    for (int i = 1; i < 8; i++) m = fmaxf(m, red[i]);
    float s = 0.f;
#pragma unroll
    for (int i = 0; i < 8; i++) { vals[i] = __expf(vals[i] - m); s += vals[i]; }
    for (int o = 16; o; o >>= 1) s += __shfl_xor_sync(~0u, s, o);
    __shared__ float red2[8];
    if ((t & 31) == 0) red2[t>>5] = s;
    __syncthreads();
    s = red2[0];
#pragma unroll
    for (int i = 1; i < 8; i++) s += red2[i];
    float inv = 1.0f / s;
    uint4 hv, lv;
    float w0 = vals[0]*inv, w1 = vals[1]*inv, w2 = vals[2]*inv, w3 = vals[3]*inv;
    float w4 = vals[4]*inv, w5 = vals[5]*inv, w6 = vals[6]*inv, w7 = vals[7]*inv;
    bf16 h0=__float2bfloat16(w0), h1=__float2bfloat16(w1), h2=__float2bfloat16(w2), h3=__float2bfloat16(w3);
    bf16 h4=__float2bfloat16(w4), h5=__float2bfloat16(w5), h6=__float2bfloat16(w6), h7=__float2bfloat16(w7);
    hv.x = (uint32_t)__bfloat16_as_ushort(h0) | ((uint32_t)__bfloat16_as_ushort(h1) << 16);
    hv.y = (uint32_t)__bfloat16_as_ushort(h2) | ((uint32_t)__bfloat16_as_ushort(h3) << 16);
    hv.z = (uint32_t)__bfloat16_as_ushort(h4) | ((uint32_t)__bfloat16_as_ushort(h5) << 16);
    hv.w = (uint32_t)__bfloat16_as_ushort(h6) | ((uint32_t)__bfloat16_as_ushort(h7) << 16);
    lv.x = pack_bf16x2(w0 - __bfloat162float(h0), w1 - __bfloat162float(h1));
    lv.y = pack_bf16x2(w2 - __bfloat162float(h2), w3 - __bfloat162float(h3));
    lv.z = pack_bf16x2(w4 - __bfloat162float(h4), w5 - __bfloat162float(h5));
    lv.w = pack_bf16x2(w6 - __bfloat162float(h6), w7 - __bfloat162float(h7));
    *(uint4*)(Phi + row * (size_t)S_ + t*8) = hv;
    *(uint4*)(Plo + row * (size_t)S_ + t*8) = lv;
}

__global__ void scalar_kernel(const float* __restrict__ g, const float* __restrict__ fpsum,
                              const float* __restrict__ curv, float* __restrict__ out0,
                              float* __restrict__ out1)
{
    __shared__ float sm[256];
    __shared__ float sc[256];
    int t = threadIdx.x;
    int f = t & 63, c = t >> 6;
    float s = 0.f;
    for (int i = c; i < S_; i += 4) s += g[i*F_ + f];
    sm[t] = s; __syncthreads();
    float tot = 0.f;
    if (c == 0) tot = sm[f] + sm[64+f] + sm[128+f] + sm[192+f];
    __syncthreads();
    sm[t] = (c == 0) ? tot * fpsum[f] : 0.f;
    float cs = 0.f;
    for (int j = t; j < S_; j += 256) cs += curv[j];
    sc[t] = cs;
    __syncthreads();
    if (t == 0) {
        float a = 0.f, b = 0.f;
        for (int i = 0; i < 64; i++) a += sm[i];
        for (int i = 0; i < 256; i++) b += sc[i];
        float val = a / ((float)S_ * (float)S_) + b / (float)S_;
        *out0 = val;
        if (out1) *out1 = val;
    }
}

// ================= launch =================
extern "C" void kernel_launch(void* const* d_in, const int* in_sizes, int n_in,
                              void* d_out, int out_size)
{
    const float* x    = (const float*)d_in[0];
    const float* wq   = (const float*)d_in[2];
    const float* wk   = (const float*)d_in[3];
    const float* wv   = (const float*)d_in[4];
    const float* wo_w = (const float*)d_in[5];
    const float* wo_b = (const float*)d_in[6];
    const float* fw   = (const float*)d_in[7];
    const float* fb   = (const float*)d_in[8];
    const float* fm1w = (const float*)d_in[9];
    const float* fm1b = (const float*)d_in[10];
    const float* fm2w = (const float*)d_in[11];
    const float* fm2b = (const float*)d_in[12];
    const float* cm   = (const float*)d_in[13];
    float* out = (float*)d_out;

    bf16 *xhi,*xlo,*wqkhi,*wqklo,*wvhi,*wvlo,*wohi,*wolo;
    bf16 *Vthi,*Vtlo,*Qahi,*Qalo,*Kahi,*Kalo,*Phi,*Plo,*athi,*atlo;
    float *QK,*fp,*fpart,*g,*metric,*mi,*fpsum,*curv,*curvb,*scores;
    cudaGetSymbolAddress((void**)&xhi, d_xhi);     cudaGetSymbolAddress((void**)&xlo, d_xlo);
    cudaGetSymbolAddress((void**)&wqkhi, d_wqkhi); cudaGetSymbolAddress((void**)&wqklo, d_wqklo);
    cudaGetSymbolAddress((void**)&wvhi, d_wvhi);   cudaGetSymbolAddress((void**)&wvlo, d_wvlo);
    cudaGetSymbolAddress((void**)&wohi, d_wohi);   cudaGetSymbolAddress((void**)&wolo, d_wolo);
    cudaGetSymbolAddress((void**)&Vthi, d_Vthi);   cudaGetSymbolAddress((void**)&Vtlo, d_Vtlo);
    cudaGetSymbolAddress((void**)&Qahi, d_Qahi);   cudaGetSymbolAddress((void**)&Qalo, d_Qalo);
    cudaGetSymbolAddress((void**)&Kahi, d_Kahi);   cudaGetSymbolAddress((void**)&Kalo, d_Kalo);
    cudaGetSymbolAddress((void**)&Phi, d_Phi);     cudaGetSymbolAddress((void**)&Plo, d_Plo);
    cudaGetSymbolAddress((void**)&athi, d_attnhi); cudaGetSymbolAddress((void**)&atlo, d_attnlo);
    cudaGetSymbolAddress((void**)&QK, d_QK);
    cudaGetSymbolAddress((void**)&fp, d_fp);       cudaGetSymbolAddress((void**)&fpart, d_fpart);
    cudaGetSymbolAddress((void**)&g, d_g);
    cudaGetSymbolAddress((void**)&metric, d_metric); cudaGetSymbolAddress((void**)&mi, d_mi);
    cudaGetSymbolAddress((void**)&fpsum, d_fpsum);   cudaGetSymbolAddress((void**)&curv, d_curv);
    cudaGetSymbolAddress((void**)&curvb, d_curvb);   cudaGetSymbolAddress((void**)&scores, d_scores);

    cudaFuncSetAttribute(mma_gemm_nt<0>, cudaFuncAttributeMaxDynamicSharedMemorySize, MMA_SMEM);
    cudaFuncSetAttribute(mma_gemm_nt<1>, cudaFuncAttributeMaxDynamicSharedMemorySize, MMA_SMEM);

    const int NDM = S_*DM;
    // 0) all 5 bf16 hi/lo splits, vectorized x4, one launch
    split5_kernel<<<dim3(NDM/1024, 5), 256>>>(
        x, wq, wk, wv, wo_w,
        xhi, wqkhi, wqkhi + (size_t)DM*DM, wvhi, wohi,
        xlo, wqklo, wqklo + (size_t)DM*DM, wvlo, wolo);

    // 1) Q and K projections batched: z=2 (fp32 out, contiguous in d_QK)
    mma_gemm_nt<0><<<dim3(16,16,2), 256, MMA_SMEM>>>(
        xhi, xlo, DM, 0, wqkhi, wqklo, DM, (size_t)DM*DM,
        QK, nullptr, nullptr, DM, (size_t)S_*DM, DM, nullptr);
    // 2) Vt[d][s] = wv @ x^T (bf16 hi/lo out)
    mma_gemm_nt<1><<<dim3(16,16,1), 256, MMA_SMEM>>>(wvhi, wvlo, DM, 0, xhi, xlo, DM, 0,
                                                     nullptr, Vthi, Vtlo, S_, 0, DM, nullptr);
    // 3) fiber projection (deterministic split-K)
    fiber_gemm<<<dim3(16, 32), 256>>>(x, fw, fpart);
    fiber_reduce<<<S_*F_/256, 256>>>(fpart, fb, fp);
    // 4) stats -> MLP -> metric -> g -> curv
    fp_stats_kernel<<<1, 256>>>(fp, fpsum, mi);
    mlp_metric_kernel<<<1, 64>>>(mi, fm1w, fm1b, fm2w, fm2b, metric);
    compute_g_kernel<<<S_/4, 256>>>(fp, metric, g);
    curv_kernel<<<S_/256, 256>>>(fp, cm, curv, curvb);
    // 5) pack augmented Q/K hi/lo
    pack_aug_kernel<<<(H_*S_*AUG)/256, 256>>>(QK, QK + (size_t)S_*DM, g, fp,
                                              Qahi, Qalo, Kahi, Kalo);
    // 6) scores = Qaug @ Kaug^T + 0.1*curv[col] (K=192, batched heads)
    mma_gemm_nt<0><<<dim3(16,16,H_), 256, MMA_SMEM>>>(
        Qahi, Qalo, AUG, (size_t)S_*AUG, Kahi, Kalo, AUG, (size_t)S_*AUG,
        scores, nullptr, nullptr, S_, (size_t)S_*S_, AUG, curvb);
    // 7) softmax -> P hi/lo (vectorized stores)
    softmax_kernel<<<H_*S_, 256>>>(scores, Phi, Plo);
    // 8) attn[q, h*128+d] = P[h] @ Vt[h]^T (bf16 hi/lo out)
    mma_gemm_nt<1><<<dim3(1,16,H_), 256, MMA_SMEM>>>(
        Phi, Plo, S_, (size_t)S_*S_, Vthi, Vtlo, S_, (size_t)DK*S_,
        nullptr, athi, atlo, DM, (size_t)DK, S_, nullptr);
    // 9) out = attn @ wo^T + wo_b (fp32 -> d_out)
    mma_gemm_nt<0><<<dim3(16,16,1), 256, MMA_SMEM>>>(athi, atlo, DM, 0, wohi, wolo, DM, 0,
                                                     out, nullptr, nullptr, DM, 0, DM, wo_b);
    // 10) ci.mean() scalar
    if (out_size > S_*DM) {
        float* o0 = out + (size_t)S_*DM;
        float* o1 = out + (size_t)(out_size - 1);
        scalar_kernel<<<1, 256>>>(g, fpsum, curv, o0, (o1 != o0) ? o1 : nullptr);
    }
}

// round 11
// speedup vs baseline: 1.0436x; 1.0286x over previous
#include <cuda_runtime.h>
#include <cuda_bf16.h>
#include <cstdint>
#include <math.h>

#define S_  2048
#define DM  2048
#define H_  16
#define DK  128
#define F_  64
#define AUG 192
#define INV_SCALE (1.0f/11.313708498984761f)
#define COUPLING 0.1f

typedef __nv_bfloat16 bf16;

// ---------------- device scratch (256B-aligned) ----------------
__device__ __align__(256) bf16  d_xhi[S_*DM],  d_xlo[S_*DM];
__device__ __align__(256) bf16  d_wqkhi[2*DM*DM], d_wqklo[2*DM*DM];   // wq then wk
__device__ __align__(256) bf16  d_wvhi[DM*DM], d_wvlo[DM*DM];
__device__ __align__(256) bf16  d_wohi[DM*DM], d_wolo[DM*DM];
__device__ __align__(256) bf16  d_Vthi[DM*S_], d_Vtlo[DM*S_];         // V transposed [d][s]
__device__ __align__(256) float d_fp[S_*F_];
__device__ __align__(256) float d_fpart[16*S_*F_];
__device__ __align__(256) float d_g[S_*F_];
__device__ __align__(256) float d_metric[F_*F_];
__device__ __align__(256) float d_mi[F_];
__device__ __align__(256) float d_fpsum[F_];
__device__ __align__(256) float d_curv[S_];
__device__ __align__(256) float d_curvb[S_];
__device__ __align__(256) bf16  d_Qahi[H_*S_*AUG], d_Qalo[H_*S_*AUG];
__device__ __align__(256) bf16  d_Kahi[H_*S_*AUG], d_Kalo[H_*S_*AUG];
__device__ __align__(256) float d_scores[H_*S_*S_];
__device__ __align__(256) bf16  d_Phi[H_*S_*S_], d_Plo[H_*S_*S_];
__device__ __align__(256) bf16  d_attnhi[S_*DM], d_attnlo[S_*DM];

// ================= portable-ISA helpers =================
__device__ __forceinline__ uint32_t smem_to_u32(const void* p) {
    uint32_t a;
    asm("{ .reg .u64 t; cvta.to.shared.u64 t, %1; cvt.u32.u64 %0, t; }" : "=r"(a) : "l"(p));
    return a;
}
__device__ __forceinline__ void cp16(uint32_t saddr, const void* g) {
    asm volatile("cp.async.cg.shared.global [%0], [%1], 16;" :: "r"(saddr), "l"(g));
}
__device__ __forceinline__ void ldsm4(uint32_t* r, uint32_t a) {
    asm volatile("ldmatrix.sync.aligned.m8n8.x4.shared.b16 {%0,%1,%2,%3}, [%4];"
                 : "=r"(r[0]), "=r"(r[1]), "=r"(r[2]), "=r"(r[3]) : "r"(a));
}
__device__ __forceinline__ void mma_bf16(float* c, const uint32_t* a, uint32_t b0, uint32_t b1) {
    asm volatile("mma.sync.aligned.m16n8k16.row.col.f32.bf16.bf16.f32 "
                 "{%0,%1,%2,%3}, {%4,%5,%6,%7}, {%8,%9}, {%0,%1,%2,%3};"
                 : "+f"(c[0]), "+f"(c[1]), "+f"(c[2]), "+f"(c[3])
                 : "r"(a[0]), "r"(a[1]), "r"(a[2]), "r"(a[3]), "r"(b0), "r"(b1));
}
__device__ __forceinline__ uint32_t pack_bf16x2(float lo, float hi) {
    uint32_t r;
    unsigned short l = __bfloat16_as_ushort(__float2bfloat16(lo));
    unsigned short h = __bfloat16_as_ushort(__float2bfloat16(hi));
    r = (uint32_t)l | ((uint32_t)h << 16);
    return r;
}

__device__ __forceinline__ uint32_t sw_off(int row, int chunk) {
    return (uint32_t)(row * 64 + ((chunk ^ ((row >> 1) & 3)) << 4));
}

// smem stage: Ahi | Alo | Bhi | Blo, each 128 rows x 32 bf16 (64B rows), XOR swizzled
#define STAGE_BYTES 32768
#define MMA_SMEM (2*STAGE_BYTES)

__device__ __forceinline__ void load_tiles(uint32_t sbase, int tid,
    const bf16* g0, const bf16* g1, const bf16* g2, const bf16* g3,
    int lda, int ldb, int k0)
{
    const bf16* gp[4] = {g0, g1, g2, g3};
#pragma unroll
    for (int i = 0; i < 8; i++) {
        int q = tid + i * 256;
        int tile = q >> 9, r = (q >> 2) & 127, c = q & 3;
        int ld = (tile < 2) ? lda : ldb;
        const bf16* src = gp[tile] + (size_t)r * ld + k0 + c * 8;
        uint32_t so = sbase + tile * 8192 + sw_off(r, c);
        cp16(so, src);
    }
    asm volatile("cp.async.commit_group;" ::: "memory");
}

// ================= NT GEMM via mma.sync, 3-term bf16 split (round-8 proven mainloop) =================
// OUT_MODE 0: fp32 C (+bias[col]);
// OUT_MODE 1: bf16 hi/lo outputs (Chi/Clo);
// OUT_MODE 2: fused QK->augmented pack: z==0 writes (v*INV_SCALE) split into Chi/Clo (Qaug),
//             z==1 writes v split into C2hi/C2lo (Kaug); dest index h*(S*AUG)+row*AUG+(col&127).
template<int OUT_MODE>
__global__ void __launch_bounds__(256)
mma_gemm_nt(const bf16* __restrict__ Ahi, const bf16* __restrict__ Alo, int lda, size_t sAz,
            const bf16* __restrict__ Bhi, const bf16* __restrict__ Blo, int ldb, size_t sBz,
            float* __restrict__ C, bf16* __restrict__ Chi, bf16* __restrict__ Clo,
            bf16* __restrict__ C2hi, bf16* __restrict__ C2lo,
            int ldc, size_t sCz, int K, const float* __restrict__ bias)
{
    extern __shared__ char smem[];
    const uint32_t sb = smem_to_u32(smem);
    const int tid = threadIdx.x, lane = tid & 31, wid = tid >> 5;
    const int wm = wid & 1, wn = wid >> 1;           // 2 x 4 warp grid, warp tile 64x32
    const size_t z = blockIdx.z;
    const int bm = blockIdx.y * 128, bn = blockIdx.x * 128;

    const bf16* gA0 = Ahi + z * sAz + (size_t)bm * lda;
    const bf16* gA1 = Alo + z * sAz + (size_t)bm * lda;
    const bf16* gB0 = Bhi + z * sBz + (size_t)bn * ldb;
    const bf16* gB1 = Blo + z * sBz + (size_t)bn * ldb;

    float acc[4][4][4];
#pragma unroll
    for (int i = 0; i < 4; i++)
#pragma unroll
        for (int j = 0; j < 4; j++)
#pragma unroll
            for (int k = 0; k < 4; k++) acc[i][j][k] = 0.f;

    const int a_row_l = (lane & 7) + ((lane >> 3) & 1) * 8;
    const int a_chk_l = lane >> 4;
    const int b_row_l = (lane & 7) + ((lane >> 4) & 1) * 8;
    const int b_chk_l = (lane >> 3) & 1;

    const int nch = K >> 5;
    load_tiles(sb, tid, gA0, gA1, gB0, gB1, lda, ldb, 0);

    for (int c = 0; c < nch; c++) {
        if (c + 1 < nch) {
            load_tiles(sb + ((c + 1) & 1) * STAGE_BYTES, tid, gA0, gA1, gB0, gB1,
                       lda, ldb, (c + 1) * 32);
            asm volatile("cp.async.wait_group 1;" ::: "memory");
        } else {
            asm volatile("cp.async.wait_group 0;" ::: "memory");
        }
        __syncthreads();
        const uint32_t s0 = sb + (c & 1) * STAGE_BYTES;
#pragma unroll
        for (int ks = 0; ks < 2; ks++) {
            uint32_t a_hi[4][4], a_lo[4][4], b_hi[8], b_lo[8];
#pragma unroll
            for (int mt = 0; mt < 4; mt++) {
                int row = wm * 64 + mt * 16 + a_row_l;
                uint32_t off = sw_off(row, ks * 2 + a_chk_l);
                ldsm4(a_hi[mt], s0 + off);
                ldsm4(a_lo[mt], s0 + 8192 + off);
            }
#pragma unroll
            for (int ntp = 0; ntp < 2; ntp++) {
                int row = wn * 32 + ntp * 16 + b_row_l;
                uint32_t off = sw_off(row, ks * 2 + b_chk_l);
                ldsm4(&b_hi[ntp * 4], s0 + 16384 + off);
                ldsm4(&b_lo[ntp * 4], s0 + 24576 + off);
            }
#pragma unroll
            for (int mt = 0; mt < 4; mt++)
#pragma unroll
                for (int nt = 0; nt < 4; nt++) {
                    int bi = (nt >> 1) * 4 + (nt & 1) * 2;
                    mma_bf16(acc[mt][nt], a_hi[mt], b_hi[bi], b_hi[bi + 1]);
                    mma_bf16(acc[mt][nt], a_hi[mt], b_lo[bi], b_lo[bi + 1]);
                    mma_bf16(acc[mt][nt], a_lo[mt], b_hi[bi], b_hi[bi + 1]);
                }
        }
        __syncthreads();
    }

    // epilogue
    const int r_l = lane >> 2, c_l = (lane & 3) * 2;
#pragma unroll
    for (int mt = 0; mt < 4; mt++) {
#pragma unroll
        for (int nt = 0; nt < 4; nt++) {
            int row0 = bm + wm * 64 + mt * 16 + r_l;
            int col  = bn + wn * 32 + nt * 8 + c_l;
            float v0 = acc[mt][nt][0], v1 = acc[mt][nt][1];
            float v2 = acc[mt][nt][2], v3 = acc[mt][nt][3];
            if (OUT_MODE == 0) {
                if (bias) { v0 += bias[col]; v1 += bias[col + 1]; v2 += bias[col]; v3 += bias[col + 1]; }
                float* p0 = C + z * sCz + (size_t)row0 * ldc + col;
                float* p1 = C + z * sCz + (size_t)(row0 + 8) * ldc + col;
                p0[0] = v0; p0[1] = v1;
                p1[0] = v2; p1[1] = v3;
            } else if (OUT_MODE == 1) {
                bf16 h0 = __float2bfloat16(v0), h1 = __float2bfloat16(v1);
                bf16 h2 = __float2bfloat16(v2), h3 = __float2bfloat16(v3);
                bf16 l0 = __float2bfloat16(v0 - __bfloat162float(h0));
                bf16 l1 = __float2bfloat16(v1 - __bfloat162float(h1));
                bf16 l2 = __float2bfloat16(v2 - __bfloat162float(h2));
                bf16 l3 = __float2bfloat16(v3 - __bfloat162float(h3));
                bf16* hp0 = Chi + z * sCz + (size_t)row0 * ldc + col;
                bf16* hp1 = Chi + z * sCz + (size_t)(row0 + 8) * ldc + col;
                bf16* lp0 = Clo + z * sCz + (size_t)row0 * ldc + col;
                bf16* lp1 = Clo + z * sCz + (size_t)(row0 + 8) * ldc + col;
                hp0[0] = h0; hp0[1] = h1; hp1[0] = h2; hp1[1] = h3;
                lp0[0] = l0; lp0[1] = l1; lp1[0] = l2; lp1[1] = l3;
            } else {
                // fused QK -> augmented pack
                bf16* hp = (z == 0) ? Chi : C2hi;
                bf16* lp = (z == 0) ? Clo : C2lo;
                const float sc = (z == 0) ? INV_SCALE : 1.0f;
                v0 *= sc; v1 *= sc; v2 *= sc; v3 *= sc;
                const int h = col >> 7, d = col & 127;
                size_t base0 = (size_t)h * (S_*AUG) + (size_t)row0 * AUG + d;
                size_t base1 = (size_t)h * (S_*AUG) + (size_t)(row0 + 8) * AUG + d;
                bf16 h0 = __float2bfloat16(v0), h1 = __float2bfloat16(v1);
                bf16 h2 = __float2bfloat16(v2), h3 = __float2bfloat16(v3);
                hp[base0]     = h0; hp[base0 + 1] = h1;
                hp[base1]     = h2; hp[base1 + 1] = h3;
                lp[base0]     = __float2bfloat16(v0 - __bfloat162float(h0));
                lp[base0 + 1] = __float2bfloat16(v1 - __bfloat162float(h1));
                lp[base1]     = __float2bfloat16(v2 - __bfloat162float(h2));
                lp[base1 + 1] = __float2bfloat16(v3 - __bfloat162float(h3));
            }
        }
    }
}

// ================= small kernels =================
__global__ void split5_kernel(
    const float* __restrict__ s0, const float* __restrict__ s1, const float* __restrict__ s2,
    const float* __restrict__ s3, const float* __restrict__ s4,
    bf16* __restrict__ h0, bf16* __restrict__ h1, bf16* __restrict__ h2,
    bf16* __restrict__ h3, bf16* __restrict__ h4,
    bf16* __restrict__ l0, bf16* __restrict__ l1, bf16* __restrict__ l2,
    bf16* __restrict__ l3, bf16* __restrict__ l4)
{
    int i4 = blockIdx.x * blockDim.x + threadIdx.x;
    int zz = blockIdx.y;
    const float* src = (zz == 0) ? s0 : (zz == 1) ? s1 : (zz == 2) ? s2 : (zz == 3) ? s3 : s4;
    bf16* hi = (zz == 0) ? h0 : (zz == 1) ? h1 : (zz == 2) ? h2 : (zz == 3) ? h3 : h4;
    bf16* lo = (zz == 0) ? l0 : (zz == 1) ? l1 : (zz == 2) ? l2 : (zz == 3) ? l3 : l4;
    float4 v = *((const float4*)src + i4);
    bf16 a = __float2bfloat16(v.x), b = __float2bfloat16(v.y);
    bf16 c = __float2bfloat16(v.z), d = __float2bfloat16(v.w);
    uint2 hv, lv;
    hv.x = (uint32_t)__bfloat16_as_ushort(a) | ((uint32_t)__bfloat16_as_ushort(b) << 16);
    hv.y = (uint32_t)__bfloat16_as_ushort(c) | ((uint32_t)__bfloat16_as_ushort(d) << 16);
    lv.x = pack_bf16x2(v.x - __bfloat162float(a), v.y - __bfloat162float(b));
    lv.y = pack_bf16x2(v.z - __bfloat162float(c), v.w - __bfloat162float(d));
    *((uint2*)hi + i4) = hv;
    *((uint2*)lo + i4) = lv;
}

__global__ void fiber_gemm(const float* __restrict__ x, const float* __restrict__ fw,
                           float* __restrict__ fpart)
{
    __shared__ float Xs[64][68];
    __shared__ float Fs[64][68];
    const int ksplit = blockIdx.x;
    const int rb = blockIdx.y * 64;
    const int t = threadIdx.x;
    const int rt = t & 15, ct = t >> 4;
    float acc[4][4] = {};
    for (int sub = 0; sub < 2; sub++) {
        const int k0 = ksplit * 128 + sub * 64;
        __syncthreads();
        for (int i = t; i < 1024; i += 256) {
            int row = i >> 4, kq = (i & 15) * 4;
            float4 v = *(const float4*)&x[(size_t)(rb + row) * DM + k0 + kq];
            Xs[kq][row] = v.x; Xs[kq+1][row] = v.y; Xs[kq+2][row] = v.z; Xs[kq+3][row] = v.w;
            float4 w = *(const float4*)&fw[(size_t)row * DM + k0 + kq];
            Fs[kq][row] = w.x; Fs[kq+1][row] = w.y; Fs[kq+2][row] = w.z; Fs[kq+3][row] = w.w;
        }
        __syncthreads();
#pragma unroll 16
        for (int k = 0; k < 64; k++) {
            float a[4], b[4];
#pragma unroll
            for (int i = 0; i < 4; i++) a[i] = Xs[k][rt*4 + i];
#pragma unroll
            for (int j = 0; j < 4; j++) b[j] = Fs[k][ct*4 + j];
#pragma unroll
            for (int i = 0; i < 4; i++)
#pragma unroll
                for (int j = 0; j < 4; j++) acc[i][j] = fmaf(a[i], b[j], acc[i][j]);
        }
    }
    float* dst = fpart + (size_t)ksplit * S_ * F_;
#pragma unroll
    for (int i = 0; i < 4; i++)
#pragma unroll
        for (int j = 0; j < 4; j++)
            dst[(size_t)(rb + rt*4 + i) * F_ + ct*4 + j] = acc[i][j];
}

__global__ void fiber_reduce(const float* __restrict__ fpart, const float* __restrict__ fb,
                             float* __restrict__ fp)
{
    int i = blockIdx.x * blockDim.x + threadIdx.x;
    if (i >= S_ * F_) return;
    float a = fb[i & 63];
#pragma unroll
    for (int s = 0; s < 16; s++) a += fpart[(size_t)s * S_ * F_ + i];
    fp[i] = a;
}

__global__ void fp_stats_kernel(const float* __restrict__ fp,
                                float* __restrict__ fpsum, float* __restrict__ mi)
{
    __shared__ float sm[256];
    int t = threadIdx.x;
    int f = t & 63, c = t >> 6;
    float s = 0.f;
    for (int i = c; i < S_; i += 4) s += fp[i*F_ + f];
    sm[t] = s; __syncthreads();
    if (c == 0) {
        float tot = sm[f] + sm[64+f] + sm[128+f] + sm[192+f];
        fpsum[f] = tot;
        mi[f] = tot / (float)S_;
    }
}

__global__ void mlp_metric_kernel(const float* __restrict__ mi,
                                  const float* __restrict__ fm1w, const float* __restrict__ fm1b,
                                  const float* __restrict__ fm2w, const float* __restrict__ fm2b,
                                  float* __restrict__ metric)
{
    __shared__ float smi[F_];
    __shared__ float hid[F_/2];
    __shared__ float raw[F_];
    int t = threadIdx.x;
    smi[t] = mi[t];
    __syncthreads();
    if (t < F_/2) {
        float a = fm1b[t];
        for (int f = 0; f < F_; f++) a = fmaf(smi[f], fm1w[t*F_ + f], a);
        hid[t] = fmaxf(a, 0.f);
    }
    __syncthreads();
    {
        float a = fm2b[t];
        for (int j = 0; j < F_/2; j++) a = fmaf(hid[j], fm2w[t*(F_/2) + j], a);
        raw[t] = a;
    }
    __syncthreads();
    for (int b = 0; b < F_; b++)
        metric[t*F_ + b] = raw[t]*raw[b] + ((t == b) ? 0.1f : 0.f);
}

__global__ void compute_g_kernel(const float* __restrict__ fp,
                                 const float* __restrict__ metric,
                                 float* __restrict__ g)
{
    __shared__ float sm[F_*F_];
    for (int i = threadIdx.x; i < F_*F_; i += blockDim.x) sm[i] = metric[i];
    __syncthreads();
    int t = threadIdx.x;
    int f = t & 63, r = t >> 6;
    int i = blockIdx.x*4 + r;
    const float* fr = fp + (size_t)i*F_;
    float a = 0.f;
#pragma unroll
    for (int k = 0; k < F_; k++) a = fmaf(fr[k], sm[k*F_ + f], a);
    g[(size_t)i*F_ + f] = a;
}

__global__ void curv_kernel(const float* __restrict__ fp, const float* __restrict__ cm,
                            float* __restrict__ curv, float* __restrict__ curvb)
{
    int j = blockIdx.x*blockDim.x + threadIdx.x;
    if (j >= S_) return;
    float a = 0.f;
#pragma unroll
    for (int f = 0; f < F_; f++) a = fmaf(fp[(size_t)j*F_ + f], cm[f*(F_+1)], a);
    curv[j] = a;
    curvb[j] = COUPLING * a;
}

// fiber columns only (d in [128,192)) of the augmented Q/K
__global__ void pack_fiber_kernel(const float* __restrict__ g, const float* __restrict__ fp,
                                  bf16* __restrict__ Qhi, bf16* __restrict__ Qlo,
                                  bf16* __restrict__ Khi, bf16* __restrict__ Klo)
{
    int idx = blockIdx.x*blockDim.x + threadIdx.x;   // over H*S*F
    if (idx >= H_*S_*F_) return;
    int f = idx & 63;
    int i = (idx >> 6) & (S_ - 1);
    int h = idx >> 17;                               // /(S_*F_) = /131072
    float qv = COUPLING * g[(size_t)i*F_ + f];
    float kv = fp[(size_t)i*F_ + f];
    size_t o = (size_t)h * (S_*AUG) + (size_t)i * AUG + DK + f;
    bf16 qh = __float2bfloat16(qv);
    Qhi[o] = qh;
    Qlo[o] = __float2bfloat16(qv - __bfloat162float(qh));
    bf16 kh = __float2bfloat16(kv);
    Khi[o] = kh;
    Klo[o] = __float2bfloat16(kv - __bfloat162float(kh));
}

__global__ void softmax_kernel(const float* __restrict__ P,
                               bf16* __restrict__ Phi, bf16* __restrict__ Plo)
{
    size_t row = blockIdx.x;
    const float* p = P + row * (size_t)S_;
    int t = threadIdx.x;
    float vals[8];
    float4 v0 = *(const float4*)(p + t*8);
    float4 v1 = *(const float4*)(p + t*8 + 4);
    vals[0]=v0.x; vals[1]=v0.y; vals[2]=v0.z; vals[3]=v0.w;
    vals[4]=v1.x; vals[5]=v1.y; vals[6]=v1.z; vals[7]=v1.w;
    float m = vals[0];
#pragma unroll
    for (int i = 1; i < 8; i++) m = fmaxf(m, vals[i]);
    __shared__ float red[8];
    for (int o = 16; o; o >>= 1) m = fmaxf(m, __shfl_xor_sync(~0u, m, o));
    if ((t & 31) == 0) red[t>>5] = m;
    __syncthreads();
    m = red[0];
#pragma unroll
    for (int i = 1; i < 8; i++) m = fmaxf(m, red[i]);
    float s = 0.f;
#pragma unroll
    for (int i = 0; i < 8; i++) { vals[i] = __expf(vals[i] - m); s += vals[i]; }
    for (int o = 16; o; o >>= 1) s += __shfl_xor_sync(~0u, s, o);
    __shared__ float red2[8];
    if ((t & 31) == 0) red2[t>>5] = s;
    __syncthreads();
    s = red2[0];
#pragma unroll
    for (int i = 1; i < 8; i++) s += red2[i];
    float inv = 1.0f / s;
    uint4 hv, lv;
    float w0 = vals[0]*inv, w1 = vals[1]*inv, w2 = vals[2]*inv, w3 = vals[3]*inv;
    float w4 = vals[4]*inv, w5 = vals[5]*inv, w6 = vals[6]*inv, w7 = vals[7]*inv;
    bf16 h0=__float2bfloat16(w0), h1=__float2bfloat16(w1), h2=__float2bfloat16(w2), h3=__float2bfloat16(w3);
    bf16 h4=__float2bfloat16(w4), h5=__float2bfloat16(w5), h6=__float2bfloat16(w6), h7=__float2bfloat16(w7);
    hv.x = (uint32_t)__bfloat16_as_ushort(h0) | ((uint32_t)__bfloat16_as_ushort(h1) << 16);
    hv.y = (uint32_t)__bfloat16_as_ushort(h2) | ((uint32_t)__bfloat16_as_ushort(h3) << 16);
    hv.z = (uint32_t)__bfloat16_as_ushort(h4) | ((uint32_t)__bfloat16_as_ushort(h5) << 16);
    hv.w = (uint32_t)__bfloat16_as_ushort(h6) | ((uint32_t)__bfloat16_as_ushort(h7) << 16);
    lv.x = pack_bf16x2(w0 - __bfloat162float(h0), w1 - __bfloat162float(h1));
    lv.y = pack_bf16x2(w2 - __bfloat162float(h2), w3 - __bfloat162float(h3));
    lv.z = pack_bf16x2(w4 - __bfloat162float(h4), w5 - __bfloat162float(h5));
    lv.w = pack_bf16x2(w6 - __bfloat162float(h6), w7 - __bfloat162float(h7));
    *(uint4*)(Phi + row * (size_t)S_ + t*8) = hv;
    *(uint4*)(Plo + row * (size_t)S_ + t*8) = lv;
}

__global__ void scalar_kernel(const float* __restrict__ g, const float* __restrict__ fpsum,
                              const float* __restrict__ curv, float* __restrict__ out0,
                              float* __restrict__ out1)
{
    __shared__ float sm[256];
    __shared__ float sc[256];
    int t = threadIdx.x;
    int f = t & 63, c = t >> 6;
    float s = 0.f;
    for (int i = c; i < S_; i += 4) s += g[i*F_ + f];
    sm[t] = s; __syncthreads();
    float tot = 0.f;
    if (c == 0) tot = sm[f] + sm[64+f] + sm[128+f] + sm[192+f];
    __syncthreads();
    sm[t] = (c == 0) ? tot * fpsum[f] : 0.f;
    float cs = 0.f;
    for (int j = t; j < S_; j += 256) cs += curv[j];
    sc[t] = cs;
    __syncthreads();
    if (t == 0) {
        float a = 0.f, b = 0.f;
        for (int i = 0; i < 64; i++) a += sm[i];
        for (int i = 0; i < 256; i++) b += sc[i];
        float val = a / ((float)S_ * (float)S_) + b / (float)S_;
        *out0 = val;
        if (out1) *out1 = val;
    }
}

// ================= launch =================
extern "C" void kernel_launch(void* const* d_in, const int* in_sizes, int n_in,
                              void* d_out, int out_size)
{
    const float* x    = (const float*)d_in[0];
    const float* wq   = (const float*)d_in[2];
    const float* wk   = (const float*)d_in[3];
    const float* wv   = (const float*)d_in[4];
    const float* wo_w = (const float*)d_in[5];
    const float* wo_b = (const float*)d_in[6];
    const float* fw   = (const float*)d_in[7];
    const float* fb   = (const float*)d_in[8];
    const float* fm1w = (const float*)d_in[9];
    const float* fm1b = (const float*)d_in[10];
    const float* fm2w = (const float*)d_in[11];
    const float* fm2b = (const float*)d_in[12];
    const float* cm   = (const float*)d_in[13];
    float* out = (float*)d_out;

    bf16 *xhi,*xlo,*wqkhi,*wqklo,*wvhi,*wvlo,*wohi,*wolo;
    bf16 *Vthi,*Vtlo,*Qahi,*Qalo,*Kahi,*Kalo,*Phi,*Plo,*athi,*atlo;
    float *fp,*fpart,*g,*metric,*mi,*fpsum,*curv,*curvb,*scores;
    cudaGetSymbolAddress((void**)&xhi, d_xhi);     cudaGetSymbolAddress((void**)&xlo, d_xlo);
    cudaGetSymbolAddress((void**)&wqkhi, d_wqkhi); cudaGetSymbolAddress((void**)&wqklo, d_wqklo);
    cudaGetSymbolAddress((void**)&wvhi, d_wvhi);   cudaGetSymbolAddress((void**)&wvlo, d_wvlo);
    cudaGetSymbolAddress((void**)&wohi, d_wohi);   cudaGetSymbolAddress((void**)&wolo, d_wolo);
    cudaGetSymbolAddress((void**)&Vthi, d_Vthi);   cudaGetSymbolAddress((void**)&Vtlo, d_Vtlo);
    cudaGetSymbolAddress((void**)&Qahi, d_Qahi);   cudaGetSymbolAddress((void**)&Qalo, d_Qalo);
    cudaGetSymbolAddress((void**)&Kahi, d_Kahi);   cudaGetSymbolAddress((void**)&Kalo, d_Kalo);
    cudaGetSymbolAddress((void**)&Phi, d_Phi);     cudaGetSymbolAddress((void**)&Plo, d_Plo);
    cudaGetSymbolAddress((void**)&athi, d_attnhi); cudaGetSymbolAddress((void**)&atlo, d_attnlo);
    cudaGetSymbolAddress((void**)&fp, d_fp);       cudaGetSymbolAddress((void**)&fpart, d_fpart);
    cudaGetSymbolAddress((void**)&g, d_g);
    cudaGetSymbolAddress((void**)&metric, d_metric); cudaGetSymbolAddress((void**)&mi, d_mi);
    cudaGetSymbolAddress((void**)&fpsum, d_fpsum);   cudaGetSymbolAddress((void**)&curv, d_curv);
    cudaGetSymbolAddress((void**)&curvb, d_curvb);   cudaGetSymbolAddress((void**)&scores, d_scores);

    cudaFuncSetAttribute(mma_gemm_nt<0>, cudaFuncAttributeMaxDynamicSharedMemorySize, MMA_SMEM);
    cudaFuncSetAttribute(mma_gemm_nt<1>, cudaFuncAttributeMaxDynamicSharedMemorySize, MMA_SMEM);
    cudaFuncSetAttribute(mma_gemm_nt<2>, cudaFuncAttributeMaxDynamicSharedMemorySize, MMA_SMEM);

    const int NDM = S_*DM;
    // 0) all 5 bf16 hi/lo splits, vectorized x4, one launch
    split5_kernel<<<dim3(NDM/1024, 5), 256>>>(
        x, wq, wk, wv, wo_w,
        xhi, wqkhi, wqkhi + (size_t)DM*DM, wvhi, wohi,
        xlo, wqklo, wqklo + (size_t)DM*DM, wvlo, wolo);

    // 1) Q and K projections batched (z=2) with FUSED augmented pack (OUT_MODE 2)
    mma_gemm_nt<2><<<dim3(16,16,2), 256, MMA_SMEM>>>(
        xhi, xlo, DM, 0, wqkhi, wqklo, DM, (size_t)DM*DM,
        nullptr, Qahi, Qalo, Kahi, Kalo, 0, 0, DM, nullptr);
    // 2) Vt[d][s] = wv @ x^T (bf16 hi/lo out)
    mma_gemm_nt<1><<<dim3(16,16,1), 256, MMA_SMEM>>>(wvhi, wvlo, DM, 0, xhi, xlo, DM, 0,
                                                     nullptr, Vthi, Vtlo, nullptr, nullptr,
                                                     S_, 0, DM, nullptr);
    // 3) fiber projection (deterministic split-K)
    fiber_gemm<<<dim3(16, 32), 256>>>(x, fw, fpart);
    fiber_reduce<<<S_*F_/256, 256>>>(fpart, fb, fp);
    // 4) stats -> MLP -> metric -> g -> curv
    fp_stats_kernel<<<1, 256>>>(fp, fpsum, mi);
    mlp_metric_kernel<<<1, 64>>>(mi, fm1w, fm1b, fm2w, fm2b, metric);
    compute_g_kernel<<<S_/4, 256>>>(fp, metric, g);
    curv_kernel<<<S_/256, 256>>>(fp, cm, curv, curvb);
    // 5) pack fiber columns of augmented Q/K
    pack_fiber_kernel<<<(H_*S_*F_)/256, 256>>>(g, fp, Qahi, Qalo, Kahi, Kalo);
    // 6) scores = Qaug @ Kaug^T + 0.1*curv[col] (K=192, batched heads)
    mma_gemm_nt<0><<<dim3(16,16,H_), 256, MMA_SMEM>>>(
        Qahi, Qalo, AUG, (size_t)S_*AUG, Kahi, Kalo, AUG, (size_t)S_*AUG,
        scores, nullptr, nullptr, nullptr, nullptr, S_, (size_t)S_*S_, AUG, curvb);
    // 7) softmax -> P hi/lo (vectorized stores)
    softmax_kernel<<<H_*S_, 256>>>(scores, Phi, Plo);
    // 8) attn[q, h*128+d] = P[h] @ Vt[h]^T (bf16 hi/lo out)
    mma_gemm_nt<1><<<dim3(1,16,H_), 256, MMA_SMEM>>>(
        Phi, Plo, S_, (size_t)S_*S_, Vthi, Vtlo, S_, (size_t)DK*S_,
        nullptr, athi, atlo, nullptr, nullptr, DM, (size_t)DK, S_, nullptr);
    // 9) out = attn @ wo^T + wo_b (fp32 -> d_out)
    mma_gemm_nt<0><<<dim3(16,16,1), 256, MMA_SMEM>>>(athi, atlo, DM, 0, wohi, wolo, DM, 0,
                                                     out, nullptr, nullptr, nullptr, nullptr,
                                                     DM, 0, DM, wo_b);
    // 10) ci.mean() scalar
    if (out_size > S_*DM) {
        float* o0 = out + (size_t)S_*DM;
        float* o1 = out + (size_t)(out_size - 1);
        scalar_kernel<<<1, 256>>>(g, fpsum, curv, o0, (o1 != o0) ? o1 : nullptr);
    }
}

// round 12
// speedup vs baseline: 1.0647x; 1.0202x over previous
#include <cuda_runtime.h>
#include <cuda_bf16.h>
#include <cstdint>
#include <math.h>

#define S_  2048
#define DM  2048
#define H_  16
#define DK  128
#define F_  64
#define AUG 192
#define INV_SCALE (1.0f/11.313708498984761f)
#define COUPLING 0.1f

typedef __nv_bfloat16 bf16;

// ---------------- device scratch (256B-aligned) ----------------
__device__ __align__(256) bf16  d_xhi[S_*DM],  d_xlo[S_*DM];
__device__ __align__(256) bf16  d_wqkhi[2*DM*DM], d_wqklo[2*DM*DM];   // wq then wk
__device__ __align__(256) bf16  d_wvhi[DM*DM], d_wvlo[DM*DM];
__device__ __align__(256) bf16  d_wohi[DM*DM], d_wolo[DM*DM];
__device__ __align__(256) float d_QK[2*S_*DM];                        // Q then K (fp32)
__device__ __align__(256) bf16  d_Vthi[DM*S_], d_Vtlo[DM*S_];         // V transposed [d][s]
__device__ __align__(256) float d_fp[S_*F_];
__device__ __align__(256) float d_fpart[16*S_*F_];
__device__ __align__(256) float d_g[S_*F_];
__device__ __align__(256) float d_metric[F_*F_];
__device__ __align__(256) float d_mi[F_];
__device__ __align__(256) float d_fpsum[F_];
__device__ __align__(256) float d_curv[S_];
__device__ __align__(256) float d_curvb[S_];
__device__ __align__(256) bf16  d_Qahi[H_*S_*AUG], d_Qalo[H_*S_*AUG];
__device__ __align__(256) bf16  d_Kahi[H_*S_*AUG], d_Kalo[H_*S_*AUG];
__device__ __align__(256) float d_scores[H_*S_*S_];
__device__ __align__(256) bf16  d_Phi[H_*S_*S_], d_Plo[H_*S_*S_];
__device__ __align__(256) bf16  d_attnhi[S_*DM], d_attnlo[S_*DM];

// ================= portable-ISA helpers =================
__device__ __forceinline__ uint32_t smem_to_u32(const void* p) {
    uint32_t a;
    asm("{ .reg .u64 t; cvta.to.shared.u64 t, %1; cvt.u32.u64 %0, t; }" : "=r"(a) : "l"(p));
    return a;
}
__device__ __forceinline__ void cp16(uint32_t saddr, const void* g) {
    asm volatile("cp.async.cg.shared.global [%0], [%1], 16;" :: "r"(saddr), "l"(g));
}
__device__ __forceinline__ void ldsm4(uint32_t* r, uint32_t a) {
    asm volatile("ldmatrix.sync.aligned.m8n8.x4.shared.b16 {%0,%1,%2,%3}, [%4];"
                 : "=r"(r[0]), "=r"(r[1]), "=r"(r[2]), "=r"(r[3]) : "r"(a));
}
__device__ __forceinline__ void mma_bf16(float* c, const uint32_t* a, uint32_t b0, uint32_t b1) {
    asm volatile("mma.sync.aligned.m16n8k16.row.col.f32.bf16.bf16.f32 "
                 "{%0,%1,%2,%3}, {%4,%5,%6,%7}, {%8,%9}, {%0,%1,%2,%3};"
                 : "+f"(c[0]), "+f"(c[1]), "+f"(c[2]), "+f"(c[3])
                 : "r"(a[0]), "r"(a[1]), "r"(a[2]), "r"(a[3]), "r"(b0), "r"(b1));
}
__device__ __forceinline__ uint32_t pack_bf16x2(float lo, float hi) {
    uint32_t r;
    unsigned short l = __bfloat16_as_ushort(__float2bfloat16(lo));
    unsigned short h = __bfloat16_as_ushort(__float2bfloat16(hi));
    r = (uint32_t)l | ((uint32_t)h << 16);
    return r;
}

// smem stage: Ahi | Alo | Bhi | Blo, each 128 rows x 32 bf16 (64B rows), XOR swizzled
#define STAGE_BYTES 32768
#define MMA_SMEM (2*STAGE_BYTES)

__device__ __forceinline__ uint32_t sw_off(int row, int chunk) {
    return (uint32_t)(row * 64 + ((chunk ^ ((row >> 1) & 3)) << 4));
}

__device__ __forceinline__ void load_tiles(uint32_t sbase, int tid,
    const bf16* g0, const bf16* g1, const bf16* g2, const bf16* g3,
    int lda, int ldb, int k0)
{
    const bf16* gp[4] = {g0, g1, g2, g3};
#pragma unroll
    for (int i = 0; i < 8; i++) {
        int q = tid + i * 256;
        int tile = q >> 9, r = (q >> 2) & 127, c = q & 3;
        int ld = (tile < 2) ? lda : ldb;
        const bf16* src = gp[tile] + (size_t)r * ld + k0 + c * 8;
        uint32_t so = sbase + tile * 8192 + sw_off(r, c);
        cp16(so, src);
    }
    asm volatile("cp.async.commit_group;" ::: "memory");
}

// ================= NT GEMM via mma.sync, 3-term bf16 split (round-8 proven) =================
template<int OUT_MODE>
__global__ void __launch_bounds__(256)
mma_gemm_nt(const bf16* __restrict__ Ahi, const bf16* __restrict__ Alo, int lda, size_t sAz,
            const bf16* __restrict__ Bhi, const bf16* __restrict__ Blo, int ldb, size_t sBz,
            float* __restrict__ C, bf16* __restrict__ Chi, bf16* __restrict__ Clo,
            int ldc, size_t sCz, int K, const float* __restrict__ bias)
{
    extern __shared__ char smem[];
    const uint32_t sb = smem_to_u32(smem);
    const int tid = threadIdx.x, lane = tid & 31, wid = tid >> 5;
    const int wm = wid & 1, wn = wid >> 1;           // 2 x 4 warp grid, warp tile 64x32
    const size_t z = blockIdx.z;
    const int bm = blockIdx.y * 128, bn = blockIdx.x * 128;

    const bf16* gA0 = Ahi + z * sAz + (size_t)bm * lda;
    const bf16* gA1 = Alo + z * sAz + (size_t)bm * lda;
    const bf16* gB0 = Bhi + z * sBz + (size_t)bn * ldb;
    const bf16* gB1 = Blo + z * sBz + (size_t)bn * ldb;

    float acc[4][4][4];
#pragma unroll
    for (int i = 0; i < 4; i++)
#pragma unroll
        for (int j = 0; j < 4; j++)
#pragma unroll
            for (int k = 0; k < 4; k++) acc[i][j][k] = 0.f;

    const int a_row_l = (lane & 7) + ((lane >> 3) & 1) * 8;
    const int a_chk_l = lane >> 4;
    const int b_row_l = (lane & 7) + ((lane >> 4) & 1) * 8;
    const int b_chk_l = (lane >> 3) & 1;

    const int nch = K >> 5;
    load_tiles(sb, tid, gA0, gA1, gB0, gB1, lda, ldb, 0);

    for (int c = 0; c < nch; c++) {
        if (c + 1 < nch) {
            load_tiles(sb + ((c + 1) & 1) * STAGE_BYTES, tid, gA0, gA1, gB0, gB1,
                       lda, ldb, (c + 1) * 32);
            asm volatile("cp.async.wait_group 1;" ::: "memory");
        } else {
            asm volatile("cp.async.wait_group 0;" ::: "memory");
        }
        __syncthreads();
        const uint32_t s0 = sb + (c & 1) * STAGE_BYTES;
#pragma unroll
        for (int ks = 0; ks < 2; ks++) {
            uint32_t a_hi[4][4], a_lo[4][4], b_hi[8], b_lo[8];
#pragma unroll
            for (int mt = 0; mt < 4; mt++) {
                int row = wm * 64 + mt * 16 + a_row_l;
                uint32_t off = sw_off(row, ks * 2 + a_chk_l);
                ldsm4(a_hi[mt], s0 + off);
                ldsm4(a_lo[mt], s0 + 8192 + off);
            }
#pragma unroll
            for (int ntp = 0; ntp < 2; ntp++) {
                int row = wn * 32 + ntp * 16 + b_row_l;
                uint32_t off = sw_off(row, ks * 2 + b_chk_l);
                ldsm4(&b_hi[ntp * 4], s0 + 16384 + off);
                ldsm4(&b_lo[ntp * 4], s0 + 24576 + off);
            }
#pragma unroll
            for (int mt = 0; mt < 4; mt++)
#pragma unroll
                for (int nt = 0; nt < 4; nt++) {
                    int bi = (nt >> 1) * 4 + (nt & 1) * 2;
                    mma_bf16(acc[mt][nt], a_hi[mt], b_hi[bi], b_hi[bi + 1]);
                    mma_bf16(acc[mt][nt], a_hi[mt], b_lo[bi], b_lo[bi + 1]);
                    mma_bf16(acc[mt][nt], a_lo[mt], b_hi[bi], b_hi[bi + 1]);
                }
        }
        __syncthreads();
    }

    // epilogue
    const int r_l = lane >> 2, c_l = (lane & 3) * 2;
#pragma unroll
    for (int mt = 0; mt < 4; mt++) {
#pragma unroll
        for (int nt = 0; nt < 4; nt++) {
            int row0 = bm + wm * 64 + mt * 16 + r_l;
            int col  = bn + wn * 32 + nt * 8 + c_l;
            float v0 = acc[mt][nt][0], v1 = acc[mt][nt][1];
            float v2 = acc[mt][nt][2], v3 = acc[mt][nt][3];
            if (OUT_MODE == 0) {
                if (bias) { v0 += bias[col]; v1 += bias[col + 1]; v2 += bias[col]; v3 += bias[col + 1]; }
                float* p0 = C + z * sCz + (size_t)row0 * ldc + col;
                float* p1 = C + z * sCz + (size_t)(row0 + 8) * ldc + col;
                p0[0] = v0; p0[1] = v1;
                p1[0] = v2; p1[1] = v3;
            } else {
                bf16 h0 = __float2bfloat16(v0), h1 = __float2bfloat16(v1);
                bf16 h2 = __float2bfloat16(v2), h3 = __float2bfloat16(v3);
                bf16 l0 = __float2bfloat16(v0 - __bfloat162float(h0));
                bf16 l1 = __float2bfloat16(v1 - __bfloat162float(h1));
                bf16 l2 = __float2bfloat16(v2 - __bfloat162float(h2));
                bf16 l3 = __float2bfloat16(v3 - __bfloat162float(h3));
                bf16* hp0 = Chi + z * sCz + (size_t)row0 * ldc + col;
                bf16* hp1 = Chi + z * sCz + (size_t)(row0 + 8) * ldc + col;
                bf16* lp0 = Clo + z * sCz + (size_t)row0 * ldc + col;
                bf16* lp1 = Clo + z * sCz + (size_t)(row0 + 8) * ldc + col;
                hp0[0] = h0; hp0[1] = h1; hp1[0] = h2; hp1[1] = h3;
                lp0[0] = l0; lp0[1] = l1; lp1[0] = l2; lp1[1] = l3;
            }
        }
    }
}

// ================= small kernels =================
__global__ void split5_kernel(
    const float* __restrict__ s0, const float* __restrict__ s1, const float* __restrict__ s2,
    const float* __restrict__ s3, const float* __restrict__ s4,
    bf16* __restrict__ h0, bf16* __restrict__ h1, bf16* __restrict__ h2,
    bf16* __restrict__ h3, bf16* __restrict__ h4,
    bf16* __restrict__ l0, bf16* __restrict__ l1, bf16* __restrict__ l2,
    bf16* __restrict__ l3, bf16* __restrict__ l4)
{
    int i4 = blockIdx.x * blockDim.x + threadIdx.x;   // index of float4
    int zz = blockIdx.y;
    const float* src = (zz == 0) ? s0 : (zz == 1) ? s1 : (zz == 2) ? s2 : (zz == 3) ? s3 : s4;
    bf16* hi = (zz == 0) ? h0 : (zz == 1) ? h1 : (zz == 2) ? h2 : (zz == 3) ? h3 : h4;
    bf16* lo = (zz == 0) ? l0 : (zz == 1) ? l1 : (zz == 2) ? l2 : (zz == 3) ? l3 : l4;
    float4 v = *((const float4*)src + i4);
    bf16 a = __float2bfloat16(v.x), b = __float2bfloat16(v.y);
    bf16 c = __float2bfloat16(v.z), d = __float2bfloat16(v.w);
    uint2 hv, lv;
    hv.x = (uint32_t)__bfloat16_as_ushort(a) | ((uint32_t)__bfloat16_as_ushort(b) << 16);
    hv.y = (uint32_t)__bfloat16_as_ushort(c) | ((uint32_t)__bfloat16_as_ushort(d) << 16);
    lv.x = pack_bf16x2(v.x - __bfloat162float(a), v.y - __bfloat162float(b));
    lv.y = pack_bf16x2(v.z - __bfloat162float(c), v.w - __bfloat162float(d));
    *((uint2*)hi + i4) = hv;
    *((uint2*)lo + i4) = lv;
}

// deterministic split-K fiber projection: 16 K-splits of 128
__global__ void fiber_gemm(const float* __restrict__ x, const float* __restrict__ fw,
                           float* __restrict__ fpart)
{
    __shared__ float Xs[64][68];
    __shared__ float Fs[64][68];
    const int ksplit = blockIdx.x;           // 0..15
    const int rb = blockIdx.y * 64;          // row block
    const int t = threadIdx.x;
    const int rt = t & 15, ct = t >> 4;
    float acc[4][4] = {};
    for (int sub = 0; sub < 2; sub++) {
        const int k0 = ksplit * 128 + sub * 64;
        __syncthreads();
        for (int i = t; i < 1024; i += 256) {
            int row = i >> 4, kq = (i & 15) * 4;
            float4 v = *(const float4*)&x[(size_t)(rb + row) * DM + k0 + kq];
            Xs[kq][row] = v.x; Xs[kq+1][row] = v.y; Xs[kq+2][row] = v.z; Xs[kq+3][row] = v.w;
            float4 w = *(const float4*)&fw[(size_t)row * DM + k0 + kq];
            Fs[kq][row] = w.x; Fs[kq+1][row] = w.y; Fs[kq+2][row] = w.z; Fs[kq+3][row] = w.w;
        }
        __syncthreads();
#pragma unroll 16
        for (int k = 0; k < 64; k++) {
            float a[4], b[4];
#pragma unroll
            for (int i = 0; i < 4; i++) a[i] = Xs[k][rt*4 + i];
#pragma unroll
            for (int j = 0; j < 4; j++) b[j] = Fs[k][ct*4 + j];
#pragma unroll
            for (int i = 0; i < 4; i++)
#pragma unroll
                for (int j = 0; j < 4; j++) acc[i][j] = fmaf(a[i], b[j], acc[i][j]);
        }
    }
    float* dst = fpart + (size_t)ksplit * S_ * F_;
#pragma unroll
    for (int i = 0; i < 4; i++)
#pragma unroll
        for (int j = 0; j < 4; j++)
            dst[(size_t)(rb + rt*4 + i) * F_ + ct*4 + j] = acc[i][j];
}

__global__ void fiber_reduce(const float* __restrict__ fpart, const float* __restrict__ fb,
                             float* __restrict__ fp)
{
    int i = blockIdx.x * blockDim.x + threadIdx.x;
    if (i >= S_ * F_) return;
    float a = fb[i & 63];
#pragma unroll
    for (int s = 0; s < 16; s++) a += fpart[(size_t)s * S_ * F_ + i];
    fp[i] = a;
}

__global__ void fp_stats_kernel(const float* __restrict__ fp,
                                float* __restrict__ fpsum, float* __restrict__ mi)
{
    __shared__ float sm[256];
    int t = threadIdx.x;
    int f = t & 63, c = t >> 6;
    float s = 0.f;
    for (int i = c; i < S_; i += 4) s += fp[i*F_ + f];
    sm[t] = s; __syncthreads();
    if (c == 0) {
        float tot = sm[f] + sm[64+f] + sm[128+f] + sm[192+f];
        fpsum[f] = tot;
        mi[f] = tot / (float)S_;
    }
}

__global__ void mlp_metric_kernel(const float* __restrict__ mi,
                                  const float* __restrict__ fm1w, const float* __restrict__ fm1b,
                                  const float* __restrict__ fm2w, const float* __restrict__ fm2b,
                                  float* __restrict__ metric)
{
    __shared__ float smi[F_];
    __shared__ float hid[F_/2];
    __shared__ float raw[F_];
    int t = threadIdx.x;
    smi[t] = mi[t];
    __syncthreads();
    if (t < F_/2) {
        float a = fm1b[t];
        for (int f = 0; f < F_; f++) a = fmaf(smi[f], fm1w[t*F_ + f], a);
        hid[t] = fmaxf(a, 0.f);
    }
    __syncthreads();
    {
        float a = fm2b[t];
        for (int j = 0; j < F_/2; j++) a = fmaf(hid[j], fm2w[t*(F_/2) + j], a);
        raw[t] = a;
    }
    __syncthreads();
    for (int b = 0; b < F_; b++)
        metric[t*F_ + b] = raw[t]*raw[b] + ((t == b) ? 0.1f : 0.f);
}

__global__ void compute_g_kernel(const float* __restrict__ fp,
                                 const float* __restrict__ metric,
                                 float* __restrict__ g)
{
    __shared__ float sm[F_*F_];
    for (int i = threadIdx.x; i < F_*F_; i += blockDim.x) sm[i] = metric[i];
    __syncthreads();
    int t = threadIdx.x;
    int f = t & 63, r = t >> 6;
    int i = blockIdx.x*4 + r;
    const float* fr = fp + (size_t)i*F_;
    float a = 0.f;
#pragma unroll
    for (int k = 0; k < F_; k++) a = fmaf(fr[k], sm[k*F_ + f], a);
    g[(size_t)i*F_ + f] = a;
}

__global__ void curv_kernel(const float* __restrict__ fp, const float* __restrict__ cm,
                            float* __restrict__ curv, float* __restrict__ curvb)
{
    int j = blockIdx.x*blockDim.x + threadIdx.x;
    if (j >= S_) return;
    float a = 0.f;
#pragma unroll
    for (int f = 0; f < F_; f++) a = fmaf(fp[(size_t)j*F_ + f], cm[f*(F_+1)], a);
    curv[j] = a;
    curvb[j] = COUPLING * a;
}

__global__ void pack_aug_kernel(const float* __restrict__ Q, const float* __restrict__ Km,
                                const float* __restrict__ g, const float* __restrict__ fp,
                                bf16* __restrict__ Qhi, bf16* __restrict__ Qlo,
                                bf16* __restrict__ Khi, bf16* __restrict__ Klo)
{
    int idx = blockIdx.x*blockDim.x + threadIdx.x;
    if (idx >= H_*S_*AUG) return;
    int d = idx % AUG;
    int i = (idx / AUG) % S_;
    int h = idx / (AUG*S_);
    float qv, kv;
    if (d < DK) {
        qv = Q[(size_t)i*DM + h*DK + d] * INV_SCALE;
        kv = Km[(size_t)i*DM + h*DK + d];
    } else {
        qv = COUPLING * g[(size_t)i*F_ + (d-DK)];
        kv = fp[(size_t)i*F_ + (d-DK)];
    }
    bf16 qh = __float2bfloat16(qv);
    Qhi[idx] = qh;
    Qlo[idx] = __float2bfloat16(qv - __bfloat162float(qh));
    bf16 kh = __float2bfloat16(kv);
    Khi[idx] = kh;
    Klo[idx] = __float2bfloat16(kv - __bfloat162float(kh));
}

__global__ void softmax_kernel(const float* __restrict__ P,
                               bf16* __restrict__ Phi, bf16* __restrict__ Plo)
{
    size_t row = blockIdx.x;
    const float* p = P + row * (size_t)S_;
    int t = threadIdx.x;
    float vals[8];
    float4 v0 = *(const float4*)(p + t*8);
    float4 v1 = *(const float4*)(p + t*8 + 4);
    vals[0]=v0.x; vals[1]=v0.y; vals[2]=v0.z; vals[3]=v0.w;
    vals[4]=v1.x; vals[5]=v1.y; vals[6]=v1.z; vals[7]=v1.w;
    float m = vals[0];
#pragma unroll
    for (int i = 1; i < 8; i++) m = fmaxf(m, vals[i]);
    __shared__ float red[8];
    for (int o = 16; o; o >>= 1) m = fmaxf(m, __shfl_xor_sync(~0u, m, o));
    if ((t & 31) == 0) red[t>>5] = m;
    __syncthreads();
    m = red[0];
#pragma unroll
    for (int i = 1; i < 8; i++) m = fmaxf(m, red[i]);
    float s = 0.f;
#pragma unroll
    for (int i = 0; i < 8; i++) { vals[i] = __expf(vals[i] - m); s += vals[i]; }
    for (int o = 16; o; o >>= 1) s += __shfl_xor_sync(~0u, s, o);
    __shared__ float red2[8];
    if ((t & 31) == 0) red2[t>>5] = s;
    __syncthreads();
    s = red2[0];
#pragma unroll
    for (int i = 1; i < 8; i++) s += red2[i];
    float inv = 1.0f / s;
    uint4 hv, lv;
    float w0 = vals[0]*inv, w1 = vals[1]*inv, w2 = vals[2]*inv, w3 = vals[3]*inv;
    float w4 = vals[4]*inv, w5 = vals[5]*inv, w6 = vals[6]*inv, w7 = vals[7]*inv;
    bf16 h0=__float2bfloat16(w0), h1=__float2bfloat16(w1), h2=__float2bfloat16(w2), h3=__float2bfloat16(w3);
    bf16 h4=__float2bfloat16(w4), h5=__float2bfloat16(w5), h6=__float2bfloat16(w6), h7=__float2bfloat16(w7);
    hv.x = (uint32_t)__bfloat16_as_ushort(h0) | ((uint32_t)__bfloat16_as_ushort(h1) << 16);
    hv.y = (uint32_t)__bfloat16_as_ushort(h2) | ((uint32_t)__bfloat16_as_ushort(h3) << 16);
    hv.z = (uint32_t)__bfloat16_as_ushort(h4) | ((uint32_t)__bfloat16_as_ushort(h5) << 16);
    hv.w = (uint32_t)__bfloat16_as_ushort(h6) | ((uint32_t)__bfloat16_as_ushort(h7) << 16);
    lv.x = pack_bf16x2(w0 - __bfloat162float(h0), w1 - __bfloat162float(h1));
    lv.y = pack_bf16x2(w2 - __bfloat162float(h2), w3 - __bfloat162float(h3));
    lv.z = pack_bf16x2(w4 - __bfloat162float(h4), w5 - __bfloat162float(h5));
    lv.w = pack_bf16x2(w6 - __bfloat162float(h6), w7 - __bfloat162float(h7));
    *(uint4*)(Phi + row * (size_t)S_ + t*8) = hv;
    *(uint4*)(Plo + row * (size_t)S_ + t*8) = lv;
}

__global__ void scalar_kernel(const float* __restrict__ g, const float* __restrict__ fpsum,
                              const float* __restrict__ curv, float* __restrict__ out0,
                              float* __restrict__ out1)
{
    __shared__ float sm[256];
    __shared__ float sc[256];
    int t = threadIdx.x;
    int f = t & 63, c = t >> 6;
    float s = 0.f;
    for (int i = c; i < S_; i += 4) s += g[i*F_ + f];
    sm[t] = s; __syncthreads();
    float tot = 0.f;
    if (c == 0) tot = sm[f] + sm[64+f] + sm[128+f] + sm[192+f];
    __syncthreads();
    sm[t] = (c == 0) ? tot * fpsum[f] : 0.f;
    float cs = 0.f;
    for (int j = t; j < S_; j += 256) cs += curv[j];
    sc[t] = cs;
    __syncthreads();
    if (t == 0) {
        float a = 0.f, b = 0.f;
        for (int i = 0; i < 64; i++) a += sm[i];
        for (int i = 0; i < 256; i++) b += sc[i];
        float val = a / ((float)S_ * (float)S_) + b / (float)S_;
        *out0 = val;
        if (out1) *out1 = val;
    }
}

// ================= launch =================
extern "C" void kernel_launch(void* const* d_in, const int* in_sizes, int n_in,
                              void* d_out, int out_size)
{
    const float* x    = (const float*)d_in[0];
    const float* wq   = (const float*)d_in[2];
    const float* wk   = (const float*)d_in[3];
    const float* wv   = (const float*)d_in[4];
    const float* wo_w = (const float*)d_in[5];
    const float* wo_b = (const float*)d_in[6];
    const float* fw   = (const float*)d_in[7];
    const float* fb   = (const float*)d_in[8];
    const float* fm1w = (const float*)d_in[9];
    const float* fm1b = (const float*)d_in[10];
    const float* fm2w = (const float*)d_in[11];
    const float* fm2b = (const float*)d_in[12];
    const float* cm   = (const float*)d_in[13];
    float* out = (float*)d_out;

    bf16 *xhi,*xlo,*wqkhi,*wqklo,*wvhi,*wvlo,*wohi,*wolo;
    bf16 *Vthi,*Vtlo,*Qahi,*Qalo,*Kahi,*Kalo,*Phi,*Plo,*athi,*atlo;
    float *QK,*fp,*fpart,*g,*metric,*mi,*fpsum,*curv,*curvb,*scores;
    cudaGetSymbolAddress((void**)&xhi, d_xhi);     cudaGetSymbolAddress((void**)&xlo, d_xlo);
    cudaGetSymbolAddress((void**)&wqkhi, d_wqkhi); cudaGetSymbolAddress((void**)&wqklo, d_wqklo);
    cudaGetSymbolAddress((void**)&wvhi, d_wvhi);   cudaGetSymbolAddress((void**)&wvlo, d_wvlo);
    cudaGetSymbolAddress((void**)&wohi, d_wohi);   cudaGetSymbolAddress((void**)&wolo, d_wolo);
    cudaGetSymbolAddress((void**)&Vthi, d_Vthi);   cudaGetSymbolAddress((void**)&Vtlo, d_Vtlo);
    cudaGetSymbolAddress((void**)&Qahi, d_Qahi);   cudaGetSymbolAddress((void**)&Qalo, d_Qalo);
    cudaGetSymbolAddress((void**)&Kahi, d_Kahi);   cudaGetSymbolAddress((void**)&Kalo, d_Kalo);
    cudaGetSymbolAddress((void**)&Phi, d_Phi);     cudaGetSymbolAddress((void**)&Plo, d_Plo);
    cudaGetSymbolAddress((void**)&athi, d_attnhi); cudaGetSymbolAddress((void**)&atlo, d_attnlo);
    cudaGetSymbolAddress((void**)&QK, d_QK);
    cudaGetSymbolAddress((void**)&fp, d_fp);       cudaGetSymbolAddress((void**)&fpart, d_fpart);
    cudaGetSymbolAddress((void**)&g, d_g);
    cudaGetSymbolAddress((void**)&metric, d_metric); cudaGetSymbolAddress((void**)&mi, d_mi);
    cudaGetSymbolAddress((void**)&fpsum, d_fpsum);   cudaGetSymbolAddress((void**)&curv, d_curv);
    cudaGetSymbolAddress((void**)&curvb, d_curvb);   cudaGetSymbolAddress((void**)&scores, d_scores);

    cudaFuncSetAttribute(mma_gemm_nt<0>, cudaFuncAttributeMaxDynamicSharedMemorySize, MMA_SMEM);
    cudaFuncSetAttribute(mma_gemm_nt<1>, cudaFuncAttributeMaxDynamicSharedMemorySize, MMA_SMEM);

    const int NDM = S_*DM;
    // 0) all 5 bf16 hi/lo splits, vectorized x4, one launch
    split5_kernel<<<dim3(NDM/1024, 5), 256>>>(
        x, wq, wk, wv, wo_w,
        xhi, wqkhi, wqkhi + (size_t)DM*DM, wvhi, wohi,
        xlo, wqklo, wqklo + (size_t)DM*DM, wvlo, wolo);

    // 1) Q and K projections batched: z=2 (fp32 out, contiguous in d_QK)
    mma_gemm_nt<0><<<dim3(16,16,2), 256, MMA_SMEM>>>(
        xhi, xlo, DM, 0, wqkhi, wqklo, DM, (size_t)DM*DM,
        QK, nullptr, nullptr, DM, (size_t)S_*DM, DM, nullptr);
    // 2) Vt[d][s] = wv @ x^T (bf16 hi/lo out)
    mma_gemm_nt<1><<<dim3(16,16,1), 256, MMA_SMEM>>>(wvhi, wvlo, DM, 0, xhi, xlo, DM, 0,
                                                     nullptr, Vthi, Vtlo, S_, 0, DM, nullptr);
    // 3) fiber projection (deterministic split-K, 512 blocks)
    fiber_gemm<<<dim3(16, 32), 256>>>(x, fw, fpart);
    fiber_reduce<<<S_*F_/256, 256>>>(fpart, fb, fp);
    // 4) stats -> MLP -> metric -> g -> curv
    fp_stats_kernel<<<1, 256>>>(fp, fpsum, mi);
    mlp_metric_kernel<<<1, 64>>>(mi, fm1w, fm1b, fm2w, fm2b, metric);
    compute_g_kernel<<<S_/4, 256>>>(fp, metric, g);
    curv_kernel<<<S_/256, 256>>>(fp, cm, curv, curvb);
    // 5) pack augmented Q/K hi/lo
    pack_aug_kernel<<<(H_*S_*AUG)/256, 256>>>(QK, QK + (size_t)S_*DM, g, fp,
                                              Qahi, Qalo, Kahi, Kalo);
    // 6) scores = Qaug @ Kaug^T + 0.1*curv[col] (K=192, batched heads)
    mma_gemm_nt<0><<<dim3(16,16,H_), 256, MMA_SMEM>>>(
        Qahi, Qalo, AUG, (size_t)S_*AUG, Kahi, Kalo, AUG, (size_t)S_*AUG,
        scores, nullptr, nullptr, S_, (size_t)S_*S_, AUG, curvb);
    // 7) softmax -> P hi/lo (vectorized stores)
    softmax_kernel<<<H_*S_, 256>>>(scores, Phi, Plo);
    // 8) attn[q, h*128+d] = P[h] @ Vt[h]^T (bf16 hi/lo out)
    mma_gemm_nt<1><<<dim3(1,16,H_), 256, MMA_SMEM>>>(
        Phi, Plo, S_, (size_t)S_*S_, Vthi, Vtlo, S_, (size_t)DK*S_,
        nullptr, athi, atlo, DM, (size_t)DK, S_, nullptr);
    // 9) out = attn @ wo^T + wo_b (fp32 -> d_out)
    mma_gemm_nt<0><<<dim3(16,16,1), 256, MMA_SMEM>>>(athi, atlo, DM, 0, wohi, wolo, DM, 0,
                                                     out, nullptr, nullptr, DM, 0, DM, wo_b);
    // 10) ci.mean() scalar
    if (out_size > S_*DM) {
        float* o0 = out + (size_t)S_*DM;
        float* o1 = out + (size_t)(out_size - 1);
        scalar_kernel<<<1, 256>>>(g, fpsum, curv, o0, (o1 != o0) ? o1 : nullptr);
    }
}

// round 13
// speedup vs baseline: 1.3390x; 1.2576x over previous
#include <cuda_runtime.h>
#include <cuda_fp16.h>
#include <cstdint>
#include <math.h>

#define S_  2048
#define DM  2048
#define H_  16
#define DK  128
#define F_  64
#define AUG 192
#define INV_SCALE (1.0f/11.313708498984761f)
#define COUPLING 0.1f

typedef __half h16;

// ---------------- device scratch (256B-aligned) ----------------
__device__ __align__(256) h16   d_xhi[S_*DM],  d_xlo[S_*DM];
__device__ __align__(256) h16   d_wqkhi[2*DM*DM];                     // wq then wk (hi only)
__device__ __align__(256) h16   d_wvhi[DM*DM], d_wvlo[DM*DM];
__device__ __align__(256) h16   d_wohi[DM*DM];
__device__ __align__(256) float d_QK[2*S_*DM];                        // Q then K (fp32)
__device__ __align__(256) h16   d_Vthi[DM*S_];                        // V transposed [d][s], hi only
__device__ __align__(256) float d_fp[S_*F_];
__device__ __align__(256) float d_fpart[16*S_*F_];
__device__ __align__(256) float d_g[S_*F_];
__device__ __align__(256) float d_metric[F_*F_];
__device__ __align__(256) float d_mi[F_];
__device__ __align__(256) float d_fpsum[F_];
__device__ __align__(256) float d_curv[S_];
__device__ __align__(256) float d_curvb[S_];
__device__ __align__(256) h16   d_Qahi[H_*S_*AUG], d_Qalo[H_*S_*AUG];
__device__ __align__(256) h16   d_Kahi[H_*S_*AUG];                    // hi only
__device__ __align__(256) float d_scores[H_*S_*S_];
__device__ __align__(256) h16   d_Phi[H_*S_*S_], d_Plo[H_*S_*S_];
__device__ __align__(256) h16   d_attnhi[S_*DM], d_attnlo[S_*DM];

// ================= portable-ISA helpers =================
__device__ __forceinline__ uint32_t smem_to_u32(const void* p) {
    uint32_t a;
    asm("{ .reg .u64 t; cvta.to.shared.u64 t, %1; cvt.u32.u64 %0, t; }" : "=r"(a) : "l"(p));
    return a;
}
__device__ __forceinline__ void cp16(uint32_t saddr, const void* g) {
    asm volatile("cp.async.cg.shared.global [%0], [%1], 16;" :: "r"(saddr), "l"(g));
}
__device__ __forceinline__ void ldsm4(uint32_t* r, uint32_t a) {
    asm volatile("ldmatrix.sync.aligned.m8n8.x4.shared.b16 {%0,%1,%2,%3}, [%4];"
                 : "=r"(r[0]), "=r"(r[1]), "=r"(r[2]), "=r"(r[3]) : "r"(a));
}
__device__ __forceinline__ void mma_f16(float* c, const uint32_t* a, uint32_t b0, uint32_t b1) {
    asm volatile("mma.sync.aligned.m16n8k16.row.col.f32.f16.f16.f32 "
                 "{%0,%1,%2,%3}, {%4,%5,%6,%7}, {%8,%9}, {%0,%1,%2,%3};"
                 : "+f"(c[0]), "+f"(c[1]), "+f"(c[2]), "+f"(c[3])
                 : "r"(a[0]), "r"(a[1]), "r"(a[2]), "r"(a[3]), "r"(b0), "r"(b1));
}
__device__ __forceinline__ uint32_t pack_h16x2(float lo, float hi) {
    unsigned short l = __half_as_ushort(__float2half(lo));
    unsigned short h = __half_as_ushort(__float2half(hi));
    return (uint32_t)l | ((uint32_t)h << 16);
}

// smem stage: Ahi | Alo | Bhi, each 128 rows x 32 h16 (64B rows), XOR swizzled
#define STAGE_BYTES 24576
#define MMA_SMEM (2*STAGE_BYTES)

__device__ __forceinline__ uint32_t sw_off(int row, int chunk) {
    return (uint32_t)(row * 64 + ((chunk ^ ((row >> 1) & 3)) << 4));
}

__device__ __forceinline__ void load_tiles(uint32_t sbase, int tid,
    const h16* g0, const h16* g1, const h16* g2,
    int lda, int ldb, int k0)
{
    const h16* gp[3] = {g0, g1, g2};
#pragma unroll
    for (int i = 0; i < 6; i++) {
        int q = tid + i * 256;                       // 0..1535
        int tile = q >> 9, r = (q >> 2) & 127, c = q & 3;
        int ld = (tile < 2) ? lda : ldb;
        const h16* src = gp[tile] + (size_t)r * ld + k0 + c * 8;
        uint32_t so = sbase + tile * 8192 + sw_off(r, c);
        cp16(so, src);
    }
    asm volatile("cp.async.commit_group;" ::: "memory");
}

// ================= NT GEMM via mma.sync, fp16 2-term split (A-side corrected) =================
// C[bm.., bn..] = sum_k A[m,k]*B[n,k]; M,N multiples of 128; K multiple of 32; batch z.
// OUT_MODE 0: fp32 C (+bias[col]); OUT_MODE 1: h16 hi/lo outputs; OUT_MODE 2: h16 hi only.
template<int OUT_MODE>
__global__ void __launch_bounds__(256)
mma_gemm_nt(const h16* __restrict__ Ahi, const h16* __restrict__ Alo, int lda, size_t sAz,
            const h16* __restrict__ Bhi, int ldb, size_t sBz,
            float* __restrict__ C, h16* __restrict__ Chi, h16* __restrict__ Clo,
            int ldc, size_t sCz, int K, const float* __restrict__ bias)
{
    extern __shared__ char smem[];
    const uint32_t sb = smem_to_u32(smem);
    const int tid = threadIdx.x, lane = tid & 31, wid = tid >> 5;
    const int wm = wid & 1, wn = wid >> 1;           // 2 x 4 warp grid, warp tile 64x32
    const size_t z = blockIdx.z;
    const int bm = blockIdx.y * 128, bn = blockIdx.x * 128;

    const h16* gA0 = Ahi + z * sAz + (size_t)bm * lda;
    const h16* gA1 = Alo + z * sAz + (size_t)bm * lda;
    const h16* gB0 = Bhi + z * sBz + (size_t)bn * ldb;

    float acc[4][4][4];
#pragma unroll
    for (int i = 0; i < 4; i++)
#pragma unroll
        for (int j = 0; j < 4; j++)
#pragma unroll
            for (int k = 0; k < 4; k++) acc[i][j][k] = 0.f;

    const int a_row_l = (lane & 7) + ((lane >> 3) & 1) * 8;
    const int a_chk_l = lane >> 4;
    const int b_row_l = (lane & 7) + ((lane >> 4) & 1) * 8;
    const int b_chk_l = (lane >> 3) & 1;

    const int nch = K >> 5;
    load_tiles(sb, tid, gA0, gA1, gB0, lda, ldb, 0);

    for (int c = 0; c < nch; c++) {
        if (c + 1 < nch) {
            load_tiles(sb + ((c + 1) & 1) * STAGE_BYTES, tid, gA0, gA1, gB0,
                       lda, ldb, (c + 1) * 32);
            asm volatile("cp.async.wait_group 1;" ::: "memory");
        } else {
            asm volatile("cp.async.wait_group 0;" ::: "memory");
        }
        __syncthreads();
        const uint32_t s0 = sb + (c & 1) * STAGE_BYTES;
#pragma unroll
        for (int ks = 0; ks < 2; ks++) {
            uint32_t a_hi[4][4], a_lo[4][4], b_hi[8];
#pragma unroll
            for (int mt = 0; mt < 4; mt++) {
                int row = wm * 64 + mt * 16 + a_row_l;
                uint32_t off = sw_off(row, ks * 2 + a_chk_l);
                ldsm4(a_hi[mt], s0 + off);
                ldsm4(a_lo[mt], s0 + 8192 + off);
            }
#pragma unroll
            for (int ntp = 0; ntp < 2; ntp++) {
                int row = wn * 32 + ntp * 16 + b_row_l;
                uint32_t off = sw_off(row, ks * 2 + b_chk_l);
                ldsm4(&b_hi[ntp * 4], s0 + 16384 + off);
            }
#pragma unroll
            for (int mt = 0; mt < 4; mt++)
#pragma unroll
                for (int nt = 0; nt < 4; nt++) {
                    int bi = (nt >> 1) * 4 + (nt & 1) * 2;
                    mma_f16(acc[mt][nt], a_hi[mt], b_hi[bi], b_hi[bi + 1]);
                    mma_f16(acc[mt][nt], a_lo[mt], b_hi[bi], b_hi[bi + 1]);
                }
        }
        __syncthreads();
    }

    // epilogue
    const int r_l = lane >> 2, c_l = (lane & 3) * 2;
#pragma unroll
    for (int mt = 0; mt < 4; mt++) {
#pragma unroll
        for (int nt = 0; nt < 4; nt++) {
            int row0 = bm + wm * 64 + mt * 16 + r_l;
            int col  = bn + wn * 32 + nt * 8 + c_l;
            float v0 = acc[mt][nt][0], v1 = acc[mt][nt][1];
            float v2 = acc[mt][nt][2], v3 = acc[mt][nt][3];
            if (OUT_MODE == 0) {
                if (bias) { v0 += bias[col]; v1 += bias[col + 1]; v2 += bias[col]; v3 += bias[col + 1]; }
                float* p0 = C + z * sCz + (size_t)row0 * ldc + col;
                float* p1 = C + z * sCz + (size_t)(row0 + 8) * ldc + col;
                p0[0] = v0; p0[1] = v1;
                p1[0] = v2; p1[1] = v3;
            } else if (OUT_MODE == 1) {
                h16 h0 = __float2half(v0), h1 = __float2half(v1);
                h16 h2 = __float2half(v2), h3 = __float2half(v3);
                h16* hp0 = Chi + z * sCz + (size_t)row0 * ldc + col;
                h16* hp1 = Chi + z * sCz + (size_t)(row0 + 8) * ldc + col;
                h16* lp0 = Clo + z * sCz + (size_t)row0 * ldc + col;
                h16* lp1 = Clo + z * sCz + (size_t)(row0 + 8) * ldc + col;
                hp0[0] = h0; hp0[1] = h1; hp1[0] = h2; hp1[1] = h3;
                lp0[0] = __float2half(v0 - __half2float(h0));
                lp0[1] = __float2half(v1 - __half2float(h1));
                lp1[0] = __float2half(v2 - __half2float(h2));
                lp1[1] = __float2half(v3 - __half2float(h3));
            } else {
                h16* hp0 = Chi + z * sCz + (size_t)row0 * ldc + col;
                h16* hp1 = Chi + z * sCz + (size_t)(row0 + 8) * ldc + col;
                hp0[0] = __float2half(v0); hp0[1] = __float2half(v1);
                hp1[0] = __float2half(v2); hp1[1] = __float2half(v3);
            }
        }
    }
}

// ================= small kernels =================
// vectorized batched split; lo pointer may be null (hi-only tensors)
__global__ void split5_kernel(
    const float* __restrict__ s0, const float* __restrict__ s1, const float* __restrict__ s2,
    const float* __restrict__ s3, const float* __restrict__ s4,
    h16* __restrict__ h0, h16* __restrict__ h1, h16* __restrict__ h2,
    h16* __restrict__ h3, h16* __restrict__ h4,
    h16* __restrict__ l0, h16* __restrict__ l3)
{
    int i4 = blockIdx.x * blockDim.x + threadIdx.x;   // index of float4
    int zz = blockIdx.y;
    const float* src = (zz == 0) ? s0 : (zz == 1) ? s1 : (zz == 2) ? s2 : (zz == 3) ? s3 : s4;
    h16* hi = (zz == 0) ? h0 : (zz == 1) ? h1 : (zz == 2) ? h2 : (zz == 3) ? h3 : h4;
    h16* lo = (zz == 0) ? l0 : (zz == 3) ? l3 : (h16*)0;
    float4 v = *((const float4*)src + i4);
    h16 a = __float2half(v.x), b = __float2half(v.y);
    h16 c = __float2half(v.z), d = __float2half(v.w);
    uint2 hv;
    hv.x = (uint32_t)__half_as_ushort(a) | ((uint32_t)__half_as_ushort(b) << 16);
    hv.y = (uint32_t)__half_as_ushort(c) | ((uint32_t)__half_as_ushort(d) << 16);
    *((uint2*)hi + i4) = hv;
    if (lo) {
        uint2 lv;
        lv.x = pack_h16x2(v.x - __half2float(a), v.y - __half2float(b));
        lv.y = pack_h16x2(v.z - __half2float(c), v.w - __half2float(d));
        *((uint2*)lo + i4) = lv;
    }
}

// deterministic split-K fiber projection: 16 K-splits of 128
__global__ void fiber_gemm(const float* __restrict__ x, const float* __restrict__ fw,
                           float* __restrict__ fpart)
{
    __shared__ float Xs[64][68];
    __shared__ float Fs[64][68];
    const int ksplit = blockIdx.x;
    const int rb = blockIdx.y * 64;
    const int t = threadIdx.x;
    const int rt = t & 15, ct = t >> 4;
    float acc[4][4] = {};
    for (int sub = 0; sub < 2; sub++) {
        const int k0 = ksplit * 128 + sub * 64;
        __syncthreads();
        for (int i = t; i < 1024; i += 256) {
            int row = i >> 4, kq = (i & 15) * 4;
            float4 v = *(const float4*)&x[(size_t)(rb + row) * DM + k0 + kq];
            Xs[kq][row] = v.x; Xs[kq+1][row] = v.y; Xs[kq+2][row] = v.z; Xs[kq+3][row] = v.w;
            float4 w = *(const float4*)&fw[(size_t)row * DM + k0 + kq];
            Fs[kq][row] = w.x; Fs[kq+1][row] = w.y; Fs[kq+2][row] = w.z; Fs[kq+3][row] = w.w;
        }
        __syncthreads();
#pragma unroll 16
        for (int k = 0; k < 64; k++) {
            float a[4], b[4];
#pragma unroll
            for (int i = 0; i < 4; i++) a[i] = Xs[k][rt*4 + i];
#pragma unroll
            for (int j = 0; j < 4; j++) b[j] = Fs[k][ct*4 + j];
#pragma unroll
            for (int i = 0; i < 4; i++)
#pragma unroll
                for (int j = 0; j < 4; j++) acc[i][j] = fmaf(a[i], b[j], acc[i][j]);
        }
    }
    float* dst = fpart + (size_t)ksplit * S_ * F_;
#pragma unroll
    for (int i = 0; i < 4; i++)
#pragma unroll
        for (int j = 0; j < 4; j++)
            dst[(size_t)(rb + rt*4 + i) * F_ + ct*4 + j] = acc[i][j];
}

__global__ void fiber_reduce(const float* __restrict__ fpart, const float* __restrict__ fb,
                             float* __restrict__ fp)
{
    int i = blockIdx.x * blockDim.x + threadIdx.x;
    if (i >= S_ * F_) return;
    float a = fb[i & 63];
#pragma unroll
    for (int s = 0; s < 16; s++) a += fpart[(size_t)s * S_ * F_ + i];
    fp[i] = a;
}

__global__ void fp_stats_kernel(const float* __restrict__ fp,
                                float* __restrict__ fpsum, float* __restrict__ mi)
{
    __shared__ float sm[256];
    int t = threadIdx.x;
    int f = t & 63, c = t >> 6;
    float s = 0.f;
    for (int i = c; i < S_; i += 4) s += fp[i*F_ + f];
    sm[t] = s; __syncthreads();
    if (c == 0) {
        float tot = sm[f] + sm[64+f] + sm[128+f] + sm[192+f];
        fpsum[f] = tot;
        mi[f] = tot / (float)S_;
    }
}

__global__ void mlp_metric_kernel(const float* __restrict__ mi,
                                  const float* __restrict__ fm1w, const float* __restrict__ fm1b,
                                  const float* __restrict__ fm2w, const float* __restrict__ fm2b,
                                  float* __restrict__ metric)
{
    __shared__ float smi[F_];
    __shared__ float hid[F_/2];
    __shared__ float raw[F_];
    int t = threadIdx.x;
    smi[t] = mi[t];
    __syncthreads();
    if (t < F_/2) {
        float a = fm1b[t];
        for (int f = 0; f < F_; f++) a = fmaf(smi[f], fm1w[t*F_ + f], a);
        hid[t] = fmaxf(a, 0.f);
    }
    __syncthreads();
    {
        float a = fm2b[t];
        for (int j = 0; j < F_/2; j++) a = fmaf(hid[j], fm2w[t*(F_/2) + j], a);
        raw[t] = a;
    }
    __syncthreads();
    for (int b = 0; b < F_; b++)
        metric[t*F_ + b] = raw[t]*raw[b] + ((t == b) ? 0.1f : 0.f);
}

__global__ void compute_g_kernel(const float* __restrict__ fp,
                                 const float* __restrict__ metric,
                                 float* __restrict__ g)
{
    __shared__ float sm[F_*F_];
    for (int i = threadIdx.x; i < F_*F_; i += blockDim.x) sm[i] = metric[i];
    __syncthreads();
    int t = threadIdx.x;
    int f = t & 63, r = t >> 6;
    int i = blockIdx.x*4 + r;
    const float* fr = fp + (size_t)i*F_;
    float a = 0.f;
#pragma unroll
    for (int k = 0; k < F_; k++) a = fmaf(fr[k], sm[k*F_ + f], a);
    g[(size_t)i*F_ + f] = a;
}

__global__ void curv_kernel(const float* __restrict__ fp, const float* __restrict__ cm,
                            float* __restrict__ curv, float* __restrict__ curvb)
{
    int j = blockIdx.x*blockDim.x + threadIdx.x;
    if (j >= S_) return;
    float a = 0.f;
#pragma unroll
    for (int f = 0; f < F_; f++) a = fmaf(fp[(size_t)j*F_ + f], cm[f*(F_+1)], a);
    curv[j] = a;
    curvb[j] = COUPLING * a;
}

__global__ void pack_aug_kernel(const float* __restrict__ Q, const float* __restrict__ Km,
                                const float* __restrict__ g, const float* __restrict__ fp,
                                h16* __restrict__ Qhi, h16* __restrict__ Qlo,
                                h16* __restrict__ Khi)
{
    int idx = blockIdx.x*blockDim.x + threadIdx.x;
    if (idx >= H_*S_*AUG) return;
    int d = idx % AUG;
    int i = (idx / AUG) % S_;
    int h = idx / (AUG*S_);
    float qv, kv;
    if (d < DK) {
        qv = Q[(size_t)i*DM + h*DK + d] * INV_SCALE;
        kv = Km[(size_t)i*DM + h*DK + d];
    } else {
        qv = COUPLING * g[(size_t)i*F_ + (d-DK)];
        kv = fp[(size_t)i*F_ + (d-DK)];
    }
    h16 qh = __float2half(qv);
    Qhi[idx] = qh;
    Qlo[idx] = __float2half(qv - __half2float(qh));
    Khi[idx] = __float2half(kv);
}

__global__ void softmax_kernel(const float* __restrict__ P,
                               h16* __restrict__ Phi, h16* __restrict__ Plo)
{
    size_t row = blockIdx.x;
    const float* p = P + row * (size_t)S_;
    int t = threadIdx.x;
    float vals[8];
    float4 v0 = *(const float4*)(p + t*8);
    float4 v1 = *(const float4*)(p + t*8 + 4);
    vals[0]=v0.x; vals[1]=v0.y; vals[2]=v0.z; vals[3]=v0.w;
    vals[4]=v1.x; vals[5]=v1.y; vals[6]=v1.z; vals[7]=v1.w;
    float m = vals[0];
#pragma unroll
    for (int i = 1; i < 8; i++) m = fmaxf(m, vals[i]);
    __shared__ float red[8];
    for (int o = 16; o; o >>= 1) m = fmaxf(m, __shfl_xor_sync(~0u, m, o));
    if ((t & 31) == 0) red[t>>5] = m;
    __syncthreads();
    m = red[0];
#pragma unroll
    for (int i = 1; i < 8; i++) m = fmaxf(m, red[i]);
    float s = 0.f;
#pragma unroll
    for (int i = 0; i < 8; i++) { vals[i] = __expf(vals[i] - m); s += vals[i]; }
    for (int o = 16; o; o >>= 1) s += __shfl_xor_sync(~0u, s, o);
    __shared__ float red2[8];
    if ((t & 31) == 0) red2[t>>5] = s;
    __syncthreads();
    s = red2[0];
#pragma unroll
    for (int i = 1; i < 8; i++) s += red2[i];
    float inv = 1.0f / s;
    uint4 hv, lv;
    float w0 = vals[0]*inv, w1 = vals[1]*inv, w2 = vals[2]*inv, w3 = vals[3]*inv;
    float w4 = vals[4]*inv, w5 = vals[5]*inv, w6 = vals[6]*inv, w7 = vals[7]*inv;
    h16 h0=__float2half(w0), h1=__float2half(w1), h2=__float2half(w2), h3=__float2half(w3);
    h16 h4=__float2half(w4), h5=__float2half(w5), h6=__float2half(w6), h7=__float2half(w7);
    hv.x = (uint32_t)__half_as_ushort(h0) | ((uint32_t)__half_as_ushort(h1) << 16);
    hv.y = (uint32_t)__half_as_ushort(h2) | ((uint32_t)__half_as_ushort(h3) << 16);
    hv.z = (uint32_t)__half_as_ushort(h4) | ((uint32_t)__half_as_ushort(h5) << 16);
    hv.w = (uint32_t)__half_as_ushort(h6) | ((uint32_t)__half_as_ushort(h7) << 16);
    lv.x = pack_h16x2(w0 - __half2float(h0), w1 - __half2float(h1));
    lv.y = pack_h16x2(w2 - __half2float(h2), w3 - __half2float(h3));
    lv.z = pack_h16x2(w4 - __half2float(h4), w5 - __half2float(h5));
    lv.w = pack_h16x2(w6 - __half2float(h6), w7 - __half2float(h7));
    *(uint4*)(Phi + row * (size_t)S_ + t*8) = hv;
    *(uint4*)(Plo + row * (size_t)S_ + t*8) = lv;
}

__global__ void scalar_kernel(const float* __restrict__ g, const float* __restrict__ fpsum,
                              const float* __restrict__ curv, float* __restrict__ out0,
                              float* __restrict__ out1)
{
    __shared__ float sm[256];
    __shared__ float sc[256];
    int t = threadIdx.x;
    int f = t & 63, c = t >> 6;
    float s = 0.f;
    for (int i = c; i < S_; i += 4) s += g[i*F_ + f];
    sm[t] = s; __syncthreads();
    float tot = 0.f;
    if (c == 0) tot = sm[f] + sm[64+f] + sm[128+f] + sm[192+f];
    __syncthreads();
    sm[t] = (c == 0) ? tot * fpsum[f] : 0.f;
    float cs = 0.f;
    for (int j = t; j < S_; j += 256) cs += curv[j];
    sc[t] = cs;
    __syncthreads();
    if (t == 0) {
        float a = 0.f, b = 0.f;
        for (int i = 0; i < 64; i++) a += sm[i];
        for (int i = 0; i < 256; i++) b += sc[i];
        float val = a / ((float)S_ * (float)S_) + b / (float)S_;
        *out0 = val;
        if (out1) *out1 = val;
    }
}

// ================= launch =================
extern "C" void kernel_launch(void* const* d_in, const int* in_sizes, int n_in,
                              void* d_out, int out_size)
{
    const float* x    = (const float*)d_in[0];
    const float* wq   = (const float*)d_in[2];
    const float* wk   = (const float*)d_in[3];
    const float* wv   = (const float*)d_in[4];
    const float* wo_w = (const float*)d_in[5];
    const float* wo_b = (const float*)d_in[6];
    const float* fw   = (const float*)d_in[7];
    const float* fb   = (const float*)d_in[8];
    const float* fm1w = (const float*)d_in[9];
    const float* fm1b = (const float*)d_in[10];
    const float* fm2w = (const float*)d_in[11];
    const float* fm2b = (const float*)d_in[12];
    const float* cm   = (const float*)d_in[13];
    float* out = (float*)d_out;

    h16 *xhi,*xlo,*wqkhi,*wvhi,*wvlo,*wohi;
    h16 *Vthi,*Qahi,*Qalo,*Kahi,*Phi,*Plo,*athi,*atlo;
    float *QK,*fp,*fpart,*g,*metric,*mi,*fpsum,*curv,*curvb,*scores;
    cudaGetSymbolAddress((void**)&xhi, d_xhi);     cudaGetSymbolAddress((void**)&xlo, d_xlo);
    cudaGetSymbolAddress((void**)&wqkhi, d_wqkhi);
    cudaGetSymbolAddress((void**)&wvhi, d_wvhi);   cudaGetSymbolAddress((void**)&wvlo, d_wvlo);
    cudaGetSymbolAddress((void**)&wohi, d_wohi);
    cudaGetSymbolAddress((void**)&Vthi, d_Vthi);
    cudaGetSymbolAddress((void**)&Qahi, d_Qahi);   cudaGetSymbolAddress((void**)&Qalo, d_Qalo);
    cudaGetSymbolAddress((void**)&Kahi, d_Kahi);
    cudaGetSymbolAddress((void**)&Phi, d_Phi);     cudaGetSymbolAddress((void**)&Plo, d_Plo);
    cudaGetSymbolAddress((void**)&athi, d_attnhi); cudaGetSymbolAddress((void**)&atlo, d_attnlo);
    cudaGetSymbolAddress((void**)&QK, d_QK);
    cudaGetSymbolAddress((void**)&fp, d_fp);       cudaGetSymbolAddress((void**)&fpart, d_fpart);
    cudaGetSymbolAddress((void**)&g, d_g);
    cudaGetSymbolAddress((void**)&metric, d_metric); cudaGetSymbolAddress((void**)&mi, d_mi);
    cudaGetSymbolAddress((void**)&fpsum, d_fpsum);   cudaGetSymbolAddress((void**)&curv, d_curv);
    cudaGetSymbolAddress((void**)&curvb, d_curvb);   cudaGetSymbolAddress((void**)&scores, d_scores);

    cudaFuncSetAttribute(mma_gemm_nt<0>, cudaFuncAttributeMaxDynamicSharedMemorySize, MMA_SMEM);
    cudaFuncSetAttribute(mma_gemm_nt<1>, cudaFuncAttributeMaxDynamicSharedMemorySize, MMA_SMEM);
    cudaFuncSetAttribute(mma_gemm_nt<2>, cudaFuncAttributeMaxDynamicSharedMemorySize, MMA_SMEM);

    const int NDM = S_*DM;
    // 0) fp16 splits: hi for all 5, lo only for x and wv
    split5_kernel<<<dim3(NDM/1024, 5), 256>>>(
        x, wq, wk, wv, wo_w,
        xhi, wqkhi, wqkhi + (size_t)DM*DM, wvhi, wohi,
        xlo, wvlo);

    // 1) Q and K projections batched: z=2 (fp32 out)
    mma_gemm_nt<0><<<dim3(16,16,2), 256, MMA_SMEM>>>(
        xhi, xlo, DM, 0, wqkhi, DM, (size_t)DM*DM,
        QK, nullptr, nullptr, DM, (size_t)S_*DM, DM, nullptr);
    // 2) Vt[d][s] = wv @ x^T (h16 hi only; A=wv corrected)
    mma_gemm_nt<2><<<dim3(16,16,1), 256, MMA_SMEM>>>(wvhi, wvlo, DM, 0, xhi, DM, 0,
                                                     nullptr, Vthi, nullptr, S_, 0, DM, nullptr);
    // 3) fiber projection (deterministic split-K)
    fiber_gemm<<<dim3(16, 32), 256>>>(x, fw, fpart);
    fiber_reduce<<<S_*F_/256, 256>>>(fpart, fb, fp);
    // 4) stats -> MLP -> metric -> g -> curv
    fp_stats_kernel<<<1, 256>>>(fp, fpsum, mi);
    mlp_metric_kernel<<<1, 64>>>(mi, fm1w, fm1b, fm2w, fm2b, metric);
    compute_g_kernel<<<S_/4, 256>>>(fp, metric, g);
    curv_kernel<<<S_/256, 256>>>(fp, cm, curv, curvb);
    // 5) pack augmented Q (hi+lo) / K (hi)
    pack_aug_kernel<<<(H_*S_*AUG)/256, 256>>>(QK, QK + (size_t)S_*DM, g, fp,
                                              Qahi, Qalo, Kahi);
    // 6) scores = Qaug @ Kaug^T + 0.1*curv[col] (K=192, batched heads)
    mma_gemm_nt<0><<<dim3(16,16,H_), 256, MMA_SMEM>>>(
        Qahi, Qalo, AUG, (size_t)S_*AUG, Kahi, AUG, (size_t)S_*AUG,
        scores, nullptr, nullptr, S_, (size_t)S_*S_, AUG, curvb);
    // 7) softmax -> P hi/lo
    softmax_kernel<<<H_*S_, 256>>>(scores, Phi, Plo);
    // 8) attn[q, h*128+d] = P[h] @ Vt[h]^T (h16 hi/lo out; A=P corrected)
    mma_gemm_nt<1><<<dim3(1,16,H_), 256, MMA_SMEM>>>(
        Phi, Plo, S_, (size_t)S_*S_, Vthi, S_, (size_t)DK*S_,
        nullptr, athi, atlo, DM, (size_t)DK, S_, nullptr);
    // 9) out = attn @ wo^T + wo_b (fp32 -> d_out)
    mma_gemm_nt<0><<<dim3(16,16,1), 256, MMA_SMEM>>>(athi, atlo, DM, 0, wohi, DM, 0,
                                                     out, nullptr, nullptr, DM, 0, DM, wo_b);
    // 10) ci.mean() scalar
    if (out_size > S_*DM) {
        float* o0 = out + (size_t)S_*DM;
        float* o1 = out + (size_t)(out_size - 1);
        scalar_kernel<<<1, 256>>>(g, fpsum, curv, o0, (o1 != o0) ? o1 : nullptr);
    }
}

// round 14
// speedup vs baseline: 1.4277x; 1.0662x over previous
#include <cuda_runtime.h>
#include <cuda_fp16.h>
#include <cstdint>
#include <math.h>

#define S_  2048
#define DM  2048
#define H_  16
#define DK  128
#define F_  64
#define AUG 192
#define INV_SCALE (1.0f/11.313708498984761f)
#define COUPLING 0.1f

typedef __half h16;

// ---------------- device scratch (256B-aligned) ----------------
__device__ __align__(256) h16   d_xhi[S_*DM],  d_xlo[S_*DM];
__device__ __align__(256) h16   d_wqkhi[2*DM*DM];                     // wq then wk (hi only)
__device__ __align__(256) h16   d_wvhi[DM*DM], d_wvlo[DM*DM];
__device__ __align__(256) h16   d_wohi[DM*DM];
__device__ __align__(256) float d_QK[2*S_*DM];                        // Q then K (fp32)
__device__ __align__(256) h16   d_Vthi[DM*S_];                        // V transposed [d][s], hi only
__device__ __align__(256) float d_fp[S_*F_];
__device__ __align__(256) float d_fpart[16*S_*F_];
__device__ __align__(256) float d_g[S_*F_];
__device__ __align__(256) float d_metric[F_*F_];
__device__ __align__(256) float d_mi[F_];
__device__ __align__(256) float d_fpsum[F_];
__device__ __align__(256) float d_curv[S_];
__device__ __align__(256) float d_curvb[S_];
__device__ __align__(256) h16   d_Qahi[H_*S_*AUG], d_Qalo[H_*S_*AUG];
__device__ __align__(256) h16   d_Kahi[H_*S_*AUG];                    // hi only
__device__ __align__(256) float d_scores[H_*S_*S_];
__device__ __align__(256) h16   d_Phi[H_*S_*S_];                      // hi only now
__device__ __align__(256) h16   d_attnhi[S_*DM], d_attnlo[S_*DM];

// ================= portable-ISA helpers =================
__device__ __forceinline__ uint32_t smem_to_u32(const void* p) {
    uint32_t a;
    asm("{ .reg .u64 t; cvta.to.shared.u64 t, %1; cvt.u32.u64 %0, t; }" : "=r"(a) : "l"(p));
    return a;
}
__device__ __forceinline__ void cp16(uint32_t saddr, const void* g) {
    asm volatile("cp.async.cg.shared.global [%0], [%1], 16;" :: "r"(saddr), "l"(g));
}
__device__ __forceinline__ void ldsm4(uint32_t* r, uint32_t a) {
    asm volatile("ldmatrix.sync.aligned.m8n8.x4.shared.b16 {%0,%1,%2,%3}, [%4];"
                 : "=r"(r[0]), "=r"(r[1]), "=r"(r[2]), "=r"(r[3]) : "r"(a));
}
__device__ __forceinline__ void mma_f16(float* c, const uint32_t* a, uint32_t b0, uint32_t b1) {
    asm volatile("mma.sync.aligned.m16n8k16.row.col.f32.f16.f16.f32 "
                 "{%0,%1,%2,%3}, {%4,%5,%6,%7}, {%8,%9}, {%0,%1,%2,%3};"
                 : "+f"(c[0]), "+f"(c[1]), "+f"(c[2]), "+f"(c[3])
                 : "r"(a[0]), "r"(a[1]), "r"(a[2]), "r"(a[3]), "r"(b0), "r"(b1));
}
__device__ __forceinline__ uint32_t pack_h16x2(float lo, float hi) {
    unsigned short l = __half_as_ushort(__float2half(lo));
    unsigned short h = __half_as_ushort(__float2half(hi));
    return (uint32_t)l | ((uint32_t)h << 16);
}

__device__ __forceinline__ uint32_t sw_off(int row, int chunk) {
    return (uint32_t)(row * 64 + ((chunk ^ ((row >> 1) & 3)) << 4));
}

// ================= 2-term kernel (A hi+lo, B hi): stage Ahi|Alo|Bhi = 24KB =================
#define STAGE_BYTES 24576
#define MMA_SMEM (2*STAGE_BYTES)

__device__ __forceinline__ void load_tiles(uint32_t sbase, int tid,
    const h16* g0, const h16* g1, const h16* g2,
    int lda, int ldb, int k0)
{
    const h16* gp[3] = {g0, g1, g2};
#pragma unroll
    for (int i = 0; i < 6; i++) {
        int q = tid + i * 256;
        int tile = q >> 9, r = (q >> 2) & 127, c = q & 3;
        int ld = (tile < 2) ? lda : ldb;
        const h16* src = gp[tile] + (size_t)r * ld + k0 + c * 8;
        uint32_t so = sbase + tile * 8192 + sw_off(r, c);
        cp16(so, src);
    }
    asm volatile("cp.async.commit_group;" ::: "memory");
}

// OUT_MODE 0: fp32 C (+bias[col]); OUT_MODE 1: h16 hi/lo; OUT_MODE 2: h16 hi only.
template<int OUT_MODE>
__global__ void __launch_bounds__(256)
mma_gemm_nt(const h16* __restrict__ Ahi, const h16* __restrict__ Alo, int lda, size_t sAz,
            const h16* __restrict__ Bhi, int ldb, size_t sBz,
            float* __restrict__ C, h16* __restrict__ Chi, h16* __restrict__ Clo,
            int ldc, size_t sCz, int K, const float* __restrict__ bias)
{
    extern __shared__ char smem[];
    const uint32_t sb = smem_to_u32(smem);
    const int tid = threadIdx.x, lane = tid & 31, wid = tid >> 5;
    const int wm = wid & 1, wn = wid >> 1;
    const size_t z = blockIdx.z;
    const int bm = blockIdx.y * 128, bn = blockIdx.x * 128;

    const h16* gA0 = Ahi + z * sAz + (size_t)bm * lda;
    const h16* gA1 = Alo + z * sAz + (size_t)bm * lda;
    const h16* gB0 = Bhi + z * sBz + (size_t)bn * ldb;

    float acc[4][4][4];
#pragma unroll
    for (int i = 0; i < 4; i++)
#pragma unroll
        for (int j = 0; j < 4; j++)
#pragma unroll
            for (int k = 0; k < 4; k++) acc[i][j][k] = 0.f;

    const int a_row_l = (lane & 7) + ((lane >> 3) & 1) * 8;
    const int a_chk_l = lane >> 4;
    const int b_row_l = (lane & 7) + ((lane >> 4) & 1) * 8;
    const int b_chk_l = (lane >> 3) & 1;

    const int nch = K >> 5;
    load_tiles(sb, tid, gA0, gA1, gB0, lda, ldb, 0);

    for (int c = 0; c < nch; c++) {
        if (c + 1 < nch) {
            load_tiles(sb + ((c + 1) & 1) * STAGE_BYTES, tid, gA0, gA1, gB0,
                       lda, ldb, (c + 1) * 32);
            asm volatile("cp.async.wait_group 1;" ::: "memory");
        } else {
            asm volatile("cp.async.wait_group 0;" ::: "memory");
        }
        __syncthreads();
        const uint32_t s0 = sb + (c & 1) * STAGE_BYTES;
#pragma unroll
        for (int ks = 0; ks < 2; ks++) {
            uint32_t a_hi[4][4], a_lo[4][4], b_hi[8];
#pragma unroll
            for (int mt = 0; mt < 4; mt++) {
                int row = wm * 64 + mt * 16 + a_row_l;
                uint32_t off = sw_off(row, ks * 2 + a_chk_l);
                ldsm4(a_hi[mt], s0 + off);
                ldsm4(a_lo[mt], s0 + 8192 + off);
            }
#pragma unroll
            for (int ntp = 0; ntp < 2; ntp++) {
                int row = wn * 32 + ntp * 16 + b_row_l;
                uint32_t off = sw_off(row, ks * 2 + b_chk_l);
                ldsm4(&b_hi[ntp * 4], s0 + 16384 + off);
            }
#pragma unroll
            for (int mt = 0; mt < 4; mt++)
#pragma unroll
                for (int nt = 0; nt < 4; nt++) {
                    int bi = (nt >> 1) * 4 + (nt & 1) * 2;
                    mma_f16(acc[mt][nt], a_hi[mt], b_hi[bi], b_hi[bi + 1]);
                    mma_f16(acc[mt][nt], a_lo[mt], b_hi[bi], b_hi[bi + 1]);
                }
        }
        __syncthreads();
    }

    const int r_l = lane >> 2, c_l = (lane & 3) * 2;
#pragma unroll
    for (int mt = 0; mt < 4; mt++) {
#pragma unroll
        for (int nt = 0; nt < 4; nt++) {
            int row0 = bm + wm * 64 + mt * 16 + r_l;
            int col  = bn + wn * 32 + nt * 8 + c_l;
            float v0 = acc[mt][nt][0], v1 = acc[mt][nt][1];
            float v2 = acc[mt][nt][2], v3 = acc[mt][nt][3];
            if (OUT_MODE == 0) {
                if (bias) { v0 += bias[col]; v1 += bias[col + 1]; v2 += bias[col]; v3 += bias[col + 1]; }
                float* p0 = C + z * sCz + (size_t)row0 * ldc + col;
                float* p1 = C + z * sCz + (size_t)(row0 + 8) * ldc + col;
                p0[0] = v0; p0[1] = v1;
                p1[0] = v2; p1[1] = v3;
            } else if (OUT_MODE == 1) {
                h16 h0 = __float2half(v0), h1 = __float2half(v1);
                h16 h2 = __float2half(v2), h3 = __float2half(v3);
                h16* hp0 = Chi + z * sCz + (size_t)row0 * ldc + col;
                h16* hp1 = Chi + z * sCz + (size_t)(row0 + 8) * ldc + col;
                h16* lp0 = Clo + z * sCz + (size_t)row0 * ldc + col;
                h16* lp1 = Clo + z * sCz + (size_t)(row0 + 8) * ldc + col;
                hp0[0] = h0; hp0[1] = h1; hp1[0] = h2; hp1[1] = h3;
                lp0[0] = __float2half(v0 - __half2float(h0));
                lp0[1] = __float2half(v1 - __half2float(h1));
                lp1[0] = __float2half(v2 - __half2float(h2));
                lp1[1] = __float2half(v3 - __half2float(h3));
            } else {
                h16* hp0 = Chi + z * sCz + (size_t)row0 * ldc + col;
                h16* hp1 = Chi + z * sCz + (size_t)(row0 + 8) * ldc + col;
                hp0[0] = __float2half(v0); hp0[1] = __float2half(v1);
                hp1[0] = __float2half(v2); hp1[1] = __float2half(v3);
            }
        }
    }
}

// ================= 1-term kernel (A hi, B hi): stage Ahi|Bhi = 16KB =================
#define STAGE1_BYTES 16384
#define MMA1_SMEM (2*STAGE1_BYTES)

__device__ __forceinline__ void load_tiles_1t(uint32_t sbase, int tid,
    const h16* g0, const h16* g1, int lda, int ldb, int k0)
{
    const h16* gp[2] = {g0, g1};
#pragma unroll
    for (int i = 0; i < 4; i++) {
        int q = tid + i * 256;
        int tile = q >> 9, r = (q >> 2) & 127, c = q & 3;
        int ld = (tile == 0) ? lda : ldb;
        const h16* src = gp[tile] + (size_t)r * ld + k0 + c * 8;
        uint32_t so = sbase + tile * 8192 + sw_off(r, c);
        cp16(so, src);
    }
    asm volatile("cp.async.commit_group;" ::: "memory");
}

// OUT_MODE 1: h16 hi/lo outputs
__global__ void __launch_bounds__(256)
mma_gemm_nt_1t(const h16* __restrict__ Ahi, int lda, size_t sAz,
               const h16* __restrict__ Bhi, int ldb, size_t sBz,
               h16* __restrict__ Chi, h16* __restrict__ Clo,
               int ldc, size_t sCz, int K)
{
    extern __shared__ char smem[];
    const uint32_t sb = smem_to_u32(smem);
    const int tid = threadIdx.x, lane = tid & 31, wid = tid >> 5;
    const int wm = wid & 1, wn = wid >> 1;
    const size_t z = blockIdx.z;
    const int bm = blockIdx.y * 128, bn = blockIdx.x * 128;

    const h16* gA0 = Ahi + z * sAz + (size_t)bm * lda;
    const h16* gB0 = Bhi + z * sBz + (size_t)bn * ldb;

    float acc[4][4][4];
#pragma unroll
    for (int i = 0; i < 4; i++)
#pragma unroll
        for (int j = 0; j < 4; j++)
#pragma unroll
            for (int k = 0; k < 4; k++) acc[i][j][k] = 0.f;

    const int a_row_l = (lane & 7) + ((lane >> 3) & 1) * 8;
    const int a_chk_l = lane >> 4;
    const int b_row_l = (lane & 7) + ((lane >> 4) & 1) * 8;
    const int b_chk_l = (lane >> 3) & 1;

    const int nch = K >> 5;
    load_tiles_1t(sb, tid, gA0, gB0, lda, ldb, 0);

    for (int c = 0; c < nch; c++) {
        if (c + 1 < nch) {
            load_tiles_1t(sb + ((c + 1) & 1) * STAGE1_BYTES, tid, gA0, gB0,
                          lda, ldb, (c + 1) * 32);
            asm volatile("cp.async.wait_group 1;" ::: "memory");
        } else {
            asm volatile("cp.async.wait_group 0;" ::: "memory");
        }
        __syncthreads();
        const uint32_t s0 = sb + (c & 1) * STAGE1_BYTES;
#pragma unroll
        for (int ks = 0; ks < 2; ks++) {
            uint32_t a_hi[4][4], b_hi[8];
#pragma unroll
            for (int mt = 0; mt < 4; mt++) {
                int row = wm * 64 + mt * 16 + a_row_l;
                ldsm4(a_hi[mt], s0 + sw_off(row, ks * 2 + a_chk_l));
            }
#pragma unroll
            for (int ntp = 0; ntp < 2; ntp++) {
                int row = wn * 32 + ntp * 16 + b_row_l;
                ldsm4(&b_hi[ntp * 4], s0 + 8192 + sw_off(row, ks * 2 + b_chk_l));
            }
#pragma unroll
            for (int mt = 0; mt < 4; mt++)
#pragma unroll
                for (int nt = 0; nt < 4; nt++) {
                    int bi = (nt >> 1) * 4 + (nt & 1) * 2;
                    mma_f16(acc[mt][nt], a_hi[mt], b_hi[bi], b_hi[bi + 1]);
                }
        }
        __syncthreads();
    }

    const int r_l = lane >> 2, c_l = (lane & 3) * 2;
#pragma unroll
    for (int mt = 0; mt < 4; mt++) {
#pragma unroll
        for (int nt = 0; nt < 4; nt++) {
            int row0 = bm + wm * 64 + mt * 16 + r_l;
            int col  = bn + wn * 32 + nt * 8 + c_l;
            float v0 = acc[mt][nt][0], v1 = acc[mt][nt][1];
            float v2 = acc[mt][nt][2], v3 = acc[mt][nt][3];
            h16 h0 = __float2half(v0), h1 = __float2half(v1);
            h16 h2 = __float2half(v2), h3 = __float2half(v3);
            h16* hp0 = Chi + z * sCz + (size_t)row0 * ldc + col;
            h16* hp1 = Chi + z * sCz + (size_t)(row0 + 8) * ldc + col;
            h16* lp0 = Clo + z * sCz + (size_t)row0 * ldc + col;
            h16* lp1 = Clo + z * sCz + (size_t)(row0 + 8) * ldc + col;
            hp0[0] = h0; hp0[1] = h1; hp1[0] = h2; hp1[1] = h3;
            lp0[0] = __float2half(v0 - __half2float(h0));
            lp0[1] = __float2half(v1 - __half2float(h1));
            lp1[0] = __float2half(v2 - __half2float(h2));
            lp1[1] = __float2half(v3 - __half2float(h3));
        }
    }
}

// ================= small kernels =================
__global__ void split5_kernel(
    const float* __restrict__ s0, const float* __restrict__ s1, const float* __restrict__ s2,
    const float* __restrict__ s3, const float* __restrict__ s4,
    h16* __restrict__ h0, h16* __restrict__ h1, h16* __restrict__ h2,
    h16* __restrict__ h3, h16* __restrict__ h4,
    h16* __restrict__ l0, h16* __restrict__ l3)
{
    int i4 = blockIdx.x * blockDim.x + threadIdx.x;
    int zz = blockIdx.y;
    const float* src = (zz == 0) ? s0 : (zz == 1) ? s1 : (zz == 2) ? s2 : (zz == 3) ? s3 : s4;
    h16* hi = (zz == 0) ? h0 : (zz == 1) ? h1 : (zz == 2) ? h2 : (zz == 3) ? h3 : h4;
    h16* lo = (zz == 0) ? l0 : (zz == 3) ? l3 : (h16*)0;
    float4 v = *((const float4*)src + i4);
    h16 a = __float2half(v.x), b = __float2half(v.y);
    h16 c = __float2half(v.z), d = __float2half(v.w);
    uint2 hv;
    hv.x = (uint32_t)__half_as_ushort(a) | ((uint32_t)__half_as_ushort(b) << 16);
    hv.y = (uint32_t)__half_as_ushort(c) | ((uint32_t)__half_as_ushort(d) << 16);
    *((uint2*)hi + i4) = hv;
    if (lo) {
        uint2 lv;
        lv.x = pack_h16x2(v.x - __half2float(a), v.y - __half2float(b));
        lv.y = pack_h16x2(v.z - __half2float(c), v.w - __half2float(d));
        *((uint2*)lo + i4) = lv;
    }
}

__global__ void fiber_gemm(const float* __restrict__ x, const float* __restrict__ fw,
                           float* __restrict__ fpart)
{
    __shared__ float Xs[64][68];
    __shared__ float Fs[64][68];
    const int ksplit = blockIdx.x;
    const int rb = blockIdx.y * 64;
    const int t = threadIdx.x;
    const int rt = t & 15, ct = t >> 4;
    float acc[4][4] = {};
    for (int sub = 0; sub < 2; sub++) {
        const int k0 = ksplit * 128 + sub * 64;
        __syncthreads();
        for (int i = t; i < 1024; i += 256) {
            int row = i >> 4, kq = (i & 15) * 4;
            float4 v = *(const float4*)&x[(size_t)(rb + row) * DM + k0 + kq];
            Xs[kq][row] = v.x; Xs[kq+1][row] = v.y; Xs[kq+2][row] = v.z; Xs[kq+3][row] = v.w;
            float4 w = *(const float4*)&fw[(size_t)row * DM + k0 + kq];
            Fs[kq][row] = w.x; Fs[kq+1][row] = w.y; Fs[kq+2][row] = w.z; Fs[kq+3][row] = w.w;
        }
        __syncthreads();
#pragma unroll 16
        for (int k = 0; k < 64; k++) {
            float a[4], b[4];
#pragma unroll
            for (int i = 0; i < 4; i++) a[i] = Xs[k][rt*4 + i];
#pragma unroll
            for (int j = 0; j < 4; j++) b[j] = Fs[k][ct*4 + j];
#pragma unroll
            for (int i = 0; i < 4; i++)
#pragma unroll
                for (int j = 0; j < 4; j++) acc[i][j] = fmaf(a[i], b[j], acc[i][j]);
        }
    }
    float* dst = fpart + (size_t)ksplit * S_ * F_;
#pragma unroll
    for (int i = 0; i < 4; i++)
#pragma unroll
        for (int j = 0; j < 4; j++)
            dst[(size_t)(rb + rt*4 + i) * F_ + ct*4 + j] = acc[i][j];
}

__global__ void fiber_reduce(const float* __restrict__ fpart, const float* __restrict__ fb,
                             float* __restrict__ fp)
{
    int i = blockIdx.x * blockDim.x + threadIdx.x;
    if (i >= S_ * F_) return;
    float a = fb[i & 63];
#pragma unroll
    for (int s = 0; s < 16; s++) a += fpart[(size_t)s * S_ * F_ + i];
    fp[i] = a;
}

__global__ void fp_stats_kernel(const float* __restrict__ fp,
                                float* __restrict__ fpsum, float* __restrict__ mi)
{
    __shared__ float sm[256];
    int t = threadIdx.x;
    int f = t & 63, c = t >> 6;
    float s = 0.f;
    for (int i = c; i < S_; i += 4) s += fp[i*F_ + f];
    sm[t] = s; __syncthreads();
    if (c == 0) {
        float tot = sm[f] + sm[64+f] + sm[128+f] + sm[192+f];
        fpsum[f] = tot;
        mi[f] = tot / (float)S_;
    }
}

__global__ void mlp_metric_kernel(const float* __restrict__ mi,
                                  const float* __restrict__ fm1w, const float* __restrict__ fm1b,
                                  const float* __restrict__ fm2w, const float* __restrict__ fm2b,
                                  float* __restrict__ metric)
{
    __shared__ float smi[F_];
    __shared__ float hid[F_/2];
    __shared__ float raw[F_];
    int t = threadIdx.x;
    smi[t] = mi[t];
    __syncthreads();
    if (t < F_/2) {
        float a = fm1b[t];
        for (int f = 0; f < F_; f++) a = fmaf(smi[f], fm1w[t*F_ + f], a);
        hid[t] = fmaxf(a, 0.f);
    }
    __syncthreads();
    {
        float a = fm2b[t];
        for (int j = 0; j < F_/2; j++) a = fmaf(hid[j], fm2w[t*(F_/2) + j], a);
        raw[t] = a;
    }
    __syncthreads();
    for (int b = 0; b < F_; b++)
        metric[t*F_ + b] = raw[t]*raw[b] + ((t == b) ? 0.1f : 0.f);
}

__global__ void compute_g_kernel(const float* __restrict__ fp,
                                 const float* __restrict__ metric,
                                 float* __restrict__ g)
{
    __shared__ float sm[F_*F_];
    for (int i = threadIdx.x; i < F_*F_; i += blockDim.x) sm[i] = metric[i];
    __syncthreads();
    int t = threadIdx.x;
    int f = t & 63, r = t >> 6;
    int i = blockIdx.x*4 + r;
    const float* fr = fp + (size_t)i*F_;
    float a = 0.f;
#pragma unroll
    for (int k = 0; k < F_; k++) a = fmaf(fr[k], sm[k*F_ + f], a);
    g[(size_t)i*F_ + f] = a;
}

__global__ void curv_kernel(const float* __restrict__ fp, const float* __restrict__ cm,
                            float* __restrict__ curv, float* __restrict__ curvb)
{
    int j = blockIdx.x*blockDim.x + threadIdx.x;
    if (j >= S_) return;
    float a = 0.f;
#pragma unroll
    for (int f = 0; f < F_; f++) a = fmaf(fp[(size_t)j*F_ + f], cm[f*(F_+1)], a);
    curv[j] = a;
    curvb[j] = COUPLING * a;
}

__global__ void pack_aug_kernel(const float* __restrict__ Q, const float* __restrict__ Km,
                                const float* __restrict__ g, const float* __restrict__ fp,
                                h16* __restrict__ Qhi, h16* __restrict__ Qlo,
                                h16* __restrict__ Khi)
{
    int idx = blockIdx.x*blockDim.x + threadIdx.x;
    if (idx >= H_*S_*AUG) return;
    int d = idx % AUG;
    int i = (idx / AUG) % S_;
    int h = idx / (AUG*S_);
    float qv, kv;
    if (d < DK) {
        qv = Q[(size_t)i*DM + h*DK + d] * INV_SCALE;
        kv = Km[(size_t)i*DM + h*DK + d];
    } else {
        qv = COUPLING * g[(size_t)i*F_ + (d-DK)];
        kv = fp[(size_t)i*F_ + (d-DK)];
    }
    h16 qh = __float2half(qv);
    Qhi[idx] = qh;
    Qlo[idx] = __float2half(qv - __half2float(qh));
    Khi[idx] = __float2half(kv);
}

__global__ void softmax_kernel(const float* __restrict__ P, h16* __restrict__ Phi)
{
    size_t row = blockIdx.x;
    const float* p = P + row * (size_t)S_;
    int t = threadIdx.x;
    float vals[8];
    float4 v0 = *(const float4*)(p + t*8);
    float4 v1 = *(const float4*)(p + t*8 + 4);
    vals[0]=v0.x; vals[1]=v0.y; vals[2]=v0.z; vals[3]=v0.w;
    vals[4]=v1.x; vals[5]=v1.y; vals[6]=v1.z; vals[7]=v1.w;
    float m = vals[0];
#pragma unroll
    for (int i = 1; i < 8; i++) m = fmaxf(m, vals[i]);
    __shared__ float red[8];
    for (int o = 16; o; o >>= 1) m = fmaxf(m, __shfl_xor_sync(~0u, m, o));
    if ((t & 31) == 0) red[t>>5] = m;
    __syncthreads();
    m = red[0];
#pragma unroll
    for (int i = 1; i < 8; i++) m = fmaxf(m, red[i]);
    float s = 0.f;
#pragma unroll
    for (int i = 0; i < 8; i++) { vals[i] = __expf(vals[i] - m); s += vals[i]; }
    for (int o = 16; o; o >>= 1) s += __shfl_xor_sync(~0u, s, o);
    __shared__ float red2[8];
    if ((t & 31) == 0) red2[t>>5] = s;
    __syncthreads();
    s = red2[0];
#pragma unroll
    for (int i = 1; i < 8; i++) s += red2[i];
    float inv = 1.0f / s;
    uint4 hv;
    hv.x = pack_h16x2(vals[0]*inv, vals[1]*inv);
    hv.y = pack_h16x2(vals[2]*inv, vals[3]*inv);
    hv.z = pack_h16x2(vals[4]*inv, vals[5]*inv);
    hv.w = pack_h16x2(vals[6]*inv, vals[7]*inv);
    *(uint4*)(Phi + row * (size_t)S_ + t*8) = hv;
}

__global__ void scalar_kernel(const float* __restrict__ g, const float* __restrict__ fpsum,
                              const float* __restrict__ curv, float* __restrict__ out0,
                              float* __restrict__ out1)
{
    __shared__ float sm[256];
    __shared__ float sc[256];
    int t = threadIdx.x;
    int f = t & 63, c = t >> 6;
    float s = 0.f;
    for (int i = c; i < S_; i += 4) s += g[i*F_ + f];
    sm[t] = s; __syncthreads();
    float tot = 0.f;
    if (c == 0) tot = sm[f] + sm[64+f] + sm[128+f] + sm[192+f];
    __syncthreads();
    sm[t] = (c == 0) ? tot * fpsum[f] : 0.f;
    float cs = 0.f;
    for (int j = t; j < S_; j += 256) cs += curv[j];
    sc[t] = cs;
    __syncthreads();
    if (t == 0) {
        float a = 0.f, b = 0.f;
        for (int i = 0; i < 64; i++) a += sm[i];
        for (int i = 0; i < 256; i++) b += sc[i];
        float val = a / ((float)S_ * (float)S_) + b / (float)S_;
        *out0 = val;
        if (out1) *out1 = val;
    }
}

// ================= launch =================
extern "C" void kernel_launch(void* const* d_in, const int* in_sizes, int n_in,
                              void* d_out, int out_size)
{
    const float* x    = (const float*)d_in[0];
    const float* wq   = (const float*)d_in[2];
    const float* wk   = (const float*)d_in[3];
    const float* wv   = (const float*)d_in[4];
    const float* wo_w = (const float*)d_in[5];
    const float* wo_b = (const float*)d_in[6];
    const float* fw   = (const float*)d_in[7];
    const float* fb   = (const float*)d_in[8];
    const float* fm1w = (const float*)d_in[9];
    const float* fm1b = (const float*)d_in[10];
    const float* fm2w = (const float*)d_in[11];
    const float* fm2b = (const float*)d_in[12];
    const float* cm   = (const float*)d_in[13];
    float* out = (float*)d_out;

    h16 *xhi,*xlo,*wqkhi,*wvhi,*wvlo,*wohi;
    h16 *Vthi,*Qahi,*Qalo,*Kahi,*Phi,*athi,*atlo;
    float *QK,*fp,*fpart,*g,*metric,*mi,*fpsum,*curv,*curvb,*scores;
    cudaGetSymbolAddress((void**)&xhi, d_xhi);     cudaGetSymbolAddress((void**)&xlo, d_xlo);
    cudaGetSymbolAddress((void**)&wqkhi, d_wqkhi);
    cudaGetSymbolAddress((void**)&wvhi, d_wvhi);   cudaGetSymbolAddress((void**)&wvlo, d_wvlo);
    cudaGetSymbolAddress((void**)&wohi, d_wohi);
    cudaGetSymbolAddress((void**)&Vthi, d_Vthi);
    cudaGetSymbolAddress((void**)&Qahi, d_Qahi);   cudaGetSymbolAddress((void**)&Qalo, d_Qalo);
    cudaGetSymbolAddress((void**)&Kahi, d_Kahi);
    cudaGetSymbolAddress((void**)&Phi, d_Phi);
    cudaGetSymbolAddress((void**)&athi, d_attnhi); cudaGetSymbolAddress((void**)&atlo, d_attnlo);
    cudaGetSymbolAddress((void**)&QK, d_QK);
    cudaGetSymbolAddress((void**)&fp, d_fp);       cudaGetSymbolAddress((void**)&fpart, d_fpart);
    cudaGetSymbolAddress((void**)&g, d_g);
    cudaGetSymbolAddress((void**)&metric, d_metric); cudaGetSymbolAddress((void**)&mi, d_mi);
    cudaGetSymbolAddress((void**)&fpsum, d_fpsum);   cudaGetSymbolAddress((void**)&curv, d_curv);
    cudaGetSymbolAddress((void**)&curvb, d_curvb);   cudaGetSymbolAddress((void**)&scores, d_scores);

    cudaFuncSetAttribute(mma_gemm_nt<0>, cudaFuncAttributeMaxDynamicSharedMemorySize, MMA_SMEM);
    cudaFuncSetAttribute(mma_gemm_nt<1>, cudaFuncAttributeMaxDynamicSharedMemorySize, MMA_SMEM);
    cudaFuncSetAttribute(mma_gemm_nt<2>, cudaFuncAttributeMaxDynamicSharedMemorySize, MMA_SMEM);
    cudaFuncSetAttribute(mma_gemm_nt_1t, cudaFuncAttributeMaxDynamicSharedMemorySize, MMA1_SMEM);

    const int NDM = S_*DM;
    // 0) fp16 splits: hi for all 5, lo only for x and wv
    split5_kernel<<<dim3(NDM/1024, 5), 256>>>(
        x, wq, wk, wv, wo_w,
        xhi, wqkhi, wqkhi + (size_t)DM*DM, wvhi, wohi,
        xlo, wvlo);

    // 1) Q and K projections batched: z=2 (fp32 out)
    mma_gemm_nt<0><<<dim3(16,16,2), 256, MMA_SMEM>>>(
        xhi, xlo, DM, 0, wqkhi, DM, (size_t)DM*DM,
        QK, nullptr, nullptr, DM, (size_t)S_*DM, DM, nullptr);
    // 2) Vt[d][s] = wv @ x^T (h16 hi only; A=wv corrected)
    mma_gemm_nt<2><<<dim3(16,16,1), 256, MMA_SMEM>>>(wvhi, wvlo, DM, 0, xhi, DM, 0,
                                                     nullptr, Vthi, nullptr, S_, 0, DM, nullptr);
    // 3) fiber projection (deterministic split-K)
    fiber_gemm<<<dim3(16, 32), 256>>>(x, fw, fpart);
    fiber_reduce<<<S_*F_/256, 256>>>(fpart, fb, fp);
    // 4) stats -> MLP -> metric -> g -> curv
    fp_stats_kernel<<<1, 256>>>(fp, fpsum, mi);
    mlp_metric_kernel<<<1, 64>>>(mi, fm1w, fm1b, fm2w, fm2b, metric);
    compute_g_kernel<<<S_/4, 256>>>(fp, metric, g);
    curv_kernel<<<S_/256, 256>>>(fp, cm, curv, curvb);
    // 5) pack augmented Q (hi+lo) / K (hi)
    pack_aug_kernel<<<(H_*S_*AUG)/256, 256>>>(QK, QK + (size_t)S_*DM, g, fp,
                                              Qahi, Qalo, Kahi);
    // 6) scores = Qaug @ Kaug^T + 0.1*curv[col] (K=192, batched heads)
    mma_gemm_nt<0><<<dim3(16,16,H_), 256, MMA_SMEM>>>(
        Qahi, Qalo, AUG, (size_t)S_*AUG, Kahi, AUG, (size_t)S_*AUG,
        scores, nullptr, nullptr, S_, (size_t)S_*S_, AUG, curvb);
    // 7) softmax -> P hi only
    softmax_kernel<<<H_*S_, 256>>>(scores, Phi);
    // 8) attn = P[h] @ Vt[h]^T (1-term fp16, h16 hi/lo out for out-proj correction)
    mma_gemm_nt_1t<<<dim3(1,16,H_), 256, MMA1_SMEM>>>(
        Phi, S_, (size_t)S_*S_, Vthi, S_, (size_t)DK*S_,
        athi, atlo, DM, (size_t)DK, S_);
    // 9) out = attn @ wo^T + wo_b (fp32 -> d_out)
    mma_gemm_nt<0><<<dim3(16,16,1), 256, MMA_SMEM>>>(athi, atlo, DM, 0, wohi, DM, 0,
                                                     out, nullptr, nullptr, DM, 0, DM, wo_b);
    // 10) ci.mean() scalar
    if (out_size > S_*DM) {
        float* o0 = out + (size_t)S_*DM;
        float* o1 = out + (size_t)(out_size - 1);
        scalar_kernel<<<1, 256>>>(g, fpsum, curv, o0, (o1 != o0) ? o1 : nullptr);
    }
}

// round 15
// speedup vs baseline: 1.5724x; 1.1014x over previous
#include <cuda_runtime.h>
#include <cuda_fp16.h>
#include <cstdint>
#include <math.h>

#define S_  2048
#define DM  2048
#define H_  16
#define DK  128
#define F_  64
#define AUG 192
#define INV_SCALE (1.0f/11.313708498984761f)
#define COUPLING 0.1f

typedef __half h16;

// ---------------- device scratch (256B-aligned) ----------------
__device__ __align__(256) h16   d_xhi[S_*DM],  d_xlo[S_*DM];
__device__ __align__(256) h16   d_wqkhi[2*DM*DM];                     // wq then wk (hi only)
__device__ __align__(256) h16   d_wvhi[DM*DM];
__device__ __align__(256) h16   d_wohi[DM*DM];
__device__ __align__(256) float d_QK[2*S_*DM];                        // Q then K (fp32)
__device__ __align__(256) h16   d_Vthi[DM*S_];                        // V transposed [d][s]
__device__ __align__(256) float d_fp[S_*F_];
__device__ __align__(256) float d_fpart[16*S_*F_];
__device__ __align__(256) float d_g[S_*F_];
__device__ __align__(256) float d_metric[F_*F_];
__device__ __align__(256) float d_mi[F_];
__device__ __align__(256) float d_fpsum[F_];
__device__ __align__(256) float d_curv[S_];
__device__ __align__(256) float d_curvb[S_];
__device__ __align__(256) h16   d_Qahi[H_*S_*AUG], d_Qalo[H_*S_*AUG];
__device__ __align__(256) h16   d_Kahi[H_*S_*AUG];
__device__ __align__(256) float d_scores[H_*S_*S_];
__device__ __align__(256) h16   d_Phi[H_*S_*S_];
__device__ __align__(256) h16   d_attnhi[S_*DM];
// ================= portable-ISA helpers =================
__device__ __forceinline__ uint32_t smem_to_u32(const void* p) {
    uint32_t a;
    asm("{ .reg .u64 t; cvta.to.shared.u64 t, %1; cvt.u32.u64 %0, t; }" : "=r"(a) : "l"(p));
    return a;
}
__device__ __forceinline__ void cp16(uint32_t saddr, const void* g) {
    asm volatile("cp.async.cg.shared.global [%0], [%1], 16;" :: "r"(saddr), "l"(g));
}
__device__ __forceinline__ void ldsm4(uint32_t* r, uint32_t a) {
    asm volatile("ldmatrix.sync.aligned.m8n8.x4.shared.b16 {%0,%1,%2,%3}, [%4];"
                 : "=r"(r[0]), "=r"(r[1]), "=r"(r[2]), "=r"(r[3]) : "r"(a));
}
__device__ __forceinline__ void mma_f16(float* c, const uint32_t* a, uint32_t b0, uint32_t b1) {
    asm volatile("mma.sync.aligned.m16n8k16.row.col.f32.f16.f16.f32 "
                 "{%0,%1,%2,%3}, {%4,%5,%6,%7}, {%8,%9}, {%0,%1,%2,%3};"
                 : "+f"(c[0]), "+f"(c[1]), "+f"(c[2]), "+f"(c[3])
                 : "r"(a[0]), "r"(a[1]), "r"(a[2]), "r"(a[3]), "r"(b0), "r"(b1));
}
__device__ __forceinline__ uint32_t pack_h16x2(float lo, float hi) {
    unsigned short l = __half_as_ushort(__float2half(lo));
    unsigned short h = __half_as_ushort(__float2half(hi));
    return (uint32_t)l | ((uint32_t)h << 16);
}

__device__ __forceinline__ uint32_t sw_off(int row, int chunk) {
    return (uint32_t)(row * 64 + ((chunk ^ ((row >> 1) & 3)) << 4));
}

// ================= 2-term kernel (A hi+lo, B hi): stage Ahi|Alo|Bhi = 24KB =================
#define STAGE_BYTES 24576
#define MMA_SMEM (2*STAGE_BYTES)

__device__ __forceinline__ void load_tiles(uint32_t sbase, int tid,
    const h16* g0, const h16* g1, const h16* g2,
    int lda, int ldb, int k0)
{
    const h16* gp[3] = {g0, g1, g2};
#pragma unroll
    for (int i = 0; i < 6; i++) {
        int q = tid + i * 256;
        int tile = q >> 9, r = (q >> 2) & 127, c = q & 3;
        int ld = (tile < 2) ? lda : ldb;
        const h16* src = gp[tile] + (size_t)r * ld + k0 + c * 8;
        uint32_t so = sbase + tile * 8192 + sw_off(r, c);
        cp16(so, src);
    }
    asm volatile("cp.async.commit_group;" ::: "memory");
}

// OUT_MODE 0: fp32 C (+bias[col])
template<int OUT_MODE>
__global__ void __launch_bounds__(256)
mma_gemm_nt(const h16* __restrict__ Ahi, const h16* __restrict__ Alo, int lda, size_t sAz,
            const h16* __restrict__ Bhi, int ldb, size_t sBz,
            float* __restrict__ C, int ldc, size_t sCz, int K, const float* __restrict__ bias)
{
    extern __shared__ char smem[];
    const uint32_t sb = smem_to_u32(smem);
    const int tid = threadIdx.x, lane = tid & 31, wid = tid >> 5;
    const int wm = wid & 1, wn = wid >> 1;
    const size_t z = blockIdx.z;
    const int bm = blockIdx.y * 128, bn = blockIdx.x * 128;

    const h16* gA0 = Ahi + z * sAz + (size_t)bm * lda;
    const h16* gA1 = Alo + z * sAz + (size_t)bm * lda;
    const h16* gB0 = Bhi + z * sBz + (size_t)bn * ldb;

    float acc[4][4][4];
#pragma unroll
    for (int i = 0; i < 4; i++)
#pragma unroll
        for (int j = 0; j < 4; j++)
#pragma unroll
            for (int k = 0; k < 4; k++) acc[i][j][k] = 0.f;

    const int a_row_l = (lane & 7) + ((lane >> 3) & 1) * 8;
    const int a_chk_l = lane >> 4;
    const int b_row_l = (lane & 7) + ((lane >> 4) & 1) * 8;
    const int b_chk_l = (lane >> 3) & 1;

    const int nch = K >> 5;
    load_tiles(sb, tid, gA0, gA1, gB0, lda, ldb, 0);

    for (int c = 0; c < nch; c++) {
        if (c + 1 < nch) {
            load_tiles(sb + ((c + 1) & 1) * STAGE_BYTES, tid, gA0, gA1, gB0,
                       lda, ldb, (c + 1) * 32);
            asm volatile("cp.async.wait_group 1;" ::: "memory");
        } else {
            asm volatile("cp.async.wait_group 0;" ::: "memory");
        }
        __syncthreads();
        const uint32_t s0 = sb + (c & 1) * STAGE_BYTES;
#pragma unroll
        for (int ks = 0; ks < 2; ks++) {
            uint32_t a_hi[4][4], a_lo[4][4], b_hi[8];
#pragma unroll
            for (int mt = 0; mt < 4; mt++) {
                int row = wm * 64 + mt * 16 + a_row_l;
                uint32_t off = sw_off(row, ks * 2 + a_chk_l);
                ldsm4(a_hi[mt], s0 + off);
                ldsm4(a_lo[mt], s0 + 8192 + off);
            }
#pragma unroll
            for (int ntp = 0; ntp < 2; ntp++) {
                int row = wn * 32 + ntp * 16 + b_row_l;
                uint32_t off = sw_off(row, ks * 2 + b_chk_l);
                ldsm4(&b_hi[ntp * 4], s0 + 16384 + off);
            }
#pragma unroll
            for (int mt = 0; mt < 4; mt++)
#pragma unroll
                for (int nt = 0; nt < 4; nt++) {
                    int bi = (nt >> 1) * 4 + (nt & 1) * 2;
                    mma_f16(acc[mt][nt], a_hi[mt], b_hi[bi], b_hi[bi + 1]);
                    mma_f16(acc[mt][nt], a_lo[mt], b_hi[bi], b_hi[bi + 1]);
                }
        }
        __syncthreads();
    }

    const int r_l = lane >> 2, c_l = (lane & 3) * 2;
#pragma unroll
    for (int mt = 0; mt < 4; mt++) {
#pragma unroll
        for (int nt = 0; nt < 4; nt++) {
            int row0 = bm + wm * 64 + mt * 16 + r_l;
            int col  = bn + wn * 32 + nt * 8 + c_l;
            float v0 = acc[mt][nt][0], v1 = acc[mt][nt][1];
            float v2 = acc[mt][nt][2], v3 = acc[mt][nt][3];
            if (bias) { v0 += bias[col]; v1 += bias[col + 1]; v2 += bias[col]; v3 += bias[col + 1]; }
            float* p0 = C + z * sCz + (size_t)row0 * ldc + col;
            float* p1 = C + z * sCz + (size_t)(row0 + 8) * ldc + col;
            p0[0] = v0; p0[1] = v1;
            p1[0] = v2; p1[1] = v3;
        }
    }
}

// ================= 1-term kernel (A hi, B hi): stage Ahi|Bhi = 16KB =================
#define STAGE1_BYTES 16384
#define MMA1_SMEM (2*STAGE1_BYTES)

__device__ __forceinline__ void load_tiles_1t(uint32_t sbase, int tid,
    const h16* g0, const h16* g1, int lda, int ldb, int k0)
{
    const h16* gp[2] = {g0, g1};
#pragma unroll
    for (int i = 0; i < 4; i++) {
        int q = tid + i * 256;
        int tile = q >> 9, r = (q >> 2) & 127, c = q & 3;
        int ld = (tile == 0) ? lda : ldb;
        const h16* src = gp[tile] + (size_t)r * ld + k0 + c * 8;
        uint32_t so = sbase + tile * 8192 + sw_off(r, c);
        cp16(so, src);
    }
    asm volatile("cp.async.commit_group;" ::: "memory");
}

// OUT_MODE 0: fp32 C (+bias[col]);  OUT_MODE 2: h16 hi only.
template<int OUT_MODE>
__global__ void __launch_bounds__(256)
mma_gemm_nt_1t(const h16* __restrict__ Ahi, int lda, size_t sAz,
               const h16* __restrict__ Bhi, int ldb, size_t sBz,
               float* __restrict__ C, h16* __restrict__ Chi,
               int ldc, size_t sCz, int K, const float* __restrict__ bias)
{
    extern __shared__ char smem[];
    const uint32_t sb = smem_to_u32(smem);
    const int tid = threadIdx.x, lane = tid & 31, wid = tid >> 5;
    const int wm = wid & 1, wn = wid >> 1;
    const size_t z = blockIdx.z;
    const int bm = blockIdx.y * 128, bn = blockIdx.x * 128;

    const h16* gA0 = Ahi + z * sAz + (size_t)bm * lda;
    const h16* gB0 = Bhi + z * sBz + (size_t)bn * ldb;

    float acc[4][4][4];
#pragma unroll
    for (int i = 0; i < 4; i++)
#pragma unroll
        for (int j = 0; j < 4; j++)
#pragma unroll
            for (int k = 0; k < 4; k++) acc[i][j][k] = 0.f;

    const int a_row_l = (lane & 7) + ((lane >> 3) & 1) * 8;
    const int a_chk_l = lane >> 4;
    const int b_row_l = (lane & 7) + ((lane >> 4) & 1) * 8;
    const int b_chk_l = (lane >> 3) & 1;

    const int nch = K >> 5;
    load_tiles_1t(sb, tid, gA0, gB0, lda, ldb, 0);

    for (int c = 0; c < nch; c++) {
        if (c + 1 < nch) {
            load_tiles_1t(sb + ((c + 1) & 1) * STAGE1_BYTES, tid, gA0, gB0,
                          lda, ldb, (c + 1) * 32);
            asm volatile("cp.async.wait_group 1;" ::: "memory");
        } else {
            asm volatile("cp.async.wait_group 0;" ::: "memory");
        }
        __syncthreads();
        const uint32_t s0 = sb + (c & 1) * STAGE1_BYTES;
#pragma unroll
        for (int ks = 0; ks < 2; ks++) {
            uint32_t a_hi[4][4], b_hi[8];
#pragma unroll
            for (int mt = 0; mt < 4; mt++) {
                int row = wm * 64 + mt * 16 + a_row_l;
                ldsm4(a_hi[mt], s0 + sw_off(row, ks * 2 + a_chk_l));
            }
#pragma unroll
            for (int ntp = 0; ntp < 2; ntp++) {
                int row = wn * 32 + ntp * 16 + b_row_l;
                ldsm4(&b_hi[ntp * 4], s0 + 8192 + sw_off(row, ks * 2 + b_chk_l));
            }
#pragma unroll
            for (int mt = 0; mt < 4; mt++)
#pragma unroll
                for (int nt = 0; nt < 4; nt++) {
                    int bi = (nt >> 1) * 4 + (nt & 1) * 2;
                    mma_f16(acc[mt][nt], a_hi[mt], b_hi[bi], b_hi[bi + 1]);
                }
        }
        __syncthreads();
    }

    const int r_l = lane >> 2, c_l = (lane & 3) * 2;
#pragma unroll
    for (int mt = 0; mt < 4; mt++) {
#pragma unroll
        for (int nt = 0; nt < 4; nt++) {
            int row0 = bm + wm * 64 + mt * 16 + r_l;
            int col  = bn + wn * 32 + nt * 8 + c_l;
            float v0 = acc[mt][nt][0], v1 = acc[mt][nt][1];
            float v2 = acc[mt][nt][2], v3 = acc[mt][nt][3];
            if (OUT_MODE == 0) {
                if (bias) { v0 += bias[col]; v1 += bias[col + 1]; v2 += bias[col]; v3 += bias[col + 1]; }
                float* p0 = C + z * sCz + (size_t)row0 * ldc + col;
                float* p1 = C + z * sCz + (size_t)(row0 + 8) * ldc + col;
                p0[0] = v0; p0[1] = v1;
                p1[0] = v2; p1[1] = v3;
            } else {
                h16* hp0 = Chi + z * sCz + (size_t)row0 * ldc + col;
                h16* hp1 = Chi + z * sCz + (size_t)(row0 + 8) * ldc + col;
                hp0[0] = __float2half(v0); hp0[1] = __float2half(v1);
                hp1[0] = __float2half(v2); hp1[1] = __float2half(v3);
            }
        }
    }
}

// ================= small kernels =================
__global__ void split5_kernel(
    const float* __restrict__ s0, const float* __restrict__ s1, const float* __restrict__ s2,
    const float* __restrict__ s3, const float* __restrict__ s4,
    h16* __restrict__ h0, h16* __restrict__ h1, h16* __restrict__ h2,
    h16* __restrict__ h3, h16* __restrict__ h4,
    h16* __restrict__ l0)
{
    int i4 = blockIdx.x * blockDim.x + threadIdx.x;
    int zz = blockIdx.y;
    const float* src = (zz == 0) ? s0 : (zz == 1) ? s1 : (zz == 2) ? s2 : (zz == 3) ? s3 : s4;
    h16* hi = (zz == 0) ? h0 : (zz == 1) ? h1 : (zz == 2) ? h2 : (zz == 3) ? h3 : h4;
    h16* lo = (zz == 0) ? l0 : (h16*)0;
    float4 v = *((const float4*)src + i4);
    h16 a = __float2half(v.x), b = __float2half(v.y);
    h16 c = __float2half(v.z), d = __float2half(v.w);
    uint2 hv;
    hv.x = (uint32_t)__half_as_ushort(a) | ((uint32_t)__half_as_ushort(b) << 16);
    hv.y = (uint32_t)__half_as_ushort(c) | ((uint32_t)__half_as_ushort(d) << 16);
    *((uint2*)hi + i4) = hv;
    if (lo) {
        uint2 lv;
        lv.x = pack_h16x2(v.x - __half2float(a), v.y - __half2float(b));
        lv.y = pack_h16x2(v.z - __half2float(c), v.w - __half2float(d));
        *((uint2*)lo + i4) = lv;
    }
}

__global__ void fiber_gemm(const float* __restrict__ x, const float* __restrict__ fw,
                           float* __restrict__ fpart)
{
    __shared__ float Xs[64][68];
    __shared__ float Fs[64][68];
    const int ksplit = blockIdx.x;
    const int rb = blockIdx.y * 64;
    const int t = threadIdx.x;
    const int rt = t & 15, ct = t >> 4;
    float acc[4][4] = {};
    for (int sub = 0; sub < 2; sub++) {
        const int k0 = ksplit * 128 + sub * 64;
        __syncthreads();
        for (int i = t; i < 1024; i += 256) {
            int row = i >> 4, kq = (i & 15) * 4;
            float4 v = *(const float4*)&x[(size_t)(rb + row) * DM + k0 + kq];
            Xs[kq][row] = v.x; Xs[kq+1][row] = v.y; Xs[kq+2][row] = v.z; Xs[kq+3][row] = v.w;
            float4 w = *(const float4*)&fw[(size_t)row * DM + k0 + kq];
            Fs[kq][row] = w.x; Fs[kq+1][row] = w.y; Fs[kq+2][row] = w.z; Fs[kq+3][row] = w.w;
        }
        __syncthreads();
#pragma unroll 16
        for (int k = 0; k < 64; k++) {
            float a[4], b[4];
#pragma unroll
            for (int i = 0; i < 4; i++) a[i] = Xs[k][rt*4 + i];
#pragma unroll
            for (int j = 0; j < 4; j++) b[j] = Fs[k][ct*4 + j];
#pragma unroll
            for (int i = 0; i < 4; i++)
#pragma unroll
                for (int j = 0; j < 4; j++) acc[i][j] = fmaf(a[i], b[j], acc[i][j]);
        }
    }
    float* dst = fpart + (size_t)ksplit * S_ * F_;
#pragma unroll
    for (int i = 0; i < 4; i++)
#pragma unroll
        for (int j = 0; j < 4; j++)
            dst[(size_t)(rb + rt*4 + i) * F_ + ct*4 + j] = acc[i][j];
}

__global__ void fiber_reduce(const float* __restrict__ fpart, const float* __restrict__ fb,
                             float* __restrict__ fp)
{
    int i = blockIdx.x * blockDim.x + threadIdx.x;
    if (i >= S_ * F_) return;
    float a = fb[i & 63];
#pragma unroll
    for (int s = 0; s < 16; s++) a += fpart[(size_t)s * S_ * F_ + i];
    fp[i] = a;
}

__global__ void fp_stats_kernel(const float* __restrict__ fp,
                                float* __restrict__ fpsum, float* __restrict__ mi)
{
    __shared__ float sm[256];
    int t = threadIdx.x;
    int f = t & 63, c = t >> 6;
    float s = 0.f;
    for (int i = c; i < S_; i += 4) s += fp[i*F_ + f];
    sm[t] = s; __syncthreads();
    if (c == 0) {
        float tot = sm[f] + sm[64+f] + sm[128+f] + sm[192+f];
        fpsum[f] = tot;
        mi[f] = tot / (float)S_;
    }
}

__global__ void mlp_metric_kernel(const float* __restrict__ mi,
                                  const float* __restrict__ fm1w, const float* __restrict__ fm1b,
                                  const float* __restrict__ fm2w, const float* __restrict__ fm2b,
                                  float* __restrict__ metric)
{
    __shared__ float smi[F_];
    __shared__ float hid[F_/2];
    __shared__ float raw[F_];
    int t = threadIdx.x;
    smi[t] = mi[t];
    __syncthreads();
    if (t < F_/2) {
        float a = fm1b[t];
        for (int f = 0; f < F_; f++) a = fmaf(smi[f], fm1w[t*F_ + f], a);
        hid[t] = fmaxf(a, 0.f);
    }
    __syncthreads();
    {
        float a = fm2b[t];
        for (int j = 0; j < F_/2; j++) a = fmaf(hid[j], fm2w[t*(F_/2) + j], a);
        raw[t] = a;
    }
    __syncthreads();
    for (int b = 0; b < F_; b++)
        metric[t*F_ + b] = raw[t]*raw[b] + ((t == b) ? 0.1f : 0.f);
}

__global__ void compute_g_kernel(const float* __restrict__ fp,
                                 const float* __restrict__ metric,
                                 float* __restrict__ g)
{
    __shared__ float sm[F_*F_];
    for (int i = threadIdx.x; i < F_*F_; i += blockDim.x) sm[i] = metric[i];
    __syncthreads();
    int t = threadIdx.x;
    int f = t & 63, r = t >> 6;
    int i = blockIdx.x*4 + r;
    const float* fr = fp + (size_t)i*F_;
    float a = 0.f;
#pragma unroll
    for (int k = 0; k < F_; k++) a = fmaf(fr[k], sm[k*F_ + f], a);
    g[(size_t)i*F_ + f] = a;
}

__global__ void curv_kernel(const float* __restrict__ fp, const float* __restrict__ cm,
                            float* __restrict__ curv, float* __restrict__ curvb)
{
    int j = blockIdx.x*blockDim.x + threadIdx.x;
    if (j >= S_) return;
    float a = 0.f;
#pragma unroll
    for (int f = 0; f < F_; f++) a = fmaf(fp[(size_t)j*F_ + f], cm[f*(F_+1)], a);
    curv[j] = a;
    curvb[j] = COUPLING * a;
}

__global__ void pack_aug_kernel(const float* __restrict__ Q, const float* __restrict__ Km,
                                const float* __restrict__ g, const float* __restrict__ fp,
                                h16* __restrict__ Qhi, h16* __restrict__ Qlo,
                                h16* __restrict__ Khi)
{
    int idx = blockIdx.x*blockDim.x + threadIdx.x;
    if (idx >= H_*S_*AUG) return;
    int d = idx % AUG;
    int i = (idx / AUG) % S_;
    int h = idx / (AUG*S_);
    float qv, kv;
    if (d < DK) {
        qv = Q[(size_t)i*DM + h*DK + d] * INV_SCALE;
        kv = Km[(size_t)i*DM + h*DK + d];
    } else {
        qv = COUPLING * g[(size_t)i*F_ + (d-DK)];
        kv = fp[(size_t)i*F_ + (d-DK)];
    }
    h16 qh = __float2half(qv);
    Qhi[idx] = qh;
    Qlo[idx] = __float2half(qv - __half2float(qh));
    Khi[idx] = __float2half(kv);
}

__global__ void softmax_kernel(const float* __restrict__ P, h16* __restrict__ Phi)
{
    size_t row = blockIdx.x;
    const float* p = P + row * (size_t)S_;
    int t = threadIdx.x;
    float vals[8];
    float4 v0 = *(const float4*)(p + t*8);
    float4 v1 = *(const float4*)(p + t*8 + 4);
    vals[0]=v0.x; vals[1]=v0.y; vals[2]=v0.z; vals[3]=v0.w;
    vals[4]=v1.x; vals[5]=v1.y; vals[6]=v1.z; vals[7]=v1.w;
    float m = vals[0];
#pragma unroll
    for (int i = 1; i < 8; i++) m = fmaxf(m, vals[i]);
    __shared__ float red[8];
    for (int o = 16; o; o >>= 1) m = fmaxf(m, __shfl_xor_sync(~0u, m, o));
    if ((t & 31) == 0) red[t>>5] = m;
    __syncthreads();
    m = red[0];
#pragma unroll
    for (int i = 1; i < 8; i++) m = fmaxf(m, red[i]);
    float s = 0.f;
#pragma unroll
    for (int i = 0; i < 8; i++) { vals[i] = __expf(vals[i] - m); s += vals[i]; }
    for (int o = 16; o; o >>= 1) s += __shfl_xor_sync(~0u, s, o);
    __shared__ float red2[8];
    if ((t & 31) == 0) red2[t>>5] = s;
    __syncthreads();
    s = red2[0];
#pragma unroll
    for (int i = 1; i < 8; i++) s += red2[i];
    float inv = 1.0f / s;
    uint4 hv;
    hv.x = pack_h16x2(vals[0]*inv, vals[1]*inv);
    hv.y = pack_h16x2(vals[2]*inv, vals[3]*inv);
    hv.z = pack_h16x2(vals[4]*inv, vals[5]*inv);
    hv.w = pack_h16x2(vals[6]*inv, vals[7]*inv);
    *(uint4*)(Phi + row * (size_t)S_ + t*8) = hv;
}

__global__ void scalar_kernel(const float* __restrict__ g, const float* __restrict__ fpsum,
                              const float* __restrict__ curv, float* __restrict__ out0,
                              float* __restrict__ out1)
{
    __shared__ float sm[256];
    __shared__ float sc[256];
    int t = threadIdx.x;
    int f = t & 63, c = t >> 6;
    float s = 0.f;
    for (int i = c; i < S_; i += 4) s += g[i*F_ + f];
    sm[t] = s; __syncthreads();
    float tot = 0.f;
    if (c == 0) tot = sm[f] + sm[64+f] + sm[128+f] + sm[192+f];
    __syncthreads();
    sm[t] = (c == 0) ? tot * fpsum[f] : 0.f;
    float cs = 0.f;
    for (int j = t; j < S_; j += 256) cs += curv[j];
    sc[t] = cs;
    __syncthreads();
    if (t == 0) {
        float a = 0.f, b = 0.f;
        for (int i = 0; i < 64; i++) a += sm[i];
        for (int i = 0; i < 256; i++) b += sc[i];
        float val = a / ((float)S_ * (float)S_) + b / (float)S_;
        *out0 = val;
        if (out1) *out1 = val;
    }
}

// ================= launch =================
extern "C" void kernel_launch(void* const* d_in, const int* in_sizes, int n_in,
                              void* d_out, int out_size)
{
    const float* x    = (const float*)d_in[0];
    const float* wq   = (const float*)d_in[2];
    const float* wk   = (const float*)d_in[3];
    const float* wv   = (const float*)d_in[4];
    const float* wo_w = (const float*)d_in[5];
    const float* wo_b = (const float*)d_in[6];
    const float* fw   = (const float*)d_in[7];
    const float* fb   = (const float*)d_in[8];
    const float* fm1w = (const float*)d_in[9];
    const float* fm1b = (const float*)d_in[10];
    const float* fm2w = (const float*)d_in[11];
    const float* fm2b = (const float*)d_in[12];
    const float* cm   = (const float*)d_in[13];
    float* out = (float*)d_out;

    h16 *xhi,*xlo,*wqkhi,*wvhi,*wohi;
    h16 *Vthi,*Qahi,*Qalo,*Kahi,*Phi,*athi;
    float *QK,*fp,*fpart,*g,*metric,*mi,*fpsum,*curv,*curvb,*scores;
    cudaGetSymbolAddress((void**)&xhi, d_xhi);     cudaGetSymbolAddress((void**)&xlo, d_xlo);
    cudaGetSymbolAddress((void**)&wqkhi, d_wqkhi);
    cudaGetSymbolAddress((void**)&wvhi, d_wvhi);
    cudaGetSymbolAddress((void**)&wohi, d_wohi);
    cudaGetSymbolAddress((void**)&Vthi, d_Vthi);
    cudaGetSymbolAddress((void**)&Qahi, d_Qahi);   cudaGetSymbolAddress((void**)&Qalo, d_Qalo);
    cudaGetSymbolAddress((void**)&Kahi, d_Kahi);
    cudaGetSymbolAddress((void**)&Phi, d_Phi);
    cudaGetSymbolAddress((void**)&athi, d_attnhi);
    cudaGetSymbolAddress((void**)&QK, d_QK);
    cudaGetSymbolAddress((void**)&fp, d_fp);       cudaGetSymbolAddress((void**)&fpart, d_fpart);
    cudaGetSymbolAddress((void**)&g, d_g);
    cudaGetSymbolAddress((void**)&metric, d_metric); cudaGetSymbolAddress((void**)&mi, d_mi);
    cudaGetSymbolAddress((void**)&fpsum, d_fpsum);   cudaGetSymbolAddress((void**)&curv, d_curv);
    cudaGetSymbolAddress((void**)&curvb, d_curvb);   cudaGetSymbolAddress((void**)&scores, d_scores);

    cudaFuncSetAttribute(mma_gemm_nt<0>, cudaFuncAttributeMaxDynamicSharedMemorySize, MMA_SMEM);
    cudaFuncSetAttribute(mma_gemm_nt_1t<0>, cudaFuncAttributeMaxDynamicSharedMemorySize, MMA1_SMEM);
    cudaFuncSetAttribute(mma_gemm_nt_1t<2>, cudaFuncAttributeMaxDynamicSharedMemorySize, MMA1_SMEM);

    const int NDM = S_*DM;
    // 0) fp16 splits: hi for all 5, lo only for x
    split5_kernel<<<dim3(NDM/1024, 5), 256>>>(
        x, wq, wk, wv, wo_w,
        xhi, wqkhi, wqkhi + (size_t)DM*DM, wvhi, wohi,
        xlo);

    // 1) Q and K projections batched: z=2 (2-term, fp32 out)
    mma_gemm_nt<0><<<dim3(16,16,2), 256, MMA_SMEM>>>(
        xhi, xlo, DM, 0, wqkhi, DM, (size_t)DM*DM,
        QK, DM, (size_t)S_*DM, DM, nullptr);
    // 2) Vt[d][s] = wv @ x^T (1-term, h16 hi out)
    mma_gemm_nt_1t<2><<<dim3(16,16,1), 256, MMA1_SMEM>>>(
        wvhi, DM, 0, xhi, DM, 0,
        nullptr, Vthi, S_, 0, DM, nullptr);
    // 3) fiber projection (deterministic split-K)
    fiber_gemm<<<dim3(16, 32), 256>>>(x, fw, fpart);
    fiber_reduce<<<S_*F_/256, 256>>>(fpart, fb, fp);
    // 4) stats -> MLP -> metric -> g -> curv
    fp_stats_kernel<<<1, 256>>>(fp, fpsum, mi);
    mlp_metric_kernel<<<1, 64>>>(mi, fm1w, fm1b, fm2w, fm2b, metric);
    compute_g_kernel<<<S_/4, 256>>>(fp, metric, g);
    curv_kernel<<<S_/256, 256>>>(fp, cm, curv, curvb);
    // 5) pack augmented Q (hi+lo) / K (hi)
    pack_aug_kernel<<<(H_*S_*AUG)/256, 256>>>(QK, QK + (size_t)S_*DM, g, fp,
                                              Qahi, Qalo, Kahi);
    // 6) scores = Qaug @ Kaug^T + 0.1*curv[col] (2-term, K=192, batched heads)
    mma_gemm_nt<0><<<dim3(16,16,H_), 256, MMA_SMEM>>>(
        Qahi, Qalo, AUG, (size_t)S_*AUG, Kahi, AUG, (size_t)S_*AUG,
        scores, S_, (size_t)S_*S_, AUG, curvb);
    // 7) softmax -> P hi only
    softmax_kernel<<<H_*S_, 256>>>(scores, Phi);
    // 8) attn = P[h] @ Vt[h]^T (1-term, h16 hi out)
    mma_gemm_nt_1t<2><<<dim3(1,16,H_), 256, MMA1_SMEM>>>(
        Phi, S_, (size_t)S_*S_, Vthi, S_, (size_t)DK*S_,
        nullptr, athi, DM, (size_t)DK, S_, nullptr);
    // 9) out = attn @ wo^T + wo_b (1-term, fp32 -> d_out)
    mma_gemm_nt_1t<0><<<dim3(16,16,1), 256, MMA1_SMEM>>>(
        athi, DM, 0, wohi, DM, 0,
        out, nullptr, DM, 0, DM, wo_b);
    // 10) ci.mean() scalar
    if (out_size > S_*DM) {
        float* o0 = out + (size_t)S_*DM;
        float* o1 = out + (size_t)(out_size - 1);
        scalar_kernel<<<1, 256>>>(g, fpsum, curv, o0, (o1 != o0) ? o1 : nullptr);
    }
}

// round 16
// speedup vs baseline: 1.7357x; 1.1038x over previous
#include <cuda_runtime.h>
#include <cuda_fp16.h>
#include <cstdint>
#include <math.h>

#define S_  2048
#define DM  2048
#define H_  16
#define DK  128
#define F_  64
#define AUG 192
#define INV_SCALE (1.0f/11.313708498984761f)
#define COUPLING 0.1f

typedef __half h16;

// ---------------- device scratch (256B-aligned) ----------------
__device__ __align__(256) h16   d_xhi[S_*DM];
__device__ __align__(256) h16   d_wqkhi[2*DM*DM];                     // wq then wk (hi only)
__device__ __align__(256) h16   d_wvhi[DM*DM];
__device__ __align__(256) h16   d_wohi[DM*DM];
__device__ __align__(256) float d_QK[2*S_*DM];                        // Q then K (fp32)
__device__ __align__(256) h16   d_Vthi[DM*S_];                        // V transposed [d][s]
__device__ __align__(256) float d_fp[S_*F_];
__device__ __align__(256) float d_fpart[16*S_*F_];
__device__ __align__(256) float d_g[S_*F_];
__device__ __align__(256) float d_metric[F_*F_];
__device__ __align__(256) float d_mi[F_];
__device__ __align__(256) float d_fpsum[F_];
__device__ __align__(256) float d_curv[S_];
__device__ __align__(256) float d_curvb[S_];
__device__ __align__(256) h16   d_Qahi[H_*S_*AUG], d_Qalo[H_*S_*AUG];
__device__ __align__(256) h16   d_Kahi[H_*S_*AUG];
__device__ __align__(256) float d_scores[H_*S_*S_];
__device__ __align__(256) h16   d_Phi[H_*S_*S_];
__device__ __align__(256) h16   d_attnhi[S_*DM];

// ================= portable-ISA helpers =================
__device__ __forceinline__ uint32_t smem_to_u32(const void* p) {
    uint32_t a;
    asm("{ .reg .u64 t; cvta.to.shared.u64 t, %1; cvt.u32.u64 %0, t; }" : "=r"(a) : "l"(p));
    return a;
}
__device__ __forceinline__ void cp16(uint32_t saddr, const void* g) {
    asm volatile("cp.async.cg.shared.global [%0], [%1], 16;" :: "r"(saddr), "l"(g));
}
__device__ __forceinline__ void ldsm4(uint32_t* r, uint32_t a) {
    asm volatile("ldmatrix.sync.aligned.m8n8.x4.shared.b16 {%0,%1,%2,%3}, [%4];"
                 : "=r"(r[0]), "=r"(r[1]), "=r"(r[2]), "=r"(r[3]) : "r"(a));
}
__device__ __forceinline__ void mma_f16(float* c, const uint32_t* a, uint32_t b0, uint32_t b1) {
    asm volatile("mma.sync.aligned.m16n8k16.row.col.f32.f16.f16.f32 "
                 "{%0,%1,%2,%3}, {%4,%5,%6,%7}, {%8,%9}, {%0,%1,%2,%3};"
                 : "+f"(c[0]), "+f"(c[1]), "+f"(c[2]), "+f"(c[3])
                 : "r"(a[0]), "r"(a[1]), "r"(a[2]), "r"(a[3]), "r"(b0), "r"(b1));
}
__device__ __forceinline__ uint32_t pack_h16x2(float lo, float hi) {
    unsigned short l = __half_as_ushort(__float2half(lo));
    unsigned short h = __half_as_ushort(__float2half(hi));
    return (uint32_t)l | ((uint32_t)h << 16);
}

__device__ __forceinline__ uint32_t sw_off(int row, int chunk) {
    return (uint32_t)(row * 64 + ((chunk ^ ((row >> 1) & 3)) << 4));
}

// ================= 2-term kernel (A hi+lo, B hi): stage Ahi|Alo|Bhi = 24KB =================
#define STAGE_BYTES 24576
#define MMA_SMEM (2*STAGE_BYTES)

__device__ __forceinline__ void load_tiles(uint32_t sbase, int tid,
    const h16* g0, const h16* g1, const h16* g2,
    int lda, int ldb, int k0)
{
    const h16* gp[3] = {g0, g1, g2};
#pragma unroll
    for (int i = 0; i < 6; i++) {
        int q = tid + i * 256;
        int tile = q >> 9, r = (q >> 2) & 127, c = q & 3;
        int ld = (tile < 2) ? lda : ldb;
        const h16* src = gp[tile] + (size_t)r * ld + k0 + c * 8;
        uint32_t so = sbase + tile * 8192 + sw_off(r, c);
        cp16(so, src);
    }
    asm volatile("cp.async.commit_group;" ::: "memory");
}

// fp32 C (+bias[col]) — used for the scores GEMM only
__global__ void __launch_bounds__(256)
mma_gemm_nt(const h16* __restrict__ Ahi, const h16* __restrict__ Alo, int lda, size_t sAz,
            const h16* __restrict__ Bhi, int ldb, size_t sBz,
            float* __restrict__ C, int ldc, size_t sCz, int K, const float* __restrict__ bias)
{
    extern __shared__ char smem[];
    const uint32_t sb = smem_to_u32(smem);
    const int tid = threadIdx.x, lane = tid & 31, wid = tid >> 5;
    const int wm = wid & 1, wn = wid >> 1;
    const size_t z = blockIdx.z;
    const int bm = blockIdx.y * 128, bn = blockIdx.x * 128;

    const h16* gA0 = Ahi + z * sAz + (size_t)bm * lda;
    const h16* gA1 = Alo + z * sAz + (size_t)bm * lda;
    const h16* gB0 = Bhi + z * sBz + (size_t)bn * ldb;

    float acc[4][4][4];
#pragma unroll
    for (int i = 0; i < 4; i++)
#pragma unroll
        for (int j = 0; j < 4; j++)
#pragma unroll
            for (int k = 0; k < 4; k++) acc[i][j][k] = 0.f;

    const int a_row_l = (lane & 7) + ((lane >> 3) & 1) * 8;
    const int a_chk_l = lane >> 4;
    const int b_row_l = (lane & 7) + ((lane >> 4) & 1) * 8;
    const int b_chk_l = (lane >> 3) & 1;

    const int nch = K >> 5;
    load_tiles(sb, tid, gA0, gA1, gB0, lda, ldb, 0);

    for (int c = 0; c < nch; c++) {
        if (c + 1 < nch) {
            load_tiles(sb + ((c + 1) & 1) * STAGE_BYTES, tid, gA0, gA1, gB0,
                       lda, ldb, (c + 1) * 32);
            asm volatile("cp.async.wait_group 1;" ::: "memory");
        } else {
            asm volatile("cp.async.wait_group 0;" ::: "memory");
        }
        __syncthreads();
        const uint32_t s0 = sb + (c & 1) * STAGE_BYTES;
#pragma unroll
        for (int ks = 0; ks < 2; ks++) {
            uint32_t a_hi[4][4], a_lo[4][4], b_hi[8];
#pragma unroll
            for (int mt = 0; mt < 4; mt++) {
                int row = wm * 64 + mt * 16 + a_row_l;
                uint32_t off = sw_off(row, ks * 2 + a_chk_l);
                ldsm4(a_hi[mt], s0 + off);
                ldsm4(a_lo[mt], s0 + 8192 + off);
            }
#pragma unroll
            for (int ntp = 0; ntp < 2; ntp++) {
                int row = wn * 32 + ntp * 16 + b_row_l;
                uint32_t off = sw_off(row, ks * 2 + b_chk_l);
                ldsm4(&b_hi[ntp * 4], s0 + 16384 + off);
            }
#pragma unroll
            for (int mt = 0; mt < 4; mt++)
#pragma unroll
                for (int nt = 0; nt < 4; nt++) {
                    int bi = (nt >> 1) * 4 + (nt & 1) * 2;
                    mma_f16(acc[mt][nt], a_hi[mt], b_hi[bi], b_hi[bi + 1]);
                    mma_f16(acc[mt][nt], a_lo[mt], b_hi[bi], b_hi[bi + 1]);
                }
        }
        __syncthreads();
    }

    const int r_l = lane >> 2, c_l = (lane & 3) * 2;
#pragma unroll
    for (int mt = 0; mt < 4; mt++) {
#pragma unroll
        for (int nt = 0; nt < 4; nt++) {
            int row0 = bm + wm * 64 + mt * 16 + r_l;
            int col  = bn + wn * 32 + nt * 8 + c_l;
            float v0 = acc[mt][nt][0], v1 = acc[mt][nt][1];
            float v2 = acc[mt][nt][2], v3 = acc[mt][nt][3];
            if (bias) { v0 += bias[col]; v1 += bias[col + 1]; v2 += bias[col]; v3 += bias[col + 1]; }
            float* p0 = C + z * sCz + (size_t)row0 * ldc + col;
            float* p1 = C + z * sCz + (size_t)(row0 + 8) * ldc + col;
            p0[0] = v0; p0[1] = v1;
            p1[0] = v2; p1[1] = v3;
        }
    }
}

// ================= 1-term kernel (A hi, B hi): stage Ahi|Bhi = 16KB =================
#define STAGE1_BYTES 16384
#define MMA1_SMEM (2*STAGE1_BYTES)

__device__ __forceinline__ void load_tiles_1t(uint32_t sbase, int tid,
    const h16* g0, const h16* g1, int lda, int ldb, int k0)
{
    const h16* gp[2] = {g0, g1};
#pragma unroll
    for (int i = 0; i < 4; i++) {
        int q = tid + i * 256;
        int tile = q >> 9, r = (q >> 2) & 127, c = q & 3;
        int ld = (tile == 0) ? lda : ldb;
        const h16* src = gp[tile] + (size_t)r * ld + k0 + c * 8;
        uint32_t so = sbase + tile * 8192 + sw_off(r, c);
        cp16(so, src);
    }
    asm volatile("cp.async.commit_group;" ::: "memory");
}

// OUT_MODE 0: fp32 C (+bias[col]);  OUT_MODE 2: h16 hi only.
template<int OUT_MODE>
__global__ void __launch_bounds__(256)
mma_gemm_nt_1t(const h16* __restrict__ Ahi, int lda, size_t sAz,
               const h16* __restrict__ Bhi, int ldb, size_t sBz,
               float* __restrict__ C, h16* __restrict__ Chi,
               int ldc, size_t sCz, int K, const float* __restrict__ bias)
{
    extern __shared__ char smem[];
    const uint32_t sb = smem_to_u32(smem);
    const int tid = threadIdx.x, lane = tid & 31, wid = tid >> 5;
    const int wm = wid & 1, wn = wid >> 1;
    const size_t z = blockIdx.z;
    const int bm = blockIdx.y * 128, bn = blockIdx.x * 128;

    const h16* gA0 = Ahi + z * sAz + (size_t)bm * lda;
    const h16* gB0 = Bhi + z * sBz + (size_t)bn * ldb;

    float acc[4][4][4];
#pragma unroll
    for (int i = 0; i < 4; i++)
#pragma unroll
        for (int j = 0; j < 4; j++)
#pragma unroll
            for (int k = 0; k < 4; k++) acc[i][j][k] = 0.f;

    const int a_row_l = (lane & 7) + ((lane >> 3) & 1) * 8;
    const int a_chk_l = lane >> 4;
    const int b_row_l = (lane & 7) + ((lane >> 4) & 1) * 8;
    const int b_chk_l = (lane >> 3) & 1;

    const int nch = K >> 5;
    load_tiles_1t(sb, tid, gA0, gB0, lda, ldb, 0);

    for (int c = 0; c < nch; c++) {
        if (c + 1 < nch) {
            load_tiles_1t(sb + ((c + 1) & 1) * STAGE1_BYTES, tid, gA0, gB0,
                          lda, ldb, (c + 1) * 32);
            asm volatile("cp.async.wait_group 1;" ::: "memory");
        } else {
            asm volatile("cp.async.wait_group 0;" ::: "memory");
        }
        __syncthreads();
        const uint32_t s0 = sb + (c & 1) * STAGE1_BYTES;
#pragma unroll
        for (int ks = 0; ks < 2; ks++) {
            uint32_t a_hi[4][4], b_hi[8];
#pragma unroll
            for (int mt = 0; mt < 4; mt++) {
                int row = wm * 64 + mt * 16 + a_row_l;
                ldsm4(a_hi[mt], s0 + sw_off(row, ks * 2 + a_chk_l));
            }
#pragma unroll
            for (int ntp = 0; ntp < 2; ntp++) {
                int row = wn * 32 + ntp * 16 + b_row_l;
                ldsm4(&b_hi[ntp * 4], s0 + 8192 + sw_off(row, ks * 2 + b_chk_l));
            }
#pragma unroll
            for (int mt = 0; mt < 4; mt++)
#pragma unroll
                for (int nt = 0; nt < 4; nt++) {
                    int bi = (nt >> 1) * 4 + (nt & 1) * 2;
                    mma_f16(acc[mt][nt], a_hi[mt], b_hi[bi], b_hi[bi + 1]);
                }
        }
        __syncthreads();
    }

    const int r_l = lane >> 2, c_l = (lane & 3) * 2;
#pragma unroll
    for (int mt = 0; mt < 4; mt++) {
#pragma unroll
        for (int nt = 0; nt < 4; nt++) {
            int row0 = bm + wm * 64 + mt * 16 + r_l;
            int col  = bn + wn * 32 + nt * 8 + c_l;
            float v0 = acc[mt][nt][0], v1 = acc[mt][nt][1];
            float v2 = acc[mt][nt][2], v3 = acc[mt][nt][3];
            if (OUT_MODE == 0) {
                if (bias) { v0 += bias[col]; v1 += bias[col + 1]; v2 += bias[col]; v3 += bias[col + 1]; }
                float* p0 = C + z * sCz + (size_t)row0 * ldc + col;
                float* p1 = C + z * sCz + (size_t)(row0 + 8) * ldc + col;
                p0[0] = v0; p0[1] = v1;
                p1[0] = v2; p1[1] = v3;
            } else {
                h16* hp0 = Chi + z * sCz + (size_t)row0 * ldc + col;
                h16* hp1 = Chi + z * sCz + (size_t)(row0 + 8) * ldc + col;
                hp0[0] = __float2half(v0); hp0[1] = __float2half(v1);
                hp1[0] = __float2half(v2); hp1[1] = __float2half(v3);
            }
        }
    }
}

// ================= small kernels =================
// all-hi split (no lo arrays needed anymore)
__global__ void split5_kernel(
    const float* __restrict__ s0, const float* __restrict__ s1, const float* __restrict__ s2,
    const float* __restrict__ s3, const float* __restrict__ s4,
    h16* __restrict__ h0, h16* __restrict__ h1, h16* __restrict__ h2,
    h16* __restrict__ h3, h16* __restrict__ h4)
{
    int i4 = blockIdx.x * blockDim.x + threadIdx.x;
    int zz = blockIdx.y;
    const float* src = (zz == 0) ? s0 : (zz == 1) ? s1 : (zz == 2) ? s2 : (zz == 3) ? s3 : s4;
    h16* hi = (zz == 0) ? h0 : (zz == 1) ? h1 : (zz == 2) ? h2 : (zz == 3) ? h3 : h4;
    float4 v = *((const float4*)src + i4);
    uint2 hv;
    hv.x = pack_h16x2(v.x, v.y);
    hv.y = pack_h16x2(v.z, v.w);
    *((uint2*)hi + i4) = hv;
}

__global__ void fiber_gemm(const float* __restrict__ x, const float* __restrict__ fw,
                           float* __restrict__ fpart)
{
    __shared__ float Xs[64][68];
    __shared__ float Fs[64][68];
    const int ksplit = blockIdx.x;
    const int rb = blockIdx.y * 64;
    const int t = threadIdx.x;
    const int rt = t & 15, ct = t >> 4;
    float acc[4][4] = {};
    for (int sub = 0; sub < 2; sub++) {
        const int k0 = ksplit * 128 + sub * 64;
        __syncthreads();
        for (int i = t; i < 1024; i += 256) {
            int row = i >> 4, kq = (i & 15) * 4;
            float4 v = *(const float4*)&x[(size_t)(rb + row) * DM + k0 + kq];
            Xs[kq][row] = v.x; Xs[kq+1][row] = v.y; Xs[kq+2][row] = v.z; Xs[kq+3][row] = v.w;
            float4 w = *(const float4*)&fw[(size_t)row * DM + k0 + kq];
            Fs[kq][row] = w.x; Fs[kq+1][row] = w.y; Fs[kq+2][row] = w.z; Fs[kq+3][row] = w.w;
        }
        __syncthreads();
#pragma unroll 16
        for (int k = 0; k < 64; k++) {
            float a[4], b[4];
#pragma unroll
            for (int i = 0; i < 4; i++) a[i] = Xs[k][rt*4 + i];
#pragma unroll
            for (int j = 0; j < 4; j++) b[j] = Fs[k][ct*4 + j];
#pragma unroll
            for (int i = 0; i < 4; i++)
#pragma unroll
                for (int j = 0; j < 4; j++) acc[i][j] = fmaf(a[i], b[j], acc[i][j]);
        }
    }
    float* dst = fpart + (size_t)ksplit * S_ * F_;
#pragma unroll
    for (int i = 0; i < 4; i++)
#pragma unroll
        for (int j = 0; j < 4; j++)
            dst[(size_t)(rb + rt*4 + i) * F_ + ct*4 + j] = acc[i][j];
}

__global__ void fiber_reduce(const float* __restrict__ fpart, const float* __restrict__ fb,
                             float* __restrict__ fp)
{
    int i = blockIdx.x * blockDim.x + threadIdx.x;
    if (i >= S_ * F_) return;
    float a = fb[i & 63];
#pragma unroll
    for (int s = 0; s < 16; s++) a += fpart[(size_t)s * S_ * F_ + i];
    fp[i] = a;
}

__global__ void fp_stats_kernel(const float* __restrict__ fp,
                                float* __restrict__ fpsum, float* __restrict__ mi)
{
    __shared__ float sm[256];
    int t = threadIdx.x;
    int f = t & 63, c = t >> 6;
    float s = 0.f;
    for (int i = c; i < S_; i += 4) s += fp[i*F_ + f];
    sm[t] = s; __syncthreads();
    if (c == 0) {
        float tot = sm[f] + sm[64+f] + sm[128+f] + sm[192+f];
        fpsum[f] = tot;
        mi[f] = tot / (float)S_;
    }
}

__global__ void mlp_metric_kernel(const float* __restrict__ mi,
                                  const float* __restrict__ fm1w, const float* __restrict__ fm1b,
                                  const float* __restrict__ fm2w, const float* __restrict__ fm2b,
                                  float* __restrict__ metric)
{
    __shared__ float smi[F_];
    __shared__ float hid[F_/2];
    __shared__ float raw[F_];
    int t = threadIdx.x;
    smi[t] = mi[t];
    __syncthreads();
    if (t < F_/2) {
        float a = fm1b[t];
        for (int f = 0; f < F_; f++) a = fmaf(smi[f], fm1w[t*F_ + f], a);
        hid[t] = fmaxf(a, 0.f);
    }
    __syncthreads();
    {
        float a = fm2b[t];
        for (int j = 0; j < F_/2; j++) a = fmaf(hid[j], fm2w[t*(F_/2) + j], a);
        raw[t] = a;
    }
    __syncthreads();
    for (int b = 0; b < F_; b++)
        metric[t*F_ + b] = raw[t]*raw[b] + ((t == b) ? 0.1f : 0.f);
}

__global__ void compute_g_kernel(const float* __restrict__ fp,
                                 const float* __restrict__ metric,
                                 float* __restrict__ g)
{
    __shared__ float sm[F_*F_];
    for (int i = threadIdx.x; i < F_*F_; i += blockDim.x) sm[i] = metric[i];
    __syncthreads();
    int t = threadIdx.x;
    int f = t & 63, r = t >> 6;
    int i = blockIdx.x*4 + r;
    const float* fr = fp + (size_t)i*F_;
    float a = 0.f;
#pragma unroll
    for (int k = 0; k < F_; k++) a = fmaf(fr[k], sm[k*F_ + f], a);
    g[(size_t)i*F_ + f] = a;
}

__global__ void curv_kernel(const float* __restrict__ fp, const float* __restrict__ cm,
                            float* __restrict__ curv, float* __restrict__ curvb)
{
    int j = blockIdx.x*blockDim.x + threadIdx.x;
    if (j >= S_) return;
    float a = 0.f;
#pragma unroll
    for (int f = 0; f < F_; f++) a = fmaf(fp[(size_t)j*F_ + f], cm[f*(F_+1)], a);
    curv[j] = a;
    curvb[j] = COUPLING * a;
}

__global__ void pack_aug_kernel(const float* __restrict__ Q, const float* __restrict__ Km,
                                const float* __restrict__ g, const float* __restrict__ fp,
                                h16* __restrict__ Qhi, h16* __restrict__ Qlo,
                                h16* __restrict__ Khi)
{
    int idx = blockIdx.x*blockDim.x + threadIdx.x;
    if (idx >= H_*S_*AUG) return;
    int d = idx % AUG;
    int i = (idx / AUG) % S_;
    int h = idx / (AUG*S_);
    float qv, kv;
    if (d < DK) {
        qv = Q[(size_t)i*DM + h*DK + d] * INV_SCALE;
        kv = Km[(size_t)i*DM + h*DK + d];
    } else {
        qv = COUPLING * g[(size_t)i*F_ + (d-DK)];
        kv = fp[(size_t)i*F_ + (d-DK)];
    }
    h16 qh = __float2half(qv);
    Qhi[idx] = qh;
    Qlo[idx] = __float2half(qv - __half2float(qh));
    Khi[idx] = __float2half(kv);
}

__global__ void softmax_kernel(const float* __restrict__ P, h16* __restrict__ Phi)
{
    size_t row = blockIdx.x;
    const float* p = P + row * (size_t)S_;
    int t = threadIdx.x;
    float vals[8];
    float4 v0 = *(const float4*)(p + t*8);
    float4 v1 = *(const float4*)(p + t*8 + 4);
    vals[0]=v0.x; vals[1]=v0.y; vals[2]=v0.z; vals[3]=v0.w;
    vals[4]=v1.x; vals[5]=v1.y; vals[6]=v1.z; vals[7]=v1.w;
    float m = vals[0];
#pragma unroll
    for (int i = 1; i < 8; i++) m = fmaxf(m, vals[i]);
    __shared__ float red[8];
    for (int o = 16; o; o >>= 1) m = fmaxf(m, __shfl_xor_sync(~0u, m, o));
    if ((t & 31) == 0) red[t>>5] = m;
    __syncthreads();
    m = red[0];
#pragma unroll
    for (int i = 1; i < 8; i++) m = fmaxf(m, red[i]);
    float s = 0.f;
#pragma unroll
    for (int i = 0; i < 8; i++) { vals[i] = __expf(vals[i] - m); s += vals[i]; }
    for (int o = 16; o; o >>= 1) s += __shfl_xor_sync(~0u, s, o);
    __shared__ float red2[8];
    if ((t & 31) == 0) red2[t>>5] = s;
    __syncthreads();
    s = red2[0];
#pragma unroll
    for (int i = 1; i < 8; i++) s += red2[i];
    float inv = 1.0f / s;
    uint4 hv;
    hv.x = pack_h16x2(vals[0]*inv, vals[1]*inv);
    hv.y = pack_h16x2(vals[2]*inv, vals[3]*inv);
    hv.z = pack_h16x2(vals[4]*inv, vals[5]*inv);
    hv.w = pack_h16x2(vals[6]*inv, vals[7]*inv);
    *(uint4*)(Phi + row * (size_t)S_ + t*8) = hv;
}

__global__ void scalar_kernel(const float* __restrict__ g, const float* __restrict__ fpsum,
                              const float* __restrict__ curv, float* __restrict__ out0,
                              float* __restrict__ out1)
{
    __shared__ float sm[256];
    __shared__ float sc[256];
    int t = threadIdx.x;
    int f = t & 63, c = t >> 6;
    float s = 0.f;
    for (int i = c; i < S_; i += 4) s += g[i*F_ + f];
    sm[t] = s; __syncthreads();
    float tot = 0.f;
    if (c == 0) tot = sm[f] + sm[64+f] + sm[128+f] + sm[192+f];
    __syncthreads();
    sm[t] = (c == 0) ? tot * fpsum[f] : 0.f;
    float cs = 0.f;
    for (int j = t; j < S_; j += 256) cs += curv[j];
    sc[t] = cs;
    __syncthreads();
    if (t == 0) {
        float a = 0.f, b = 0.f;
        for (int i = 0; i < 64; i++) a += sm[i];
        for (int i = 0; i < 256; i++) b += sc[i];
        float val = a / ((float)S_ * (float)S_) + b / (float)S_;
        *out0 = val;
        if (out1) *out1 = val;
    }
}

// ================= launch =================
extern "C" void kernel_launch(void* const* d_in, const int* in_sizes, int n_in,
                              void* d_out, int out_size)
{
    const float* x    = (const float*)d_in[0];
    const float* wq   = (const float*)d_in[2];
    const float* wk   = (const float*)d_in[3];
    const float* wv   = (const float*)d_in[4];
    const float* wo_w = (const float*)d_in[5];
    const float* wo_b = (const float*)d_in[6];
    const float* fw   = (const float*)d_in[7];
    const float* fb   = (const float*)d_in[8];
    const float* fm1w = (const float*)d_in[9];
    const float* fm1b = (const float*)d_in[10];
    const float* fm2w = (const float*)d_in[11];
    const float* fm2b = (const float*)d_in[12];
    const float* cm   = (const float*)d_in[13];
    float* out = (float*)d_out;

    h16 *xhi,*wqkhi,*wvhi,*wohi;
    h16 *Vthi,*Qahi,*Qalo,*Kahi,*Phi,*athi;
    float *QK,*fp,*fpart,*g,*metric,*mi,*fpsum,*curv,*curvb,*scores;
    cudaGetSymbolAddress((void**)&xhi, d_xhi);
    cudaGetSymbolAddress((void**)&wqkhi, d_wqkhi);
    cudaGetSymbolAddress((void**)&wvhi, d_wvhi);
    cudaGetSymbolAddress((void**)&wohi, d_wohi);
    cudaGetSymbolAddress((void**)&Vthi, d_Vthi);
    cudaGetSymbolAddress((void**)&Qahi, d_Qahi);   cudaGetSymbolAddress((void**)&Qalo, d_Qalo);
    cudaGetSymbolAddress((void**)&Kahi, d_Kahi);
    cudaGetSymbolAddress((void**)&Phi, d_Phi);
    cudaGetSymbolAddress((void**)&athi, d_attnhi);
    cudaGetSymbolAddress((void**)&QK, d_QK);
    cudaGetSymbolAddress((void**)&fp, d_fp);       cudaGetSymbolAddress((void**)&fpart, d_fpart);
    cudaGetSymbolAddress((void**)&g, d_g);
    cudaGetSymbolAddress((void**)&metric, d_metric); cudaGetSymbolAddress((void**)&mi, d_mi);
    cudaGetSymbolAddress((void**)&fpsum, d_fpsum);   cudaGetSymbolAddress((void**)&curv, d_curv);
    cudaGetSymbolAddress((void**)&curvb, d_curvb);   cudaGetSymbolAddress((void**)&scores, d_scores);

    cudaFuncSetAttribute(mma_gemm_nt, cudaFuncAttributeMaxDynamicSharedMemorySize, MMA_SMEM);
    cudaFuncSetAttribute(mma_gemm_nt_1t<0>, cudaFuncAttributeMaxDynamicSharedMemorySize, MMA1_SMEM);
    cudaFuncSetAttribute(mma_gemm_nt_1t<2>, cudaFuncAttributeMaxDynamicSharedMemorySize, MMA1_SMEM);

    const int NDM = S_*DM;
    // 0) fp16 hi splits for all 5 tensors
    split5_kernel<<<dim3(NDM/1024, 5), 256>>>(
        x, wq, wk, wv, wo_w,
        xhi, wqkhi, wqkhi + (size_t)DM*DM, wvhi, wohi);

    // 1) Q and K projections batched: z=2 (1-term, fp32 out)
    mma_gemm_nt_1t<0><<<dim3(16,16,2), 256, MMA1_SMEM>>>(
        xhi, DM, 0, wqkhi, DM, (size_t)DM*DM,
        QK, nullptr, DM, (size_t)S_*DM, DM, nullptr);
    // 2) Vt[d][s] = wv @ x^T (1-term, h16 hi out)
    mma_gemm_nt_1t<2><<<dim3(16,16,1), 256, MMA1_SMEM>>>(
        wvhi, DM, 0, xhi, DM, 0,
        nullptr, Vthi, S_, 0, DM, nullptr);
    // 3) fiber projection (deterministic split-K)
    fiber_gemm<<<dim3(16, 32), 256>>>(x, fw, fpart);
    fiber_reduce<<<S_*F_/256, 256>>>(fpart, fb, fp);
    // 4) stats -> MLP -> metric -> g -> curv
    fp_stats_kernel<<<1, 256>>>(fp, fpsum, mi);
    mlp_metric_kernel<<<1, 64>>>(mi, fm1w, fm1b, fm2w, fm2b, metric);
    compute_g_kernel<<<S_/4, 256>>>(fp, metric, g);
    curv_kernel<<<S_/256, 256>>>(fp, cm, curv, curvb);
    // 5) pack augmented Q (hi+lo) / K (hi)
    pack_aug_kernel<<<(H_*S_*AUG)/256, 256>>>(QK, QK + (size_t)S_*DM, g, fp,
                                              Qahi, Qalo, Kahi);
    // 6) scores = Qaug @ Kaug^T + 0.1*curv[col] (2-term, K=192, batched heads)
    mma_gemm_nt<<<dim3(16,16,H_), 256, MMA_SMEM>>>(
        Qahi, Qalo, AUG, (size_t)S_*AUG, Kahi, AUG, (size_t)S_*AUG,
        scores, S_, (size_t)S_*S_, AUG, curvb);
    // 7) softmax -> P hi only
    softmax_kernel<<<H_*S_, 256>>>(scores, Phi);
    // 8) attn = P[h] @ Vt[h]^T (1-term, h16 hi out)
    mma_gemm_nt_1t<2><<<dim3(1,16,H_), 256, MMA1_SMEM>>>(
        Phi, S_, (size_t)S_*S_, Vthi, S_, (size_t)DK*S_,
        nullptr, athi, DM, (size_t)DK, S_, nullptr);
    // 9) out = attn @ wo^T + wo_b (1-term, fp32 -> d_out)
    mma_gemm_nt_1t<0><<<dim3(16,16,1), 256, MMA1_SMEM>>>(
        athi, DM, 0, wohi, DM, 0,
        out, nullptr, DM, 0, DM, wo_b);
    // 10) ci.mean() scalar
    if (out_size > S_*DM) {
        float* o0 = out + (size_t)S_*DM;
        float* o1 = out + (size_t)(out_size - 1);
        scalar_kernel<<<1, 256>>>(g, fpsum, curv, o0, (o1 != o0) ? o1 : nullptr);
    }
}

// round 17
// speedup vs baseline: 1.8572x; 1.0700x over previous
#include <cuda_runtime.h>
#include <cuda_fp16.h>
#include <cstdint>
#include <math.h>

#define S_  2048
#define DM  2048
#define H_  16
#define DK  128
#define F_  64
#define AUG 192
#define INV_SCALE (1.0f/11.313708498984761f)
#define COUPLING 0.1f

typedef __half h16;

// ---------------- device scratch (256B-aligned) ----------------
__device__ __align__(256) h16   d_xhi[S_*DM];
__device__ __align__(256) h16   d_wqkhi[2*DM*DM];                     // wq then wk
__device__ __align__(256) h16   d_wvhi[DM*DM];
__device__ __align__(256) h16   d_wohi[DM*DM];
__device__ __align__(256) float d_QK[2*S_*DM];                        // Q then K (fp32)
__device__ __align__(256) h16   d_Vthi[DM*S_];                        // V transposed [d][s]
__device__ __align__(256) float d_fp[S_*F_];
__device__ __align__(256) float d_fpart[16*S_*F_];
__device__ __align__(256) float d_g[S_*F_];
__device__ __align__(256) float d_metric[F_*F_];
__device__ __align__(256) float d_mi[F_];
__device__ __align__(256) float d_fpsum[F_];
__device__ __align__(256) float d_curv[S_];
__device__ __align__(256) float d_curvb[S_];
__device__ __align__(256) h16   d_Qahi[H_*S_*AUG];
__device__ __align__(256) h16   d_Kahi[H_*S_*AUG];
__device__ __align__(256) float d_scores[H_*S_*S_];
__device__ __align__(256) h16   d_Phi[H_*S_*S_];
__device__ __align__(256) h16   d_attnhi[S_*DM];

// ================= portable-ISA helpers =================
__device__ __forceinline__ uint32_t smem_to_u32(const void* p) {
    uint32_t a;
    asm("{ .reg .u64 t; cvta.to.shared.u64 t, %1; cvt.u32.u64 %0, t; }" : "=r"(a) : "l"(p));
    return a;
}
__device__ __forceinline__ void cp16(uint32_t saddr, const void* g) {
    asm volatile("cp.async.cg.shared.global [%0], [%1], 16;" :: "r"(saddr), "l"(g));
}
__device__ __forceinline__ void ldsm4(uint32_t* r, uint32_t a) {
    asm volatile("ldmatrix.sync.aligned.m8n8.x4.shared.b16 {%0,%1,%2,%3}, [%4];"
                 : "=r"(r[0]), "=r"(r[1]), "=r"(r[2]), "=r"(r[3]) : "r"(a));
}
__device__ __forceinline__ void mma_f16(float* c, const uint32_t* a, uint32_t b0, uint32_t b1) {
    asm volatile("mma.sync.aligned.m16n8k16.row.col.f32.f16.f16.f32 "
                 "{%0,%1,%2,%3}, {%4,%5,%6,%7}, {%8,%9}, {%0,%1,%2,%3};"
                 : "+f"(c[0]), "+f"(c[1]), "+f"(c[2]), "+f"(c[3])
                 : "r"(a[0]), "r"(a[1]), "r"(a[2]), "r"(a[3]), "r"(b0), "r"(b1));
}
__device__ __forceinline__ uint32_t pack_h16x2(float lo, float hi) {
    unsigned short l = __half_as_ushort(__float2half(lo));
    unsigned short h = __half_as_ushort(__float2half(hi));
    return (uint32_t)l | ((uint32_t)h << 16);
}

__device__ __forceinline__ uint32_t sw_off(int row, int chunk) {
    return (uint32_t)(row * 64 + ((chunk ^ ((row >> 1) & 3)) << 4));
}

// ================= 1-term fp16 NT GEMM: stage Ahi|Bhi = 16KB, double buffered =================
#define STAGE1_BYTES 16384
#define MMA1_SMEM (2*STAGE1_BYTES)

__device__ __forceinline__ void load_tiles_1t(uint32_t sbase, int tid,
    const h16* g0, const h16* g1, int lda, int ldb, int k0)
{
    const h16* gp[2] = {g0, g1};
#pragma unroll
    for (int i = 0; i < 4; i++) {
        int q = tid + i * 256;
        int tile = q >> 9, r = (q >> 2) & 127, c = q & 3;
        int ld = (tile == 0) ? lda : ldb;
        const h16* src = gp[tile] + (size_t)r * ld + k0 + c * 8;
        uint32_t so = sbase + tile * 8192 + sw_off(r, c);
        cp16(so, src);
    }
    asm volatile("cp.async.commit_group;" ::: "memory");
}

// OUT_MODE 0: fp32 C (+bias[col]);  OUT_MODE 2: h16 hi only.
template<int OUT_MODE>
__global__ void __launch_bounds__(256)
mma_gemm_nt_1t(const h16* __restrict__ Ahi, int lda, size_t sAz,
               const h16* __restrict__ Bhi, int ldb, size_t sBz,
               float* __restrict__ C, h16* __restrict__ Chi,
               int ldc, size_t sCz, int K, const float* __restrict__ bias)
{
    extern __shared__ char smem[];
    const uint32_t sb = smem_to_u32(smem);
    const int tid = threadIdx.x, lane = tid & 31, wid = tid >> 5;
    const int wm = wid & 1, wn = wid >> 1;
    const size_t z = blockIdx.z;
    const int bm = blockIdx.y * 128, bn = blockIdx.x * 128;

    const h16* gA0 = Ahi + z * sAz + (size_t)bm * lda;
    const h16* gB0 = Bhi + z * sBz + (size_t)bn * ldb;

    float acc[4][4][4];
#pragma unroll
    for (int i = 0; i < 4; i++)
#pragma unroll
        for (int j = 0; j < 4; j++)
#pragma unroll
            for (int k = 0; k < 4; k++) acc[i][j][k] = 0.f;

    const int a_row_l = (lane & 7) + ((lane >> 3) & 1) * 8;
    const int a_chk_l = lane >> 4;
    const int b_row_l = (lane & 7) + ((lane >> 4) & 1) * 8;
    const int b_chk_l = (lane >> 3) & 1;

    const int nch = K >> 5;
    load_tiles_1t(sb, tid, gA0, gB0, lda, ldb, 0);

    for (int c = 0; c < nch; c++) {
        if (c + 1 < nch) {
            load_tiles_1t(sb + ((c + 1) & 1) * STAGE1_BYTES, tid, gA0, gB0,
                          lda, ldb, (c + 1) * 32);
            asm volatile("cp.async.wait_group 1;" ::: "memory");
        } else {
            asm volatile("cp.async.wait_group 0;" ::: "memory");
        }
        __syncthreads();
        const uint32_t s0 = sb + (c & 1) * STAGE1_BYTES;
#pragma unroll
        for (int ks = 0; ks < 2; ks++) {
            uint32_t a_hi[4][4], b_hi[8];
#pragma unroll
            for (int mt = 0; mt < 4; mt++) {
                int row = wm * 64 + mt * 16 + a_row_l;
                ldsm4(a_hi[mt], s0 + sw_off(row, ks * 2 + a_chk_l));
            }
#pragma unroll
            for (int ntp = 0; ntp < 2; ntp++) {
                int row = wn * 32 + ntp * 16 + b_row_l;
                ldsm4(&b_hi[ntp * 4], s0 + 8192 + sw_off(row, ks * 2 + b_chk_l));
            }
#pragma unroll
            for (int mt = 0; mt < 4; mt++)
#pragma unroll
                for (int nt = 0; nt < 4; nt++) {
                    int bi = (nt >> 1) * 4 + (nt & 1) * 2;
                    mma_f16(acc[mt][nt], a_hi[mt], b_hi[bi], b_hi[bi + 1]);
                }
        }
        __syncthreads();
    }

    const int r_l = lane >> 2, c_l = (lane & 3) * 2;
#pragma unroll
    for (int mt = 0; mt < 4; mt++) {
#pragma unroll
        for (int nt = 0; nt < 4; nt++) {
            int row0 = bm + wm * 64 + mt * 16 + r_l;
            int col  = bn + wn * 32 + nt * 8 + c_l;
            float v0 = acc[mt][nt][0], v1 = acc[mt][nt][1];
            float v2 = acc[mt][nt][2], v3 = acc[mt][nt][3];
            if (OUT_MODE == 0) {
                if (bias) { v0 += bias[col]; v1 += bias[col + 1]; v2 += bias[col]; v3 += bias[col + 1]; }
                float* p0 = C + z * sCz + (size_t)row0 * ldc + col;
                float* p1 = C + z * sCz + (size_t)(row0 + 8) * ldc + col;
                p0[0] = v0; p0[1] = v1;
                p1[0] = v2; p1[1] = v3;
            } else {
                h16* hp0 = Chi + z * sCz + (size_t)row0 * ldc + col;
                h16* hp1 = Chi + z * sCz + (size_t)(row0 + 8) * ldc + col;
                hp0[0] = __float2half(v0); hp0[1] = __float2half(v1);
                hp1[0] = __float2half(v2); hp1[1] = __float2half(v3);
            }
        }
    }
}

// ================= small kernels =================
__global__ void split5_kernel(
    const float* __restrict__ s0, const float* __restrict__ s1, const float* __restrict__ s2,
    const float* __restrict__ s3, const float* __restrict__ s4,
    h16* __restrict__ h0, h16* __restrict__ h1, h16* __restrict__ h2,
    h16* __restrict__ h3, h16* __restrict__ h4)
{
    int i4 = blockIdx.x * blockDim.x + threadIdx.x;
    int zz = blockIdx.y;
    const float* src = (zz == 0) ? s0 : (zz == 1) ? s1 : (zz == 2) ? s2 : (zz == 3) ? s3 : s4;
    h16* hi = (zz == 0) ? h0 : (zz == 1) ? h1 : (zz == 2) ? h2 : (zz == 3) ? h3 : h4;
    float4 v = *((const float4*)src + i4);
    uint2 hv;
    hv.x = pack_h16x2(v.x, v.y);
    hv.y = pack_h16x2(v.z, v.w);
    *((uint2*)hi + i4) = hv;
}

__global__ void fiber_gemm(const float* __restrict__ x, const float* __restrict__ fw,
                           float* __restrict__ fpart)
{
    __shared__ float Xs[64][68];
    __shared__ float Fs[64][68];
    const int ksplit = blockIdx.x;
    const int rb = blockIdx.y * 64;
    const int t = threadIdx.x;
    const int rt = t & 15, ct = t >> 4;
    float acc[4][4] = {};
    for (int sub = 0; sub < 2; sub++) {
        const int k0 = ksplit * 128 + sub * 64;
        __syncthreads();
        for (int i = t; i < 1024; i += 256) {
            int row = i >> 4, kq = (i & 15) * 4;
            float4 v = *(const float4*)&x[(size_t)(rb + row) * DM + k0 + kq];
            Xs[kq][row] = v.x; Xs[kq+1][row] = v.y; Xs[kq+2][row] = v.z; Xs[kq+3][row] = v.w;
            float4 w = *(const float4*)&fw[(size_t)row * DM + k0 + kq];
            Fs[kq][row] = w.x; Fs[kq+1][row] = w.y; Fs[kq+2][row] = w.z; Fs[kq+3][row] = w.w;
        }
        __syncthreads();
#pragma unroll 16
        for (int k = 0; k < 64; k++) {
            float a[4], b[4];
#pragma unroll
            for (int i = 0; i < 4; i++) a[i] = Xs[k][rt*4 + i];
#pragma unroll
            for (int j = 0; j < 4; j++) b[j] = Fs[k][ct*4 + j];
#pragma unroll
            for (int i = 0; i < 4; i++)
#pragma unroll
                for (int j = 0; j < 4; j++) acc[i][j] = fmaf(a[i], b[j], acc[i][j]);
        }
    }
    float* dst = fpart + (size_t)ksplit * S_ * F_;
#pragma unroll
    for (int i = 0; i < 4; i++)
#pragma unroll
        for (int j = 0; j < 4; j++)
            dst[(size_t)(rb + rt*4 + i) * F_ + ct*4 + j] = acc[i][j];
}

__global__ void fiber_reduce(const float* __restrict__ fpart, const float* __restrict__ fb,
                             float* __restrict__ fp)
{
    int i = blockIdx.x * blockDim.x + threadIdx.x;
    if (i >= S_ * F_) return;
    float a = fb[i & 63];
#pragma unroll
    for (int s = 0; s < 16; s++) a += fpart[(size_t)s * S_ * F_ + i];
    fp[i] = a;
}

__global__ void fp_stats_kernel(const float* __restrict__ fp,
                                float* __restrict__ fpsum, float* __restrict__ mi)
{
    __shared__ float sm[256];
    int t = threadIdx.x;
    int f = t & 63, c = t >> 6;
    float s = 0.f;
    for (int i = c; i < S_; i += 4) s += fp[i*F_ + f];
    sm[t] = s; __syncthreads();
    if (c == 0) {
        float tot = sm[f] + sm[64+f] + sm[128+f] + sm[192+f];
        fpsum[f] = tot;
        mi[f] = tot / (float)S_;
    }
}

__global__ void mlp_metric_kernel(const float* __restrict__ mi,
                                  const float* __restrict__ fm1w, const float* __restrict__ fm1b,
                                  const float* __restrict__ fm2w, const float* __restrict__ fm2b,
                                  float* __restrict__ metric)
{
    __shared__ float smi[F_];
    __shared__ float hid[F_/2];
    __shared__ float raw[F_];
    int t = threadIdx.x;
    smi[t] = mi[t];
    __syncthreads();
    if (t < F_/2) {
        float a = fm1b[t];
        for (int f = 0; f < F_; f++) a = fmaf(smi[f], fm1w[t*F_ + f], a);
        hid[t] = fmaxf(a, 0.f);
    }
    __syncthreads();
    {
        float a = fm2b[t];
        for (int j = 0; j < F_/2; j++) a = fmaf(hid[j], fm2w[t*(F_/2) + j], a);
        raw[t] = a;
    }
    __syncthreads();
    for (int b = 0; b < F_; b++)
        metric[t*F_ + b] = raw[t]*raw[b] + ((t == b) ? 0.1f : 0.f);
}

__global__ void compute_g_kernel(const float* __restrict__ fp,
                                 const float* __restrict__ metric,
                                 float* __restrict__ g)
{
    __shared__ float sm[F_*F_];
    for (int i = threadIdx.x; i < F_*F_; i += blockDim.x) sm[i] = metric[i];
    __syncthreads();
    int t = threadIdx.x;
    int f = t & 63, r = t >> 6;
    int i = blockIdx.x*4 + r;
    const float* fr = fp + (size_t)i*F_;
    float a = 0.f;
#pragma unroll
    for (int k = 0; k < F_; k++) a = fmaf(fr[k], sm[k*F_ + f], a);
    g[(size_t)i*F_ + f] = a;
}

__global__ void curv_kernel(const float* __restrict__ fp, const float* __restrict__ cm,
                            float* __restrict__ curv, float* __restrict__ curvb)
{
    int j = blockIdx.x*blockDim.x + threadIdx.x;
    if (j >= S_) return;
    float a = 0.f;
#pragma unroll
    for (int f = 0; f < F_; f++) a = fmaf(fp[(size_t)j*F_ + f], cm[f*(F_+1)], a);
    curv[j] = a;
    curvb[j] = COUPLING * a;
}

__global__ void pack_aug_kernel(const float* __restrict__ Q, const float* __restrict__ Km,
                                const float* __restrict__ g, const float* __restrict__ fp,
                                h16* __restrict__ Qhi, h16* __restrict__ Khi)
{
    int idx = blockIdx.x*blockDim.x + threadIdx.x;
    if (idx >= H_*S_*AUG) return;
    int d = idx % AUG;
    int i = (idx / AUG) % S_;
    int h = idx / (AUG*S_);
    float qv, kv;
    if (d < DK) {
        qv = Q[(size_t)i*DM + h*DK + d] * INV_SCALE;
        kv = Km[(size_t)i*DM + h*DK + d];
    } else {
        qv = COUPLING * g[(size_t)i*F_ + (d-DK)];
        kv = fp[(size_t)i*F_ + (d-DK)];
    }
    Qhi[idx] = __float2half(qv);
    Khi[idx] = __float2half(kv);
}

__global__ void softmax_kernel(const float* __restrict__ P, h16* __restrict__ Phi)
{
    size_t row = blockIdx.x;
    const float* p = P + row * (size_t)S_;
    int t = threadIdx.x;
    float vals[8];
    float4 v0 = *(const float4*)(p + t*8);
    float4 v1 = *(const float4*)(p + t*8 + 4);
    vals[0]=v0.x; vals[1]=v0.y; vals[2]=v0.z; vals[3]=v0.w;
    vals[4]=v1.x; vals[5]=v1.y; vals[6]=v1.z; vals[7]=v1.w;
    float m = vals[0];
#pragma unroll
    for (int i = 1; i < 8; i++) m = fmaxf(m, vals[i]);
    __shared__ float red[8];
    for (int o = 16; o; o >>= 1) m = fmaxf(m, __shfl_xor_sync(~0u, m, o));
    if ((t & 31) == 0) red[t>>5] = m;
    __syncthreads();
    m = red[0];
#pragma unroll
    for (int i = 1; i < 8; i++) m = fmaxf(m, red[i]);
    float s = 0.f;
#pragma unroll
    for (int i = 0; i < 8; i++) { vals[i] = __expf(vals[i] - m); s += vals[i]; }
    for (int o = 16; o; o >>= 1) s += __shfl_xor_sync(~0u, s, o);
    __shared__ float red2[8];
    if ((t & 31) == 0) red2[t>>5] = s;
    __syncthreads();
    s = red2[0];
#pragma unroll
    for (int i = 1; i < 8; i++) s += red2[i];
    float inv = 1.0f / s;
    uint4 hv;
    hv.x = pack_h16x2(vals[0]*inv, vals[1]*inv);
    hv.y = pack_h16x2(vals[2]*inv, vals[3]*inv);
    hv.z = pack_h16x2(vals[4]*inv, vals[5]*inv);
    hv.w = pack_h16x2(vals[6]*inv, vals[7]*inv);
    *(uint4*)(Phi + row * (size_t)S_ + t*8) = hv;
}

__global__ void scalar_kernel(const float* __restrict__ g, const float* __restrict__ fpsum,
                              const float* __restrict__ curv, float* __restrict__ out0,
                              float* __restrict__ out1)
{
    __shared__ float sm[256];
    __shared__ float sc[256];
    int t = threadIdx.x;
    int f = t & 63, c = t >> 6;
    float s = 0.f;
    for (int i = c; i < S_; i += 4) s += g[i*F_ + f];
    sm[t] = s; __syncthreads();
    float tot = 0.f;
    if (c == 0) tot = sm[f] + sm[64+f] + sm[128+f] + sm[192+f];
    __syncthreads();
    sm[t] = (c == 0) ? tot * fpsum[f] : 0.f;
    float cs = 0.f;
    for (int j = t; j < S_; j += 256) cs += curv[j];
    sc[t] = cs;
    __syncthreads();
    if (t == 0) {
        float a = 0.f, b = 0.f;
        for (int i = 0; i < 64; i++) a += sm[i];
        for (int i = 0; i < 256; i++) b += sc[i];
        float val = a / ((float)S_ * (float)S_) + b / (float)S_;
        *out0 = val;
        if (out1) *out1 = val;
    }
}

// ================= launch =================
extern "C" void kernel_launch(void* const* d_in, const int* in_sizes, int n_in,
                              void* d_out, int out_size)
{
    const float* x    = (const float*)d_in[0];
    const float* wq   = (const float*)d_in[2];
    const float* wk   = (const float*)d_in[3];
    const float* wv   = (const float*)d_in[4];
    const float* wo_w = (const float*)d_in[5];
    const float* wo_b = (const float*)d_in[6];
    const float* fw   = (const float*)d_in[7];
    const float* fb   = (const float*)d_in[8];
    const float* fm1w = (const float*)d_in[9];
    const float* fm1b = (const float*)d_in[10];
    const float* fm2w = (const float*)d_in[11];
    const float* fm2b = (const float*)d_in[12];
    const float* cm   = (const float*)d_in[13];
    float* out = (float*)d_out;

    h16 *xhi,*wqkhi,*wvhi,*wohi;
    h16 *Vthi,*Qahi,*Kahi,*Phi,*athi;
    float *QK,*fp,*fpart,*g,*metric,*mi,*fpsum,*curv,*curvb,*scores;
    cudaGetSymbolAddress((void**)&xhi, d_xhi);
    cudaGetSymbolAddress((void**)&wqkhi, d_wqkhi);
    cudaGetSymbolAddress((void**)&wvhi, d_wvhi);
    cudaGetSymbolAddress((void**)&wohi, d_wohi);
    cudaGetSymbolAddress((void**)&Vthi, d_Vthi);
    cudaGetSymbolAddress((void**)&Qahi, d_Qahi);
    cudaGetSymbolAddress((void**)&Kahi, d_Kahi);
    cudaGetSymbolAddress((void**)&Phi, d_Phi);
    cudaGetSymbolAddress((void**)&athi, d_attnhi);
    cudaGetSymbolAddress((void**)&QK, d_QK);
    cudaGetSymbolAddress((void**)&fp, d_fp);       cudaGetSymbolAddress((void**)&fpart, d_fpart);
    cudaGetSymbolAddress((void**)&g, d_g);
    cudaGetSymbolAddress((void**)&metric, d_metric); cudaGetSymbolAddress((void**)&mi, d_mi);
    cudaGetSymbolAddress((void**)&fpsum, d_fpsum);   cudaGetSymbolAddress((void**)&curv, d_curv);
    cudaGetSymbolAddress((void**)&curvb, d_curvb);   cudaGetSymbolAddress((void**)&scores, d_scores);

    cudaFuncSetAttribute(mma_gemm_nt_1t<0>, cudaFuncAttributeMaxDynamicSharedMemorySize, MMA1_SMEM);
    cudaFuncSetAttribute(mma_gemm_nt_1t<2>, cudaFuncAttributeMaxDynamicSharedMemorySize, MMA1_SMEM);

    const int NDM = S_*DM;
    // 0) fp16 hi splits for all 5 tensors
    split5_kernel<<<dim3(NDM/1024, 5), 256>>>(
        x, wq, wk, wv, wo_w,
        xhi, wqkhi, wqkhi + (size_t)DM*DM, wvhi, wohi);

    // 1) Q and K projections batched: z=2 (1-term, fp32 out)
    mma_gemm_nt_1t<0><<<dim3(16,16,2), 256, MMA1_SMEM>>>(
        xhi, DM, 0, wqkhi, DM, (size_t)DM*DM,
        QK, nullptr, DM, (size_t)S_*DM, DM, nullptr);
    // 2) Vt[d][s] = wv @ x^T (1-term, h16 hi out)
    mma_gemm_nt_1t<2><<<dim3(16,16,1), 256, MMA1_SMEM>>>(
        wvhi, DM, 0, xhi, DM, 0,
        nullptr, Vthi, S_, 0, DM, nullptr);
    // 3) fiber projection (deterministic split-K)
    fiber_gemm<<<dim3(16, 32), 256>>>(x, fw, fpart);
    fiber_reduce<<<S_*F_/256, 256>>>(fpart, fb, fp);
    // 4) stats -> MLP -> metric -> g -> curv
    fp_stats_kernel<<<1, 256>>>(fp, fpsum, mi);
    mlp_metric_kernel<<<1, 64>>>(mi, fm1w, fm1b, fm2w, fm2b, metric);
    compute_g_kernel<<<S_/4, 256>>>(fp, metric, g);
    curv_kernel<<<S_/256, 256>>>(fp, cm, curv, curvb);
    // 5) pack augmented Q / K (hi only)
    pack_aug_kernel<<<(H_*S_*AUG)/256, 256>>>(QK, QK + (size_t)S_*DM, g, fp,
                                              Qahi, Kahi);
    // 6) scores = Qaug @ Kaug^T + 0.1*curv[col] (1-term, K=192, batched heads)
    mma_gemm_nt_1t<0><<<dim3(16,16,H_), 256, MMA1_SMEM>>>(
        Qahi, AUG, (size_t)S_*AUG, Kahi, AUG, (size_t)S_*AUG,
        scores, nullptr, S_, (size_t)S_*S_, AUG, curvb);
    // 7) softmax -> P hi only
    softmax_kernel<<<H_*S_, 256>>>(scores, Phi);
    // 8) attn = P[h] @ Vt[h]^T (1-term, h16 hi out)
    mma_gemm_nt_1t<2><<<dim3(1,16,H_), 256, MMA1_SMEM>>>(
        Phi, S_, (size_t)S_*S_, Vthi, S_, (size_t)DK*S_,
        nullptr, athi, DM, (size_t)DK, S_, nullptr);
    // 9) out = attn @ wo^T + wo_b (1-term, fp32 -> d_out)
    mma_gemm_nt_1t<0><<<dim3(16,16,1), 256, MMA1_SMEM>>>(
        athi, DM, 0, wohi, DM, 0,
        out, nullptr, DM, 0, DM, wo_b);
    // 10) ci.mean() scalar
    if (out_size > S_*DM) {
        float* o0 = out + (size_t)S_*DM;
        float* o1 = out + (size_t)(out_size - 1);
        scalar_kernel<<<1, 256>>>(g, fpsum, curv, o0, (o1 != o0) ? o1 : nullptr);
    }
}